// round 2
// baseline (speedup 1.0000x reference)
#include <cuda_runtime.h>
#include <math.h>

#define Bz   64
#define Tz   2048
#define IND  256
#define ST   512
#define OD   256
#define M_ROWS (Bz*Tz)   // 131072
#define EPSC 1e-5f

// ---------------- scratch (static device memory; no allocs allowed) ----------
__device__ float g_v [(size_t)M_ROWS*ST];   // after proj+silu          (256MB)
__device__ float g_vc[(size_t)M_ROWS*ST];   // after conv (pre-BN)      (256MB)
__device__ float g_u [(size_t)M_ROWS*ST];   // vc_norm @ Bm + bias      (256MB)
__device__ float g_s [(size_t)M_ROWS*ST];   // LN'd states              (256MB)
__device__ float g_wt[IND*ST];              // W_in^T  (k,n)
__device__ float g_wk[3*ST*ST];             // conv taps as (tap, i, o)
__device__ float g_bm2[ST*ST];              // BN-folded Bm
__device__ float g_ubias[ST];
__device__ float g_sum[ST];
__device__ float g_sumsq[ST];

// ---------------- prep: transpose W_in, repack conv_w, zero accumulators -----
__global__ void k_prep(const float* __restrict__ W_in, const float* __restrict__ conv_w) {
    int idx = blockIdx.x * blockDim.x + threadIdx.x;
    if (idx < 3*ST*ST) {              // conv_w (o,i,k) -> g_wk[k][i][o]
        int o   = idx / (ST*3);
        int rem = idx % (ST*3);
        int i   = rem / 3;
        int k   = rem % 3;
        g_wk[(size_t)k*ST*ST + i*ST + o] = conv_w[idx];
    }
    if (idx < IND*ST) {               // W_in (n,k) -> g_wt[k][n]
        int n = idx / IND, k = idx % IND;
        g_wt[k*ST + n] = W_in[idx];
    }
    if (idx < ST) { g_sum[idx] = 0.f; g_sumsq[idx] = 0.f; }
}

// ---------------- generic NN GEMM: out[m,n] = act(sum_k A[m,k]*B[k,n] + bias[n])
// tiles 64x64x16, 256 threads, 4x4 per-thread microtile
__global__ __launch_bounds__(256)
void k_gemm(const float* __restrict__ Ap, const float* __restrict__ Bp,
            const float* __restrict__ bias, float* __restrict__ outp,
            int Kd, int N, int act) {
    __shared__ float As[16][68];
    __shared__ float Bs[16][68];
    const int tid = threadIdx.x;
    const int tx = tid & 15, ty = tid >> 4;
    const int m0 = blockIdx.y * 64, n0 = blockIdx.x * 64;
    const int ar = tid >> 2, ak = (tid & 3) * 4;    // A loader: row, k-quad
    const int bk = tid >> 4, bn = (tid & 15) * 4;   // B loader: k-row, n-quad

    float acc[4][4] = {};
    for (int k0 = 0; k0 < Kd; k0 += 16) {
        float4 a4 = *(const float4*)(Ap + (size_t)(m0 + ar) * Kd + k0 + ak);
        As[ak+0][ar] = a4.x; As[ak+1][ar] = a4.y;
        As[ak+2][ar] = a4.z; As[ak+3][ar] = a4.w;
        *(float4*)&Bs[bk][bn] = *(const float4*)(Bp + (size_t)(k0 + bk) * N + n0 + bn);
        __syncthreads();
#pragma unroll
        for (int kk = 0; kk < 16; kk++) {
            float ra[4], rb[4];
            *(float4*)ra = *(const float4*)&As[kk][ty*4];
            *(float4*)rb = *(const float4*)&Bs[kk][tx*4];
#pragma unroll
            for (int i = 0; i < 4; i++)
#pragma unroll
                for (int j = 0; j < 4; j++)
                    acc[i][j] = fmaf(ra[i], rb[j], acc[i][j]);
        }
        __syncthreads();
    }
#pragma unroll
    for (int i = 0; i < 4; i++) {
        float v[4];
#pragma unroll
        for (int j = 0; j < 4; j++) {
            float bv = bias ? bias[n0 + tx*4 + j] : 0.f;
            float val = acc[i][j] + bv;
            if (act == 1) val = val / (1.f + expf(-val));   // silu
            v[j] = val;
        }
        *(float4*)(outp + (size_t)(m0 + ty*4 + i) * N + n0 + tx*4) = *(float4*)v;
    }
}

// ---------------- conv as 3 row-shifted GEMMs (zero-pad at batch edges) ------
__global__ __launch_bounds__(256)
void k_conv(const float* __restrict__ cb) {
    __shared__ float As[16][68];
    __shared__ float Bs[16][68];
    const int tid = threadIdx.x;
    const int tx = tid & 15, ty = tid >> 4;
    const int m0 = blockIdx.y * 64, n0 = blockIdx.x * 64;
    const int ar = tid >> 2, ak = (tid & 3) * 4;
    const int bk = tid >> 4, bn = (tid & 15) * 4;

    const int r = m0 + ar;
    const int t = r & (Tz - 1);
    float acc[4][4] = {};
#pragma unroll
    for (int tap = 0; tap < 3; tap++) {
        const float* Bk = g_wk + (size_t)tap * ST * ST;
        const int tt = t + tap - 1;
        const bool valid = (tt >= 0) && (tt < Tz);
        const float* Arow = g_v + (size_t)(r + tap - 1) * ST;
        for (int k0 = 0; k0 < ST; k0 += 16) {
            float4 a4 = make_float4(0.f, 0.f, 0.f, 0.f);
            if (valid) a4 = *(const float4*)(Arow + k0 + ak);
            As[ak+0][ar] = a4.x; As[ak+1][ar] = a4.y;
            As[ak+2][ar] = a4.z; As[ak+3][ar] = a4.w;
            *(float4*)&Bs[bk][bn] = *(const float4*)(Bk + (size_t)(k0 + bk) * ST + n0 + bn);
            __syncthreads();
#pragma unroll
            for (int kk = 0; kk < 16; kk++) {
                float ra[4], rb[4];
                *(float4*)ra = *(const float4*)&As[kk][ty*4];
                *(float4*)rb = *(const float4*)&Bs[kk][tx*4];
#pragma unroll
                for (int i = 0; i < 4; i++)
#pragma unroll
                    for (int j = 0; j < 4; j++)
                        acc[i][j] = fmaf(ra[i], rb[j], acc[i][j]);
            }
            __syncthreads();
        }
    }
#pragma unroll
    for (int i = 0; i < 4; i++) {
        float v[4];
#pragma unroll
        for (int j = 0; j < 4; j++) v[j] = acc[i][j] + cb[n0 + tx*4 + j];
        *(float4*)(g_vc + (size_t)(m0 + ty*4 + i) * ST + n0 + tx*4) = *(float4*)v;
    }
}

// ---------------- BN stats: per-channel sum / sumsq over 131072 rows ---------
__global__ __launch_bounds__(512)
void k_stats() {
    const int n = threadIdx.x;
    const int rpc = M_ROWS / 512;      // 256 rows per CTA
    const int r0 = blockIdx.x * rpc;
    float s1 = 0.f, s2 = 0.f;
    for (int r = 0; r < rpc; r++) {
        float v = g_vc[(size_t)(r0 + r) * ST + n];
        s1 += v; s2 += v * v;
    }
    atomicAdd(&g_sum[n], s1);
    atomicAdd(&g_sumsq[n], s2);
}

// ---------------- fold BN into Bm: Bm2[i,j] = sc_i*Bm[i,j]; ubias[j]=sum sh_i*Bm[i,j]
__global__ __launch_bounds__(512)
void k_finalize(const float* __restrict__ Bm, const float* __restrict__ bng,
                const float* __restrict__ bnb) {
    __shared__ float sc[ST], sh[ST];
    const int j = threadIdx.x;
    float mu  = g_sum[j]   * (1.f / M_ROWS);
    float var = g_sumsq[j] * (1.f / M_ROWS) - mu * mu;
    float inv = rsqrtf(var + EPSC);
    float s   = bng[j] * inv;
    sc[j] = s;
    sh[j] = bnb[j] - mu * s;
    __syncthreads();
    float ub = 0.f;
    for (int i = 0; i < ST; i++) {
        float bmv = Bm[(size_t)i * ST + j];
        g_bm2[(size_t)i * ST + j] = sc[i] * bmv;
        ub += sh[i] * bmv;
    }
    g_ubias[j] = ub;
}

// ---------------- sequential recurrence: one CTA per batch row ---------------
// s = LN(s @ A + u_t) ; states stored to g_s for the bulk output GEMM
__global__ __launch_bounds__(512)
void k_recur(const float* __restrict__ A, const float* __restrict__ lng,
             const float* __restrict__ lnb) {
    __shared__ float ss[ST];
    __shared__ float red1[16], red2[16], bc[2];
    const int j = threadIdx.x;
    const int b = blockIdx.x;
    const float gj = lng[j], bj = lnb[j];
    ss[j] = 0.f;
    __syncthreads();
    const float* Acol = A + j;
    const size_t base = (size_t)b * Tz * ST;
    for (int t = 0; t < Tz; t++) {
        float acc = g_u[base + (size_t)t * ST + j];
#pragma unroll 8
        for (int i = 0; i < ST; i += 4) {
            float4 s4 = *(const float4*)&ss[i];
            acc = fmaf(s4.x, Acol[(size_t)(i+0)*ST], acc);
            acc = fmaf(s4.y, Acol[(size_t)(i+1)*ST], acc);
            acc = fmaf(s4.z, Acol[(size_t)(i+2)*ST], acc);
            acc = fmaf(s4.w, Acol[(size_t)(i+3)*ST], acc);
        }
        // block LayerNorm reduction (sum, sumsq)
        float v1 = acc, v2 = acc * acc;
#pragma unroll
        for (int o = 16; o > 0; o >>= 1) {
            v1 += __shfl_xor_sync(0xffffffffu, v1, o);
            v2 += __shfl_xor_sync(0xffffffffu, v2, o);
        }
        const int lane = j & 31, w = j >> 5;
        if (lane == 0) { red1[w] = v1; red2[w] = v2; }
        __syncthreads();
        if (w == 0) {
            float a1 = (lane < 16) ? red1[lane] : 0.f;
            float a2 = (lane < 16) ? red2[lane] : 0.f;
#pragma unroll
            for (int o = 8; o > 0; o >>= 1) {
                a1 += __shfl_xor_sync(0xffffffffu, a1, o);
                a2 += __shfl_xor_sync(0xffffffffu, a2, o);
            }
            if (lane == 0) {
                float mean = a1 * (1.f / ST);
                float var  = a2 * (1.f / ST) - mean * mean;
                bc[0] = mean;
                bc[1] = rsqrtf(var + EPSC);
            }
        }
        __syncthreads();
        float sval = (acc - bc[0]) * bc[1] * gj + bj;
        ss[j] = sval;                                   // safe: all reads done pre-sync
        g_s[base + (size_t)t * ST + j] = sval;
        __syncthreads();
    }
}

// ---------------- launch ------------------------------------------------------
extern "C" void kernel_launch(void* const* d_in, const int* in_sizes, int n_in,
                              void* d_out, int out_size) {
    const float* x      = (const float*)d_in[0];
    const float* W_in   = (const float*)d_in[1];
    const float* b_in   = (const float*)d_in[2];
    const float* conv_w = (const float*)d_in[3];
    const float* conv_b = (const float*)d_in[4];
    const float* bng    = (const float*)d_in[5];
    const float* bnb    = (const float*)d_in[6];
    const float* lng    = (const float*)d_in[7];
    const float* lnb    = (const float*)d_in[8];
    const float* A      = (const float*)d_in[9];
    const float* Bm     = (const float*)d_in[10];
    const float* C      = (const float*)d_in[11];
    float* out = (float*)d_out;

    void *p_v, *p_vc, *p_u, *p_s, *p_wt, *p_bm2, *p_ub;
    cudaGetSymbolAddress(&p_v,   g_v);
    cudaGetSymbolAddress(&p_vc,  g_vc);
    cudaGetSymbolAddress(&p_u,   g_u);
    cudaGetSymbolAddress(&p_s,   g_s);
    cudaGetSymbolAddress(&p_wt,  g_wt);
    cudaGetSymbolAddress(&p_bm2, g_bm2);
    cudaGetSymbolAddress(&p_ub,  g_ubias);

    // 1) repack weights + zero accumulators
    k_prep<<<1536, 512>>>(W_in, conv_w);
    // 2) v = silu(x @ W_in^T + b_in)
    k_gemm<<<dim3(ST/64, M_ROWS/64), 256>>>(x, (const float*)p_wt, b_in,
                                            (float*)p_v, IND, ST, 1);
    // 3) vc = conv1d(v) + conv_b  (3 shifted GEMMs)
    k_conv<<<dim3(ST/64, M_ROWS/64), 256>>>(conv_b);
    // 4) BN stats
    k_stats<<<512, 512>>>();
    // 5) fold BN into Bm
    k_finalize<<<1, 512>>>(Bm, bng, bnb);
    // 6) u = vc_norm @ Bm + ubias
    k_gemm<<<dim3(ST/64, M_ROWS/64), 256>>>((const float*)p_vc, (const float*)p_bm2,
                                            (const float*)p_ub, (float*)p_u, ST, ST, 0);
    // 7) sequential recurrence (64 independent chains)
    k_recur<<<Bz, 512>>>(A, lng, lnb);
    // 8) y = S @ C
    k_gemm<<<dim3(OD/64, M_ROWS/64), 256>>>((const float*)p_s, C, nullptr,
                                            out, ST, OD, 0);
}

// round 3
// speedup vs baseline: 1.8558x; 1.8558x over previous
#include <cuda_runtime.h>
#include <math.h>
#include <cstdint>

#define Bz   64
#define Tz   2048
#define IND  256
#define ST   512
#define OD   256
#define M_ROWS (Bz*Tz)   // 131072
#define EPSC 1e-5f

// ---------------- scratch ----------------------------------------------------
__device__ float g_v [(size_t)M_ROWS*ST];
__device__ float g_vc[(size_t)M_ROWS*ST];
__device__ float g_u [(size_t)M_ROWS*ST];
__device__ float g_s [(size_t)M_ROWS*ST];
__device__ float g_wt[IND*ST];              // W_in^T  (k,n)
__device__ float g_wk[3*ST*ST];             // conv taps as virtual-K 1536 x 512
__device__ float g_bm2[ST*ST];              // BN-folded Bm
__device__ float g_ubias[ST];
__device__ float g_sum[ST];
__device__ float g_sumsq[ST];

__device__ __forceinline__ uint32_t smem_u32(const void* p) {
    return (uint32_t)__cvta_generic_to_shared(p);
}

// ---------------- prep -------------------------------------------------------
__global__ void k_prep(const float* __restrict__ W_in, const float* __restrict__ conv_w) {
    int idx = blockIdx.x * blockDim.x + threadIdx.x;
    if (idx < 3*ST*ST) {              // conv_w (o,i,k) -> g_wk[(k*ST+i)][o]
        int o   = idx / (ST*3);
        int rem = idx % (ST*3);
        int i   = rem / 3;
        int k   = rem % 3;
        g_wk[((size_t)k*ST + i)*ST + o] = conv_w[idx];
    }
    if (idx < IND*ST) {               // W_in (n,k) -> g_wt[k][n]
        int n = idx / IND, k = idx % IND;
        g_wt[k*ST + n] = W_in[idx];
    }
    if (idx < ST) { g_sum[idx] = 0.f; g_sumsq[idx] = 0.f; }
}

// ---------------- 128x128x16 double-buffered SGEMM ---------------------------
__global__ __launch_bounds__(256, 2)
void k_gemm(const float* __restrict__ Ap, const float* __restrict__ Bp,
            const float* __restrict__ bias, float* __restrict__ outp,
            int Kd, int N, int act) {
    __shared__ float As[2][16][128];
    __shared__ float Bs[2][16][128];
    const int t = threadIdx.x;
    const int m0 = blockIdx.y * 128, n0 = blockIdx.x * 128;
    const int am = t >> 2, ak = (t & 3) << 2;
    const int bkr = t >> 5, bn = (t & 31) << 2;
    const int tx = t & 15, ty = t >> 4;

    const float* Ag0 = Ap + (size_t)(m0 + am) * Kd + ak;
    const float* Ag1 = Ap + (size_t)(m0 + am + 64) * Kd + ak;
    const float* Bg0 = Bp + (size_t)bkr * N + n0 + bn;
    const float* Bg1 = Bp + (size_t)(bkr + 8) * N + n0 + bn;

    float4 ra0 = *(const float4*)Ag0;
    float4 ra1 = *(const float4*)Ag1;
    float4 rb0 = *(const float4*)Bg0;
    float4 rb1 = *(const float4*)Bg1;

    As[0][ak+0][am] = ra0.x; As[0][ak+1][am] = ra0.y;
    As[0][ak+2][am] = ra0.z; As[0][ak+3][am] = ra0.w;
    As[0][ak+0][am+64] = ra1.x; As[0][ak+1][am+64] = ra1.y;
    As[0][ak+2][am+64] = ra1.z; As[0][ak+3][am+64] = ra1.w;
    *(float4*)&Bs[0][bkr][bn]   = rb0;
    *(float4*)&Bs[0][bkr+8][bn] = rb1;
    __syncthreads();

    float acc[8][8];
#pragma unroll
    for (int i = 0; i < 8; i++)
#pragma unroll
        for (int j = 0; j < 8; j++) acc[i][j] = 0.f;

    int buf = 0;
    for (int k0 = 0; k0 < Kd; k0 += 16) {
        const bool more = (k0 + 16) < Kd;
        if (more) {
            ra0 = *(const float4*)(Ag0 + k0 + 16);
            ra1 = *(const float4*)(Ag1 + k0 + 16);
            rb0 = *(const float4*)(Bg0 + (size_t)(k0 + 16) * N);
            rb1 = *(const float4*)(Bg1 + (size_t)(k0 + 16) * N);
        }
#pragma unroll
        for (int kk = 0; kk < 16; kk++) {
            float a[8], b[8];
            *(float4*)&a[0] = *(const float4*)&As[buf][kk][ty*4];
            *(float4*)&a[4] = *(const float4*)&As[buf][kk][64 + ty*4];
            *(float4*)&b[0] = *(const float4*)&Bs[buf][kk][tx*4];
            *(float4*)&b[4] = *(const float4*)&Bs[buf][kk][64 + tx*4];
#pragma unroll
            for (int i = 0; i < 8; i++)
#pragma unroll
                for (int j = 0; j < 8; j++)
                    acc[i][j] = fmaf(a[i], b[j], acc[i][j]);
        }
        if (more) {
            buf ^= 1;
            As[buf][ak+0][am] = ra0.x; As[buf][ak+1][am] = ra0.y;
            As[buf][ak+2][am] = ra0.z; As[buf][ak+3][am] = ra0.w;
            As[buf][ak+0][am+64] = ra1.x; As[buf][ak+1][am+64] = ra1.y;
            As[buf][ak+2][am+64] = ra1.z; As[buf][ak+3][am+64] = ra1.w;
            *(float4*)&Bs[buf][bkr][bn]   = rb0;
            *(float4*)&Bs[buf][bkr+8][bn] = rb1;
            __syncthreads();
        }
    }
#pragma unroll
    for (int i = 0; i < 8; i++) {
        const int m = m0 + ((i < 4) ? (ty*4 + i) : (60 + ty*4 + i));
        float* orow = outp + (size_t)m * N + n0;
        float v[8];
#pragma unroll
        for (int j = 0; j < 8; j++) {
            const int col = (j < 4) ? (tx*4 + j) : (60 + tx*4 + j);
            float val = acc[i][j] + (bias ? bias[n0 + col] : 0.f);
            if (act == 1) val = val / (1.f + expf(-val));
            v[j] = val;
        }
        *(float4*)(orow + tx*4)      = *(float4*)&v[0];
        *(float4*)(orow + 64 + tx*4) = *(float4*)&v[4];
    }
}

// ---------------- conv as virtual K=1536 GEMM --------------------------------
__device__ __forceinline__ float4 conv_loadA(int r, int kv) {
    const int tap = kv >> 9;
    const int kl  = kv & 511;
    const int tt  = (r & (Tz - 1)) + tap - 1;
    if (tt < 0 || tt >= Tz) return make_float4(0.f, 0.f, 0.f, 0.f);
    return *(const float4*)(g_v + (size_t)(r + tap - 1) * ST + kl);
}

__global__ __launch_bounds__(256, 2)
void k_conv(const float* __restrict__ cb) {
    __shared__ float As[2][16][128];
    __shared__ float Bs[2][16][128];
    const int t = threadIdx.x;
    const int m0 = blockIdx.y * 128, n0 = blockIdx.x * 128;
    const int am = t >> 2, ak = (t & 3) << 2;
    const int bkr = t >> 5, bn = (t & 31) << 2;
    const int tx = t & 15, ty = t >> 4;
    const int N = ST, Kd = 3 * ST;
    const int r0 = m0 + am, r1 = m0 + am + 64;

    float4 ra0 = conv_loadA(r0, ak);
    float4 ra1 = conv_loadA(r1, ak);
    float4 rb0 = *(const float4*)(g_wk + (size_t)bkr * N + n0 + bn);
    float4 rb1 = *(const float4*)(g_wk + (size_t)(bkr + 8) * N + n0 + bn);

    As[0][ak+0][am] = ra0.x; As[0][ak+1][am] = ra0.y;
    As[0][ak+2][am] = ra0.z; As[0][ak+3][am] = ra0.w;
    As[0][ak+0][am+64] = ra1.x; As[0][ak+1][am+64] = ra1.y;
    As[0][ak+2][am+64] = ra1.z; As[0][ak+3][am+64] = ra1.w;
    *(float4*)&Bs[0][bkr][bn]   = rb0;
    *(float4*)&Bs[0][bkr+8][bn] = rb1;
    __syncthreads();

    float acc[8][8];
#pragma unroll
    for (int i = 0; i < 8; i++)
#pragma unroll
        for (int j = 0; j < 8; j++) acc[i][j] = 0.f;

    int buf = 0;
    for (int k0 = 0; k0 < Kd; k0 += 16) {
        const bool more = (k0 + 16) < Kd;
        if (more) {
            ra0 = conv_loadA(r0, k0 + 16 + ak);
            ra1 = conv_loadA(r1, k0 + 16 + ak);
            rb0 = *(const float4*)(g_wk + (size_t)(k0 + 16 + bkr) * N + n0 + bn);
            rb1 = *(const float4*)(g_wk + (size_t)(k0 + 24 + bkr) * N + n0 + bn);
        }
#pragma unroll
        for (int kk = 0; kk < 16; kk++) {
            float a[8], b[8];
            *(float4*)&a[0] = *(const float4*)&As[buf][kk][ty*4];
            *(float4*)&a[4] = *(const float4*)&As[buf][kk][64 + ty*4];
            *(float4*)&b[0] = *(const float4*)&Bs[buf][kk][tx*4];
            *(float4*)&b[4] = *(const float4*)&Bs[buf][kk][64 + tx*4];
#pragma unroll
            for (int i = 0; i < 8; i++)
#pragma unroll
                for (int j = 0; j < 8; j++)
                    acc[i][j] = fmaf(a[i], b[j], acc[i][j]);
        }
        if (more) {
            buf ^= 1;
            As[buf][ak+0][am] = ra0.x; As[buf][ak+1][am] = ra0.y;
            As[buf][ak+2][am] = ra0.z; As[buf][ak+3][am] = ra0.w;
            As[buf][ak+0][am+64] = ra1.x; As[buf][ak+1][am+64] = ra1.y;
            As[buf][ak+2][am+64] = ra1.z; As[buf][ak+3][am+64] = ra1.w;
            *(float4*)&Bs[buf][bkr][bn]   = rb0;
            *(float4*)&Bs[buf][bkr+8][bn] = rb1;
            __syncthreads();
        }
    }
#pragma unroll
    for (int i = 0; i < 8; i++) {
        const int m = m0 + ((i < 4) ? (ty*4 + i) : (60 + ty*4 + i));
        float* orow = g_vc + (size_t)m * N + n0;
        float v[8];
#pragma unroll
        for (int j = 0; j < 8; j++) {
            const int col = (j < 4) ? (tx*4 + j) : (60 + tx*4 + j);
            v[j] = acc[i][j] + cb[n0 + col];
        }
        *(float4*)(orow + tx*4)      = *(float4*)&v[0];
        *(float4*)(orow + 64 + tx*4) = *(float4*)&v[4];
    }
}

// ---------------- BN stats ---------------------------------------------------
__global__ __launch_bounds__(512)
void k_stats() {
    const int n = threadIdx.x;
    const int rpc = M_ROWS / 512;
    const int r0 = blockIdx.x * rpc;
    float s1 = 0.f, s2 = 0.f;
    for (int r = 0; r < rpc; r++) {
        float v = g_vc[(size_t)(r0 + r) * ST + n];
        s1 += v; s2 += v * v;
    }
    atomicAdd(&g_sum[n], s1);
    atomicAdd(&g_sumsq[n], s2);
}

__global__ __launch_bounds__(512)
void k_finalize(const float* __restrict__ Bm, const float* __restrict__ bng,
                const float* __restrict__ bnb) {
    __shared__ float sc[ST], sh[ST];
    const int j = threadIdx.x;
    float mu  = g_sum[j]   * (1.f / M_ROWS);
    float var = g_sumsq[j] * (1.f / M_ROWS) - mu * mu;
    float inv = rsqrtf(var + EPSC);
    float s   = bng[j] * inv;
    sc[j] = s;
    sh[j] = bnb[j] - mu * s;
    __syncthreads();
    float ub = 0.f;
    for (int i = 0; i < ST; i++) {
        float bmv = Bm[(size_t)i * ST + j];
        g_bm2[(size_t)i * ST + j] = sc[i] * bmv;
        ub += sh[i] * bmv;
    }
    g_ubias[j] = ub;
}

// ---------------- cluster recurrence -----------------------------------------
// 16 clusters (chain-groups of 4) x 8 CTAs (64-column j-tiles).
// A[:, jtile] resident in SMEM; per-step LN via DSMEM partial exchange;
// new state broadcast to all 8 CTAs via st.shared::cluster.
#define RC_SMEM_FLOATS 39064
__global__ __launch_bounds__(512, 1) __cluster_dims__(8, 1, 1)
void k_recur(const float* __restrict__ A, const float* __restrict__ lng,
             const float* __restrict__ lnb) {
    extern __shared__ float sm[];
    float* Atile = sm;            // [512][64]
    float* sbuf  = sm + 32768;    // [2][4][512]
    float* pbuf  = sm + 36864;    // [2][8][8]
    float* pred  = sm + 36992;    // [512][4]
    float* ws    = sm + 39040;    // [16]
    float* pl    = sm + 39056;    // [8]

    const int t    = threadIdx.x;
    const int rank = blockIdx.x;      // j tile
    const int grp  = blockIdx.y;      // chain group
    const int jg0  = rank * 64;

    // preload A tile (coalesced float4)
    for (int idx = t; idx < 512 * 16; idx += 512) {
        int i  = idx >> 4;
        int jv = (idx & 15) << 2;
        *(float4*)&Atile[i*64 + jv] = *(const float4*)(A + (size_t)i*ST + jg0 + jv);
    }
    for (int idx = t; idx < 4*512; idx += 512) sbuf[idx] = 0.f;

    const int ip = t >> 6;
    const int cc = (t >> 4) & 3;
    const int jq = t & 15;
    const int c2 = t >> 6;            // finalize role (t<256): chain in group
    const int jj = t & 63;

    float gj = 0.f, bj = 0.f;
    size_t urow0 = 0;
    if (t < 256) {
        gj = lng[jg0 + jj];
        bj = lnb[jg0 + jj];
        const int chain = grp * 4 + c2;
        urow0 = (size_t)chain * Tz * ST + jg0 + jj;
    }

    const uint32_t sb_base = smem_u32(sbuf);
    const uint32_t pb_base = smem_u32(pbuf);

    asm volatile("barrier.cluster.arrive.aligned;\n" ::: "memory");
    asm volatile("barrier.cluster.wait.aligned;\n" ::: "memory");

    int p = 0;
    float uval = (t < 256) ? g_u[urow0] : 0.f;

    for (int step = 0; step < Tz; step++) {
        // ---- compute: partial matvec over i-slice -------------------------
        const float* sb  = sbuf + (p*4 + cc)*512;
        const float* Ap2 = Atile + jq*4;
        float4 acc = make_float4(0.f, 0.f, 0.f, 0.f);
#pragma unroll 4
        for (int i = ip*64; i < ip*64 + 64; i += 4) {
            float4 s4 = *(const float4*)(sb + i);
            float4 a;
            a = *(const float4*)(Ap2 + (i+0)*64);
            acc.x = fmaf(s4.x, a.x, acc.x); acc.y = fmaf(s4.x, a.y, acc.y);
            acc.z = fmaf(s4.x, a.z, acc.z); acc.w = fmaf(s4.x, a.w, acc.w);
            a = *(const float4*)(Ap2 + (i+1)*64);
            acc.x = fmaf(s4.y, a.x, acc.x); acc.y = fmaf(s4.y, a.y, acc.y);
            acc.z = fmaf(s4.y, a.z, acc.z); acc.w = fmaf(s4.y, a.w, acc.w);
            a = *(const float4*)(Ap2 + (i+2)*64);
            acc.x = fmaf(s4.z, a.x, acc.x); acc.y = fmaf(s4.z, a.y, acc.y);
            acc.z = fmaf(s4.z, a.z, acc.z); acc.w = fmaf(s4.z, a.w, acc.w);
            a = *(const float4*)(Ap2 + (i+3)*64);
            acc.x = fmaf(s4.w, a.x, acc.x); acc.y = fmaf(s4.w, a.y, acc.y);
            acc.z = fmaf(s4.w, a.z, acc.z); acc.w = fmaf(s4.w, a.w, acc.w);
        }
        *(float4*)&pred[t*4] = acc;
        __syncthreads();

        // ---- finalize y + local LN partials -------------------------------
        float y = 0.f;
        if (t < 256) {
            y = uval;
#pragma unroll
            for (int q = 0; q < 8; q++)
                y += pred[(q*64 + c2*16 + (jj >> 2))*4 + (jj & 3)];
            float s1 = y, s2 = y*y;
#pragma unroll
            for (int o = 16; o > 0; o >>= 1) {
                s1 += __shfl_xor_sync(0xffffffffu, s1, o);
                s2 += __shfl_xor_sync(0xffffffffu, s2, o);
            }
            if ((t & 31) == 0) { ws[(t>>5)*2] = s1; ws[(t>>5)*2+1] = s2; }
        }
        __syncthreads();
        if (t < 4) {
            pl[t*2+0] = ws[t*4+0] + ws[t*4+2];
            pl[t*2+1] = ws[t*4+1] + ws[t*4+3];
        }
        __syncthreads();
        if (t < 64) {
            const int r = t >> 3, k = t & 7;
            const uint32_t la = pb_base + (uint32_t)(((p*8 + rank)*8 + k) * 4);
            uint32_t ra_;
            asm volatile("mapa.shared::cluster.u32 %0, %1, %2;" : "=r"(ra_) : "r"(la), "r"(r));
            asm volatile("st.shared::cluster.f32 [%0], %1;" :: "r"(ra_), "f"(pl[k]) : "memory");
        }
        float unext = 0.f;
        if (t < 256 && step + 1 < Tz)
            unext = g_u[urow0 + (size_t)(step + 1) * ST];

        asm volatile("barrier.cluster.arrive.aligned;\n" ::: "memory");
        asm volatile("barrier.cluster.wait.aligned;\n" ::: "memory");

        // ---- LN + broadcast new state -------------------------------------
        if (t < 256) {
            float q1 = 0.f, q2 = 0.f;
#pragma unroll
            for (int r = 0; r < 8; r++) {
                q1 += pbuf[(p*8 + r)*8 + c2*2 + 0];
                q2 += pbuf[(p*8 + r)*8 + c2*2 + 1];
            }
            const float mean = q1 * (1.f / ST);
            const float var  = q2 * (1.f / ST) - mean * mean;
            const float rstd = rsqrtf(var + EPSC);
            const float sval = (y - mean) * rstd * gj + bj;
            g_s[urow0 + (size_t)step * ST] = sval;
            const uint32_t la = sb_base + (uint32_t)(((((p^1)*4 + c2)*512) + jg0 + jj) * 4);
#pragma unroll
            for (int r = 0; r < 8; r++) {
                uint32_t ra_;
                asm volatile("mapa.shared::cluster.u32 %0, %1, %2;" : "=r"(ra_) : "r"(la), "r"(r));
                asm volatile("st.shared::cluster.f32 [%0], %1;" :: "r"(ra_), "f"(sval) : "memory");
            }
        }
        uval = unext;

        asm volatile("barrier.cluster.arrive.aligned;\n" ::: "memory");
        asm volatile("barrier.cluster.wait.aligned;\n" ::: "memory");
        p ^= 1;
    }
}

// ---------------- launch ------------------------------------------------------
extern "C" void kernel_launch(void* const* d_in, const int* in_sizes, int n_in,
                              void* d_out, int out_size) {
    const float* x      = (const float*)d_in[0];
    const float* W_in   = (const float*)d_in[1];
    const float* b_in   = (const float*)d_in[2];
    const float* conv_w = (const float*)d_in[3];
    const float* conv_b = (const float*)d_in[4];
    const float* bng    = (const float*)d_in[5];
    const float* bnb    = (const float*)d_in[6];
    const float* lng    = (const float*)d_in[7];
    const float* lnb    = (const float*)d_in[8];
    const float* A      = (const float*)d_in[9];
    const float* Bm     = (const float*)d_in[10];
    const float* C      = (const float*)d_in[11];
    float* out = (float*)d_out;

    void *p_v, *p_vc, *p_u, *p_s, *p_wt, *p_bm2, *p_ub;
    cudaGetSymbolAddress(&p_v,   g_v);
    cudaGetSymbolAddress(&p_vc,  g_vc);
    cudaGetSymbolAddress(&p_u,   g_u);
    cudaGetSymbolAddress(&p_s,   g_s);
    cudaGetSymbolAddress(&p_wt,  g_wt);
    cudaGetSymbolAddress(&p_bm2, g_bm2);
    cudaGetSymbolAddress(&p_ub,  g_ubias);

    static int rc_attr_set = 0;
    if (!rc_attr_set) {
        cudaFuncSetAttribute(k_recur, cudaFuncAttributeMaxDynamicSharedMemorySize,
                             RC_SMEM_FLOATS * 4);
        rc_attr_set = 1;
    }

    // 1) repack weights + zero accumulators
    k_prep<<<1536, 512>>>(W_in, conv_w);
    // 2) v = silu(x @ W_in^T + b_in)
    k_gemm<<<dim3(ST/128, M_ROWS/128), 256>>>(x, (const float*)p_wt, b_in,
                                              (float*)p_v, IND, ST, 1);
    // 3) vc = conv1d(v) + conv_b  (virtual K=1536 GEMM)
    k_conv<<<dim3(ST/128, M_ROWS/128), 256>>>(conv_b);
    // 4) BN stats
    k_stats<<<512, 512>>>();
    // 5) fold BN into Bm
    k_finalize<<<1, 512>>>(Bm, bng, bnb);
    // 6) u = vc_norm @ Bm + ubias
    k_gemm<<<dim3(ST/128, M_ROWS/128), 256>>>((const float*)p_vc, (const float*)p_bm2,
                                              (const float*)p_ub, (float*)p_u, ST, ST, 0);
    // 7) sequential recurrence: 16 clusters x 8 CTAs, A resident in SMEM
    k_recur<<<dim3(8, 16), 512, RC_SMEM_FLOATS * 4>>>(A, lng, lnb);
    // 8) y = S @ C
    k_gemm<<<dim3(OD/128, M_ROWS/128), 256>>>((const float*)p_s, C, nullptr,
                                              out, ST, OD, 0);
}

// round 5
// speedup vs baseline: 2.1224x; 1.1437x over previous
#include <cuda_runtime.h>
#include <cuda_bf16.h>
#include <math.h>
#include <cstdint>

#define Bz   64
#define Tz   2048
#define IND  256
#define ST   512
#define OD   256
#define M_ROWS (Bz*Tz)   // 131072
#define EPSC 1e-5f

// ---------------- scratch (static device memory) -----------------------------
__device__ __nv_bfloat16 g_vh[(size_t)M_ROWS*ST];   // proj output, split hi
__device__ __nv_bfloat16 g_vl[(size_t)M_ROWS*ST];   // proj output, split lo
__device__ float         g_vc[(size_t)M_ROWS*ST];   // conv output (fp32)
__device__ float         g_u [(size_t)M_ROWS*ST];   // recurrence input (fp32)
__device__ __nv_bfloat16 g_sh[(size_t)M_ROWS*ST];   // states, split hi
__device__ __nv_bfloat16 g_sl[(size_t)M_ROWS*ST];   // states, split lo
__device__ __nv_bfloat16 g_wth[ST*IND], g_wtl[ST*IND];     // W_in  Bt[n][k]
__device__ __nv_bfloat16 g_wkh[ST*3*ST], g_wkl[ST*3*ST];   // conv  Bt[n][tap*512+i]
__device__ __nv_bfloat16 g_bmh[ST*ST], g_bml[ST*ST];       // BN-folded Bm, Bt[j][i]
__device__ __nv_bfloat16 g_cth[OD*ST], g_ctl[OD*ST];       // C     Bt[n][k]
__device__ float g_ubias[ST];
__device__ float g_sum[ST];
__device__ float g_sumsq[ST];

__device__ __forceinline__ uint32_t smem_u32(const void* p) {
    return (uint32_t)__cvta_generic_to_shared(p);
}
__device__ __forceinline__ void split2(float x, __nv_bfloat16& h, __nv_bfloat16& l) {
    h = __float2bfloat16(x);
    l = __float2bfloat16(x - __bfloat162float(h));
}

// ---------------- prep: split/transpose all weights ---------------------------
__global__ void k_prep(const float* __restrict__ W_in, const float* __restrict__ conv_w,
                       const float* __restrict__ C) {
    int idx = blockIdx.x * blockDim.x + threadIdx.x;
    if (idx < ST*IND) {                 // W_in[n][k] -> Bt[n][k]
        split2(W_in[idx], g_wth[idx], g_wtl[idx]);
    }
    if (idx < ST*3*ST) {                // conv: Bt[n][tap*512+i] = conv_w[n][i][tap]
        int n = idx / (3*ST);
        int rem = idx % (3*ST);
        int tap = rem / ST, i = rem % ST;
        split2(conv_w[((size_t)n*ST + i)*3 + tap], g_wkh[idx], g_wkl[idx]);
    }
    if (idx < OD*ST) {                  // C[k][n] -> Ct[n][k]
        int n = idx / ST, k = idx % ST;
        split2(C[(size_t)k*OD + n], g_cth[idx], g_ctl[idx]);
    }
    if (idx < ST) { g_sum[idx] = 0.f; g_sumsq[idx] = 0.f; }
}

// ---------------- mma.sync helpers --------------------------------------------
__device__ __forceinline__ void mma16816(float* c, const uint32_t* a, const uint32_t* b) {
    asm volatile(
        "mma.sync.aligned.m16n8k16.row.col.f32.bf16.bf16.f32 "
        "{%0,%1,%2,%3}, {%4,%5,%6,%7}, {%8,%9}, {%0,%1,%2,%3};"
        : "+f"(c[0]), "+f"(c[1]), "+f"(c[2]), "+f"(c[3])
        : "r"(a[0]), "r"(a[1]), "r"(a[2]), "r"(a[3]), "r"(b[0]), "r"(b[1]));
}
__device__ __forceinline__ void ldsm4(uint32_t* r, uint32_t addr) {
    asm volatile("ldmatrix.sync.aligned.m8n8.x4.shared.b16 {%0,%1,%2,%3}, [%4];"
                 : "=r"(r[0]), "=r"(r[1]), "=r"(r[2]), "=r"(r[3]) : "r"(addr));
}
__device__ __forceinline__ void ldsm2(uint32_t* r, uint32_t addr) {
    asm volatile("ldmatrix.sync.aligned.m8n8.x2.shared.b16 {%0,%1}, [%2];"
                 : "=r"(r[0]), "=r"(r[1]) : "r"(addr));
}

// ---------------- split-bf16 warp-MMA GEMM -------------------------------------
// out[m,n] = act( sum_k A[m,k]*B[k,n] + bias[n] )
// 128x128 CTA tile, K-chunks of 64; B given as Bt[n][k] (k-contig).
// smem rows padded to 72 halfs (144B) -> conflict-free ldmatrix, no swizzle.
#define SRS 72
#define TILE_HALFS (128*SRS)          // 9216 halfs = 18432 B
#define SMB_TOTAL (4*TILE_HALFS*2)    // Ah, Al, Bh, Bl = 73728 B

__global__ __launch_bounds__(256, 1)
void k_tgemm(const float* __restrict__ Afp,
             const __nv_bfloat16* __restrict__ Ah, const __nv_bfloat16* __restrict__ Al,
             const __nv_bfloat16* __restrict__ Bh, const __nv_bfloat16* __restrict__ Bl,
             const float* __restrict__ bias, float* __restrict__ outf,
             __nv_bfloat16* __restrict__ outh, __nv_bfloat16* __restrict__ outl,
             int Kd, int N, int act, int convmode) {
    extern __shared__ __nv_bfloat16 smem[];
    __nv_bfloat16* sAh = smem;
    __nv_bfloat16* sAl = smem + TILE_HALFS;
    __nv_bfloat16* sBh = smem + 2*TILE_HALFS;
    __nv_bfloat16* sBl = smem + 3*TILE_HALFS;

    const int t = threadIdx.x;
    const int w = t >> 5, lane = t & 31;
    const int wm = w >> 2, wn = w & 3;          // warp tile: rows wm*64, cols wn*32
    const int m0 = blockIdx.y * 128, n0 = blockIdx.x * 128;

    float acc[4][4][4];
#pragma unroll
    for (int i = 0; i < 4; i++)
#pragma unroll
        for (int j = 0; j < 4; j++)
#pragma unroll
            for (int q = 0; q < 4; q++) acc[i][j][q] = 0.f;

    // ldmatrix source addresses (within-warp)
    const uint32_t aBase = smem_u32(sAh) +
        (uint32_t)(((wm*64 + (lane & 15)) * SRS + (lane >> 4) * 8) * 2);
    const uint32_t alBase = aBase + TILE_HALFS * 2;
    const uint32_t bBase = smem_u32(sBh) +
        (uint32_t)(((wn*32 + (lane & 7)) * SRS + ((lane >> 3) & 1) * 8) * 2);
    const uint32_t blBase = bBase + TILE_HALFS * 2;

    const int nch = Kd >> 6;
    for (int c = 0; c < nch; c++) {
        const int k0 = c << 6;
        if (c) __syncthreads();

        // ---- stage B chunk (pre-split bf16): 128 rows x 64 halfs ------------
#pragma unroll
        for (int it = 0; it < 4; it++) {
            const int idx = t + it * 256;           // 1024 uint4
            const int r = idx >> 3, j = idx & 7;
            const size_t goff = (size_t)(n0 + r) * Kd + k0 + j * 8;
            const uint32_t so = r * SRS + j * 8;
            *(uint4*)(sBh + so) = *(const uint4*)(Bh + goff);
            *(uint4*)(sBl + so) = *(const uint4*)(Bl + goff);
        }
        // ---- stage A chunk ---------------------------------------------------
        if (Afp) {   // fp32 -> split on the fly
#pragma unroll
            for (int it = 0; it < 8; it++) {
                const int idx = t + it * 256;       // 2048 float4
                const int r = idx >> 4, j = idx & 15;
                float4 v = *(const float4*)(Afp + (size_t)(m0 + r) * Kd + k0 + j * 4);
                __nv_bfloat162 h0 = __floats2bfloat162_rn(v.x, v.y);
                __nv_bfloat162 h1 = __floats2bfloat162_rn(v.z, v.w);
                __nv_bfloat162 l0 = __floats2bfloat162_rn(v.x - __bfloat162float(h0.x),
                                                          v.y - __bfloat162float(h0.y));
                __nv_bfloat162 l1 = __floats2bfloat162_rn(v.z - __bfloat162float(h1.x),
                                                          v.w - __bfloat162float(h1.y));
                const uint32_t so = r * SRS + j * 4;
                uint2 hh; hh.x = *(uint32_t*)&h0; hh.y = *(uint32_t*)&h1;
                uint2 ll; ll.x = *(uint32_t*)&l0; ll.y = *(uint32_t*)&l1;
                *(uint2*)(sAh + so) = hh;
                *(uint2*)(sAl + so) = ll;
            }
        } else {     // pre-split bf16 (optionally conv row-shift)
            const int tap = convmode ? (k0 >> 9) : 0;
            const int kl0 = convmode ? (k0 & 511) : k0;
#pragma unroll
            for (int it = 0; it < 4; it++) {
                const int idx = t + it * 256;
                const int r = idx >> 3, j = idx & 7;
                const int rg = m0 + r;
                uint4 vh = make_uint4(0,0,0,0), vl = make_uint4(0,0,0,0);
                if (convmode) {
                    const int tl = (rg & (Tz - 1)) + tap - 1;
                    if (tl >= 0 && tl < Tz) {
                        const size_t goff = (size_t)(rg + tap - 1) * ST + kl0 + j * 8;
                        vh = *(const uint4*)(Ah + goff);
                        vl = *(const uint4*)(Al + goff);
                    }
                } else {
                    const size_t goff = (size_t)rg * Kd + k0 + j * 8;
                    vh = *(const uint4*)(Ah + goff);
                    vl = *(const uint4*)(Al + goff);
                }
                const uint32_t so = r * SRS + j * 8;
                *(uint4*)(sAh + so) = vh;
                *(uint4*)(sAl + so) = vl;
            }
        }
        __syncthreads();

        // ---- compute: 4 k-steps of 16 ---------------------------------------
#pragma unroll
        for (int ks = 0; ks < 4; ks++) {
            const uint32_t koff = (uint32_t)(ks * 16 * 2);
            uint32_t ah[4][4], al[4][4], bh[4][2], bl[4][2];
#pragma unroll
            for (int mi = 0; mi < 4; mi++) {
                ldsm4(ah[mi], aBase  + (uint32_t)(mi * 16 * SRS * 2) + koff);
                ldsm4(al[mi], alBase + (uint32_t)(mi * 16 * SRS * 2) + koff);
            }
#pragma unroll
            for (int ni = 0; ni < 4; ni++) {
                ldsm2(bh[ni], bBase  + (uint32_t)(ni * 8 * SRS * 2) + koff);
                ldsm2(bl[ni], blBase + (uint32_t)(ni * 8 * SRS * 2) + koff);
            }
#pragma unroll
            for (int mi = 0; mi < 4; mi++)
#pragma unroll
                for (int ni = 0; ni < 4; ni++) {
                    mma16816(acc[mi][ni], ah[mi], bh[ni]);
                    mma16816(acc[mi][ni], ah[mi], bl[ni]);
                    mma16816(acc[mi][ni], al[mi], bh[ni]);
                }
        }
    }

    // ---- epilogue -------------------------------------------------------------
    const int g = lane >> 2, tg = lane & 3;
#pragma unroll
    for (int mi = 0; mi < 4; mi++) {
#pragma unroll
        for (int ni = 0; ni < 4; ni++) {
            const int col = n0 + wn*32 + ni*8 + tg*2;
            const float b0 = bias ? bias[col]     : 0.f;
            const float b1 = bias ? bias[col + 1] : 0.f;
#pragma unroll
            for (int half = 0; half < 2; half++) {
                const int row = m0 + wm*64 + mi*16 + g + half*8;
                float v0 = acc[mi][ni][half*2+0] + b0;
                float v1 = acc[mi][ni][half*2+1] + b1;
                if (act == 1) {
                    v0 = v0 / (1.f + expf(-v0));
                    v1 = v1 / (1.f + expf(-v1));
                }
                if (outf) {
                    float2 f2; f2.x = v0; f2.y = v1;
                    *(float2*)(outf + (size_t)row * N + col) = f2;
                }
                if (outh) {
                    __nv_bfloat162 h2 = __floats2bfloat162_rn(v0, v1);
                    __nv_bfloat162 l2 = __floats2bfloat162_rn(
                        v0 - __bfloat162float(h2.x), v1 - __bfloat162float(h2.y));
                    *(__nv_bfloat162*)(outh + (size_t)row * N + col) = h2;
                    *(__nv_bfloat162*)(outl + (size_t)row * N + col) = l2;
                }
            }
        }
    }
}

// ---------------- BN stats ----------------------------------------------------
__global__ __launch_bounds__(512)
void k_stats() {
    const int n = threadIdx.x;
    const int rpc = M_ROWS / 512;
    const int r0 = blockIdx.x * rpc;
    float s1 = 0.f, s2 = 0.f;
    for (int r = 0; r < rpc; r++) {
        float v = g_vc[(size_t)(r0 + r) * ST + n];
        s1 += v; s2 += v * v;
    }
    atomicAdd(&g_sum[n], s1);
    atomicAdd(&g_sumsq[n], s2);
}

// fold BN into Bm: Bt[j][i] = split(sc_i * Bm[i][j]); ubias[j] = sum sh_i*Bm[i][j]
__global__ __launch_bounds__(512)
void k_finalize(const float* __restrict__ Bm, const float* __restrict__ bng,
                const float* __restrict__ bnb) {
    __shared__ float sc[ST], sh[ST];
    const int j = threadIdx.x;
    float mu  = g_sum[j]   * (1.f / M_ROWS);
    float var = g_sumsq[j] * (1.f / M_ROWS) - mu * mu;
    float inv = rsqrtf(var + EPSC);
    float s   = bng[j] * inv;
    sc[j] = s;
    sh[j] = bnb[j] - mu * s;
    __syncthreads();
    float ub = 0.f;
    for (int i = 0; i < ST; i++) {
        float bmv = Bm[(size_t)i * ST + j];
        split2(sc[i] * bmv, g_bmh[(size_t)j * ST + i], g_bml[(size_t)j * ST + i]);
        ub += sh[i] * bmv;
    }
    g_ubias[j] = ub;
}

// ---------------- cluster recurrence (split-bf16 state out) -------------------
#define RC_SMEM_FLOATS 39064
__global__ __launch_bounds__(512, 1) __cluster_dims__(8, 1, 1)
void k_recur(const float* __restrict__ A, const float* __restrict__ lng,
             const float* __restrict__ lnb) {
    extern __shared__ float sm[];
    float* Atile = sm;            // [512][64]
    float* sbuf  = sm + 32768;    // [2][4][512]
    float* pbuf  = sm + 36864;    // [2][8][8]
    float* pred  = sm + 36992;    // [512][4]
    float* ws    = sm + 39040;    // [16]
    float* pl    = sm + 39056;    // [8]

    const int t    = threadIdx.x;
    const int rank = blockIdx.x;
    const int grp  = blockIdx.y;
    const int jg0  = rank * 64;

    for (int idx = t; idx < 512 * 16; idx += 512) {
        int i  = idx >> 4;
        int jv = (idx & 15) << 2;
        *(float4*)&Atile[i*64 + jv] = *(const float4*)(A + (size_t)i*ST + jg0 + jv);
    }
    for (int idx = t; idx < 4*512; idx += 512) sbuf[idx] = 0.f;

    const int ip = t >> 6;
    const int cc = (t >> 4) & 3;
    const int jq = t & 15;
    const int c2 = t >> 6;
    const int jj = t & 63;

    float gj = 0.f, bj = 0.f;
    size_t urow0 = 0;
    if (t < 256) {
        gj = lng[jg0 + jj];
        bj = lnb[jg0 + jj];
        const int chain = grp * 4 + c2;
        urow0 = (size_t)chain * Tz * ST + jg0 + jj;
    }

    const uint32_t sb_base = smem_u32(sbuf);
    const uint32_t pb_base = smem_u32(pbuf);

    asm volatile("barrier.cluster.arrive.aligned;\n" ::: "memory");
    asm volatile("barrier.cluster.wait.aligned;\n" ::: "memory");

    int p = 0;
    float uval = (t < 256) ? g_u[urow0] : 0.f;

    for (int step = 0; step < Tz; step++) {
        const float* sbp = sbuf + (p*4 + cc)*512;
        const float* Ap2 = Atile + jq*4;
        float4 acc = make_float4(0.f, 0.f, 0.f, 0.f);
#pragma unroll 4
        for (int i = ip*64; i < ip*64 + 64; i += 4) {
            float4 s4 = *(const float4*)(sbp + i);
            float4 a;
            a = *(const float4*)(Ap2 + (i+0)*64);
            acc.x = fmaf(s4.x, a.x, acc.x); acc.y = fmaf(s4.x, a.y, acc.y);
            acc.z = fmaf(s4.x, a.z, acc.z); acc.w = fmaf(s4.x, a.w, acc.w);
            a = *(const float4*)(Ap2 + (i+1)*64);
            acc.x = fmaf(s4.y, a.x, acc.x); acc.y = fmaf(s4.y, a.y, acc.y);
            acc.z = fmaf(s4.y, a.z, acc.z); acc.w = fmaf(s4.y, a.w, acc.w);
            a = *(const float4*)(Ap2 + (i+2)*64);
            acc.x = fmaf(s4.z, a.x, acc.x); acc.y = fmaf(s4.z, a.y, acc.y);
            acc.z = fmaf(s4.z, a.z, acc.z); acc.w = fmaf(s4.z, a.w, acc.w);
            a = *(const float4*)(Ap2 + (i+3)*64);
            acc.x = fmaf(s4.w, a.x, acc.x); acc.y = fmaf(s4.w, a.y, acc.y);
            acc.z = fmaf(s4.w, a.z, acc.z); acc.w = fmaf(s4.w, a.w, acc.w);
        }
        *(float4*)&pred[t*4] = acc;
        __syncthreads();

        float y = 0.f;
        if (t < 256) {
            y = uval;
#pragma unroll
            for (int q = 0; q < 8; q++)
                y += pred[(q*64 + c2*16 + (jj >> 2))*4 + (jj & 3)];
            float s1 = y, s2 = y*y;
#pragma unroll
            for (int o = 16; o > 0; o >>= 1) {
                s1 += __shfl_xor_sync(0xffffffffu, s1, o);
                s2 += __shfl_xor_sync(0xffffffffu, s2, o);
            }
            if ((t & 31) == 0) { ws[(t>>5)*2] = s1; ws[(t>>5)*2+1] = s2; }
        }
        __syncthreads();
        if (t < 4) {
            pl[t*2+0] = ws[t*4+0] + ws[t*4+2];
            pl[t*2+1] = ws[t*4+1] + ws[t*4+3];
        }
        __syncthreads();
        if (t < 64) {
            const int r = t >> 3, k = t & 7;
            const uint32_t la = pb_base + (uint32_t)(((p*8 + rank)*8 + k) * 4);
            uint32_t ra_;
            asm volatile("mapa.shared::cluster.u32 %0, %1, %2;" : "=r"(ra_) : "r"(la), "r"(r));
            asm volatile("st.shared::cluster.f32 [%0], %1;" :: "r"(ra_), "f"(pl[k]) : "memory");
        }
        float unext = 0.f;
        if (t < 256 && step + 1 < Tz)
            unext = g_u[urow0 + (size_t)(step + 1) * ST];

        asm volatile("barrier.cluster.arrive.aligned;\n" ::: "memory");
        asm volatile("barrier.cluster.wait.aligned;\n" ::: "memory");

        if (t < 256) {
            float q1 = 0.f, q2 = 0.f;
#pragma unroll
            for (int r = 0; r < 8; r++) {
                q1 += pbuf[(p*8 + r)*8 + c2*2 + 0];
                q2 += pbuf[(p*8 + r)*8 + c2*2 + 1];
            }
            const float mean = q1 * (1.f / ST);
            const float var  = q2 * (1.f / ST) - mean * mean;
            const float rstd = rsqrtf(var + EPSC);
            const float sval = (y - mean) * rstd * gj + bj;
            __nv_bfloat16 hh = __float2bfloat16(sval);
            g_sh[urow0 + (size_t)step * ST] = hh;
            g_sl[urow0 + (size_t)step * ST] =
                __float2bfloat16(sval - __bfloat162float(hh));
            const uint32_t la = sb_base + (uint32_t)(((((p^1)*4 + c2)*512) + jg0 + jj) * 4);
#pragma unroll
            for (int r = 0; r < 8; r++) {
                uint32_t ra_;
                asm volatile("mapa.shared::cluster.u32 %0, %1, %2;" : "=r"(ra_) : "r"(la), "r"(r));
                asm volatile("st.shared::cluster.f32 [%0], %1;" :: "r"(ra_), "f"(sval) : "memory");
            }
        }
        uval = unext;

        asm volatile("barrier.cluster.arrive.aligned;\n" ::: "memory");
        asm volatile("barrier.cluster.wait.aligned;\n" ::: "memory");
        p ^= 1;
    }
}

// ---------------- launch ------------------------------------------------------
extern "C" void kernel_launch(void* const* d_in, const int* in_sizes, int n_in,
                              void* d_out, int out_size) {
    const float* x      = (const float*)d_in[0];
    const float* W_in   = (const float*)d_in[1];
    const float* b_in   = (const float*)d_in[2];
    const float* conv_w = (const float*)d_in[3];
    const float* conv_b = (const float*)d_in[4];
    const float* bng    = (const float*)d_in[5];
    const float* bnb    = (const float*)d_in[6];
    const float* lng    = (const float*)d_in[7];
    const float* lnb    = (const float*)d_in[8];
    const float* A      = (const float*)d_in[9];
    const float* Bm     = (const float*)d_in[10];
    const float* C      = (const float*)d_in[11];
    float* out = (float*)d_out;

    void *p_vh, *p_vl, *p_vc, *p_u, *p_sh, *p_sl;
    void *p_wth, *p_wtl, *p_wkh, *p_wkl, *p_bmh, *p_bml, *p_cth, *p_ctl, *p_ub;
    cudaGetSymbolAddress(&p_vh,  g_vh);  cudaGetSymbolAddress(&p_vl,  g_vl);
    cudaGetSymbolAddress(&p_vc,  g_vc);  cudaGetSymbolAddress(&p_u,   g_u);
    cudaGetSymbolAddress(&p_sh,  g_sh);  cudaGetSymbolAddress(&p_sl,  g_sl);
    cudaGetSymbolAddress(&p_wth, g_wth); cudaGetSymbolAddress(&p_wtl, g_wtl);
    cudaGetSymbolAddress(&p_wkh, g_wkh); cudaGetSymbolAddress(&p_wkl, g_wkl);
    cudaGetSymbolAddress(&p_bmh, g_bmh); cudaGetSymbolAddress(&p_bml, g_bml);
    cudaGetSymbolAddress(&p_cth, g_cth); cudaGetSymbolAddress(&p_ctl, g_ctl);
    cudaGetSymbolAddress(&p_ub,  g_ubias);

    cudaFuncSetAttribute(k_tgemm, cudaFuncAttributeMaxDynamicSharedMemorySize, SMB_TOTAL);
    cudaFuncSetAttribute(k_recur, cudaFuncAttributeMaxDynamicSharedMemorySize,
                         RC_SMEM_FLOATS * 4);

    // 1) split/transpose weights, zero accumulators
    k_prep<<<1536, 512>>>(W_in, conv_w, C);
    // 2) v = silu(x @ W_in^T + b_in) -> split bf16
    k_tgemm<<<dim3(4, 1024), 256, SMB_TOTAL>>>(
        x, nullptr, nullptr, (const __nv_bfloat16*)p_wth, (const __nv_bfloat16*)p_wtl,
        b_in, nullptr, (__nv_bfloat16*)p_vh, (__nv_bfloat16*)p_vl, IND, ST, 1, 0);
    // 3) vc = conv1d(v) + conv_b  (virtual K=1536 GEMM) -> fp32
    k_tgemm<<<dim3(4, 1024), 256, SMB_TOTAL>>>(
        nullptr, (const __nv_bfloat16*)p_vh, (const __nv_bfloat16*)p_vl,
        (const __nv_bfloat16*)p_wkh, (const __nv_bfloat16*)p_wkl,
        conv_b, (float*)p_vc, nullptr, nullptr, 3*ST, ST, 0, 1);
    // 4) BN stats
    k_stats<<<512, 512>>>();
    // 5) fold BN into Bm (split)
    k_finalize<<<1, 512>>>(Bm, bng, bnb);
    // 6) u = vc_norm @ Bm + ubias -> fp32
    k_tgemm<<<dim3(4, 1024), 256, SMB_TOTAL>>>(
        (const float*)p_vc, nullptr, nullptr,
        (const __nv_bfloat16*)p_bmh, (const __nv_bfloat16*)p_bml,
        (const float*)p_ub, (float*)p_u, nullptr, nullptr, ST, ST, 0, 0);
    // 7) sequential recurrence -> split bf16 states
    k_recur<<<dim3(8, 16), 512, RC_SMEM_FLOATS * 4>>>(A, lng, lnb);
    // 8) y = S @ C
    k_tgemm<<<dim3(2, 1024), 256, SMB_TOTAL>>>(
        nullptr, (const __nv_bfloat16*)p_sh, (const __nv_bfloat16*)p_sl,
        (const __nv_bfloat16*)p_cth, (const __nv_bfloat16*)p_ctl,
        nullptr, out, nullptr, nullptr, ST, OD, 0, 0);
}

// round 6
// speedup vs baseline: 2.1454x; 1.0108x over previous
#include <cuda_runtime.h>
#include <cuda_bf16.h>
#include <math.h>
#include <cstdint>

#define Bz   64
#define Tz   2048
#define IND  256
#define ST   512
#define OD   256
#define M_ROWS (Bz*Tz)   // 131072
#define EPSC 1e-5f

// ---------------- scratch (static device memory) -----------------------------
__device__ __nv_bfloat16 g_xh[(size_t)M_ROWS*IND], g_xl[(size_t)M_ROWS*IND];
__device__ __nv_bfloat16 g_vh[(size_t)M_ROWS*ST],  g_vl[(size_t)M_ROWS*ST];
__device__ __nv_bfloat16 g_vch[(size_t)M_ROWS*ST], g_vcl[(size_t)M_ROWS*ST];
__device__ float         g_u [(size_t)M_ROWS*ST];
__device__ __nv_bfloat16 g_sh[(size_t)M_ROWS*ST],  g_sl[(size_t)M_ROWS*ST];
__device__ __nv_bfloat16 g_wth[ST*IND], g_wtl[ST*IND];     // W_in  Bt[n][k]
__device__ __nv_bfloat16 g_wkh[ST*3*ST], g_wkl[ST*3*ST];   // conv  Bt[n][tap*512+i]
__device__ __nv_bfloat16 g_bmh[ST*ST], g_bml[ST*ST];       // BN-folded Bm, Bt[j][i]
__device__ __nv_bfloat16 g_cth[OD*ST], g_ctl[OD*ST];       // C     Bt[n][k]
__device__ float g_ubias[ST];
__device__ float g_sum[ST];
__device__ float g_sumsq[ST];

__device__ __forceinline__ uint32_t smem_u32(const void* p) {
    return (uint32_t)__cvta_generic_to_shared(p);
}
__device__ __forceinline__ void split2(float x, __nv_bfloat16& h, __nv_bfloat16& l) {
    h = __float2bfloat16(x);
    l = __float2bfloat16(x - __bfloat162float(h));
}

// ---------------- prep: split/transpose all weights ---------------------------
__global__ void k_prep(const float* __restrict__ W_in, const float* __restrict__ conv_w,
                       const float* __restrict__ C) {
    int idx = blockIdx.x * blockDim.x + threadIdx.x;
    if (idx < ST*IND) {                 // W_in[n][k] -> Bt[n][k]
        split2(W_in[idx], g_wth[idx], g_wtl[idx]);
    }
    if (idx < ST*3*ST) {                // conv: Bt[n][tap*512+i] = conv_w[n][i][tap]
        int n = idx / (3*ST);
        int rem = idx % (3*ST);
        int tap = rem / ST, i = rem % ST;
        split2(conv_w[((size_t)n*ST + i)*3 + tap], g_wkh[idx], g_wkl[idx]);
    }
    if (idx < OD*ST) {                  // C[k][n] -> Ct[n][k]
        int n = idx / ST, k = idx % ST;
        split2(C[(size_t)k*OD + n], g_cth[idx], g_ctl[idx]);
    }
    if (idx < ST) { g_sum[idx] = 0.f; g_sumsq[idx] = 0.f; }
}

// split x -> bf16 hi/lo
__global__ __launch_bounds__(256)
void k_split(const float* __restrict__ x) {
    const size_t i = ((size_t)blockIdx.x * 256 + threadIdx.x) * 4;
    float4 v = *(const float4*)(x + i);
    __nv_bfloat162 h0 = __floats2bfloat162_rn(v.x, v.y);
    __nv_bfloat162 h1 = __floats2bfloat162_rn(v.z, v.w);
    __nv_bfloat162 l0 = __floats2bfloat162_rn(v.x - __bfloat162float(h0.x),
                                              v.y - __bfloat162float(h0.y));
    __nv_bfloat162 l1 = __floats2bfloat162_rn(v.z - __bfloat162float(h1.x),
                                              v.w - __bfloat162float(h1.y));
    uint2 hh; hh.x = *(uint32_t*)&h0; hh.y = *(uint32_t*)&h1;
    uint2 ll; ll.x = *(uint32_t*)&l0; ll.y = *(uint32_t*)&l1;
    *(uint2*)(g_xh + i) = hh;
    *(uint2*)(g_xl + i) = ll;
}

// ---------------- mma.sync helpers --------------------------------------------
__device__ __forceinline__ void mma16816(float* c, const uint32_t* a, const uint32_t* b) {
    asm volatile(
        "mma.sync.aligned.m16n8k16.row.col.f32.bf16.bf16.f32 "
        "{%0,%1,%2,%3}, {%4,%5,%6,%7}, {%8,%9}, {%0,%1,%2,%3};"
        : "+f"(c[0]), "+f"(c[1]), "+f"(c[2]), "+f"(c[3])
        : "r"(a[0]), "r"(a[1]), "r"(a[2]), "r"(a[3]), "r"(b[0]), "r"(b[1]));
}
__device__ __forceinline__ void ldsm4(uint32_t* r, uint32_t addr) {
    asm volatile("ldmatrix.sync.aligned.m8n8.x4.shared.b16 {%0,%1,%2,%3}, [%4];"
                 : "=r"(r[0]), "=r"(r[1]), "=r"(r[2]), "=r"(r[3]) : "r"(addr));
}
__device__ __forceinline__ void ldsm2(uint32_t* r, uint32_t addr) {
    asm volatile("ldmatrix.sync.aligned.m8n8.x2.shared.b16 {%0,%1}, [%2];"
                 : "=r"(r[0]), "=r"(r[1]) : "r"(addr));
}
__device__ __forceinline__ void cpa16(uint32_t dst, const void* src, bool pred) {
    int sz = pred ? 16 : 0;
    asm volatile("cp.async.cg.shared.global [%0], [%1], 16, %2;"
                 :: "r"(dst), "l"(src), "r"(sz) : "memory");
}
#define CPA_COMMIT() asm volatile("cp.async.commit_group;" ::: "memory")

// ---------------- split-bf16 warp-MMA GEMM -------------------------------------
// out[m,n] = act( sum_k A[m,k]*B[k,n] + bias[n] )
// 128x128 CTA tile, K-chunks of 64, cp.async double-buffered; B is Bt[n][k].
// smem rows 72 halfs (144B) -> conflict-free ldmatrix.
#define SRS 72
#define TILE_HALFS (128*SRS)             // 9216 halfs = 18432 B
#define CHUNK_HALFS (4*TILE_HALFS)       // Ah, Al, Bh, Bl
#define SMB_TOTAL (2*CHUNK_HALFS*2)      // double-buffered = 147456 B

__global__ __launch_bounds__(256, 1)
void k_tgemm(const __nv_bfloat16* __restrict__ Ah, const __nv_bfloat16* __restrict__ Al,
             const __nv_bfloat16* __restrict__ Bh, const __nv_bfloat16* __restrict__ Bl,
             const float* __restrict__ bias, float* __restrict__ outf,
             __nv_bfloat16* __restrict__ outh, __nv_bfloat16* __restrict__ outl,
             int Kd, int N, int act, int convmode) {
    extern __shared__ __nv_bfloat16 smem[];
    const int t = threadIdx.x;
    const int w = t >> 5, lane = t & 31;
    const int wm = w >> 2, wn = w & 3;
    const int m0 = blockIdx.y * 128, n0 = blockIdx.x * 128;

    float acc[4][4][4];
#pragma unroll
    for (int i = 0; i < 4; i++)
#pragma unroll
        for (int j = 0; j < 4; j++)
#pragma unroll
            for (int q = 0; q < 4; q++) acc[i][j][q] = 0.f;

    // ldmatrix base addrs in buffer 0 (byte offsets; add buf*CHUNK_HALFS*2)
    const uint32_t smb = smem_u32(smem);
    const uint32_t aBase = smb +
        (uint32_t)(((wm*64 + (lane & 15)) * SRS + (lane >> 4) * 8) * 2);
    const uint32_t alOff = TILE_HALFS * 2;
    const uint32_t bBase = smb + 2*TILE_HALFS*2 +
        (uint32_t)(((wn*32 + (lane & 7)) * SRS + ((lane >> 3) & 1) * 8) * 2);
    const uint32_t blOff = TILE_HALFS * 2;

    // staging indices
    const int sr = t >> 3, sj = t & 7;               // 32 rows x 8 col-chunks / pass
    const int nch = Kd >> 6;

    // stage chunk c into buffer buf (cp.async, 16 ops/thread)
    auto stage = [&](int c, int buf) {
        const int k0 = c << 6;
        __nv_bfloat16* base = smem + buf * CHUNK_HALFS;
        __nv_bfloat16* sAh = base;
        __nv_bfloat16* sAl = base + TILE_HALFS;
        __nv_bfloat16* sBh = base + 2*TILE_HALFS;
        __nv_bfloat16* sBl = base + 3*TILE_HALFS;
        const int tap = convmode ? (k0 >> 9) : 0;
        const int kl0 = convmode ? (k0 & 511) : k0;
#pragma unroll
        for (int it = 0; it < 4; it++) {
            const int r = sr + it * 32;
            const uint32_t so = (uint32_t)((r * SRS + sj * 8) * 2);
            // B
            {
                const size_t goff = (size_t)(n0 + r) * Kd + k0 + sj * 8;
                cpa16(smem_u32(sBh) + so, Bh + goff, true);
                cpa16(smem_u32(sBl) + so, Bl + goff, true);
            }
            // A
            {
                const int rg = m0 + r;
                bool pred = true;
                size_t goff;
                if (convmode) {
                    const int tl = (rg & (Tz - 1)) + tap - 1;
                    pred = (tl >= 0) && (tl < Tz);
                    const int rs = pred ? (rg + tap - 1) : rg;
                    goff = (size_t)rs * ST + kl0 + sj * 8;
                } else {
                    goff = (size_t)rg * Kd + k0 + sj * 8;
                }
                cpa16(smem_u32(sAh) + so, Ah + goff, pred);
                cpa16(smem_u32(sAl) + so, Al + goff, pred);
            }
        }
    };

    stage(0, 0);
    CPA_COMMIT();

    for (int c = 0; c < nch; c++) {
        const bool more = (c + 1) < nch;
        if (more) { stage(c + 1, (c + 1) & 1); CPA_COMMIT(); }
        if (more) asm volatile("cp.async.wait_group 1;" ::: "memory");
        else      asm volatile("cp.async.wait_group 0;" ::: "memory");
        __syncthreads();

        const uint32_t boff = (uint32_t)((c & 1) * CHUNK_HALFS * 2);
#pragma unroll
        for (int ks = 0; ks < 4; ks++) {
            const uint32_t koff = boff + (uint32_t)(ks * 32);
            uint32_t a[4][4], bh[4][2], bl[4][2];
#pragma unroll
            for (int mi = 0; mi < 4; mi++)
                ldsm4(a[mi], aBase + (uint32_t)(mi * 16 * SRS * 2) + koff);
#pragma unroll
            for (int ni = 0; ni < 4; ni++) {
                ldsm2(bh[ni], bBase + (uint32_t)(ni * 8 * SRS * 2) + koff);
                ldsm2(bl[ni], bBase + blOff + (uint32_t)(ni * 8 * SRS * 2) + koff);
            }
            // term hh
#pragma unroll
            for (int mi = 0; mi < 4; mi++)
#pragma unroll
                for (int ni = 0; ni < 4; ni++) mma16816(acc[mi][ni], a[mi], bh[ni]);
            // term hl
#pragma unroll
            for (int mi = 0; mi < 4; mi++)
#pragma unroll
                for (int ni = 0; ni < 4; ni++) mma16816(acc[mi][ni], a[mi], bl[ni]);
            // reload a <- A-lo, term lh
#pragma unroll
            for (int mi = 0; mi < 4; mi++)
                ldsm4(a[mi], aBase + alOff + (uint32_t)(mi * 16 * SRS * 2) + koff);
#pragma unroll
            for (int mi = 0; mi < 4; mi++)
#pragma unroll
                for (int ni = 0; ni < 4; ni++) mma16816(acc[mi][ni], a[mi], bh[ni]);
        }
        __syncthreads();
    }

    // ---- epilogue -------------------------------------------------------------
    const int g = lane >> 2, tg = lane & 3;
#pragma unroll
    for (int mi = 0; mi < 4; mi++) {
#pragma unroll
        for (int ni = 0; ni < 4; ni++) {
            const int col = n0 + wn*32 + ni*8 + tg*2;
            const float b0 = bias ? bias[col]     : 0.f;
            const float b1 = bias ? bias[col + 1] : 0.f;
#pragma unroll
            for (int half = 0; half < 2; half++) {
                const int row = m0 + wm*64 + mi*16 + g + half*8;
                float v0 = acc[mi][ni][half*2+0] + b0;
                float v1 = acc[mi][ni][half*2+1] + b1;
                if (act == 1) {
                    v0 = v0 / (1.f + expf(-v0));
                    v1 = v1 / (1.f + expf(-v1));
                }
                if (outf) {
                    float2 f2; f2.x = v0; f2.y = v1;
                    *(float2*)(outf + (size_t)row * N + col) = f2;
                }
                if (outh) {
                    __nv_bfloat162 h2 = __floats2bfloat162_rn(v0, v1);
                    __nv_bfloat162 l2 = __floats2bfloat162_rn(
                        v0 - __bfloat162float(h2.x), v1 - __bfloat162float(h2.y));
                    *(__nv_bfloat162*)(outh + (size_t)row * N + col) = h2;
                    *(__nv_bfloat162*)(outl + (size_t)row * N + col) = l2;
                }
            }
        }
    }
}

// ---------------- BN stats (from split vc) ------------------------------------
__global__ __launch_bounds__(512)
void k_stats() {
    const int n = threadIdx.x;
    const int rpc = M_ROWS / 512;
    const int r0 = blockIdx.x * rpc;
    float s1 = 0.f, s2 = 0.f;
    for (int r = 0; r < rpc; r++) {
        const size_t o = (size_t)(r0 + r) * ST + n;
        float v = __bfloat162float(g_vch[o]) + __bfloat162float(g_vcl[o]);
        s1 += v; s2 += v * v;
    }
    atomicAdd(&g_sum[n], s1);
    atomicAdd(&g_sumsq[n], s2);
}

// fold BN into Bm
__global__ __launch_bounds__(512)
void k_finalize(const float* __restrict__ Bm, const float* __restrict__ bng,
                const float* __restrict__ bnb) {
    __shared__ float sc[ST], sh[ST];
    const int j = threadIdx.x;
    float mu  = g_sum[j]   * (1.f / M_ROWS);
    float var = g_sumsq[j] * (1.f / M_ROWS) - mu * mu;
    float inv = rsqrtf(var + EPSC);
    float s   = bng[j] * inv;
    sc[j] = s;
    sh[j] = bnb[j] - mu * s;
    __syncthreads();
    float ub = 0.f;
    for (int i = 0; i < ST; i++) {
        float bmv = Bm[(size_t)i * ST + j];
        split2(sc[i] * bmv, g_bmh[(size_t)j * ST + i], g_bml[(size_t)j * ST + i]);
        ub += sh[i] * bmv;
    }
    g_ubias[j] = ub;
}

// ---------------- cluster recurrence (split-bf16 state out) -------------------
#define RC_SMEM_FLOATS 39064
__global__ __launch_bounds__(512, 1) __cluster_dims__(8, 1, 1)
void k_recur(const float* __restrict__ A, const float* __restrict__ lng,
             const float* __restrict__ lnb) {
    extern __shared__ float sm[];
    float* Atile = sm;            // [512][64]
    float* sbuf  = sm + 32768;    // [2][4][512]
    float* pbuf  = sm + 36864;    // [2][8][8]
    float* pred  = sm + 36992;    // [512][4]
    float* ws    = sm + 39040;    // [16]
    float* pl    = sm + 39056;    // [8]

    const int t    = threadIdx.x;
    const int rank = blockIdx.x;
    const int grp  = blockIdx.y;
    const int jg0  = rank * 64;

    for (int idx = t; idx < 512 * 16; idx += 512) {
        int i  = idx >> 4;
        int jv = (idx & 15) << 2;
        *(float4*)&Atile[i*64 + jv] = *(const float4*)(A + (size_t)i*ST + jg0 + jv);
    }
    for (int idx = t; idx < 4*512; idx += 512) sbuf[idx] = 0.f;

    const int ip = t >> 6;
    const int cc = (t >> 4) & 3;
    const int jq = t & 15;
    const int c2 = t >> 6;
    const int jj = t & 63;

    float gj = 0.f, bj = 0.f;
    size_t urow0 = 0;
    if (t < 256) {
        gj = lng[jg0 + jj];
        bj = lnb[jg0 + jj];
        const int chain = grp * 4 + c2;
        urow0 = (size_t)chain * Tz * ST + jg0 + jj;
    }

    const uint32_t sb_base = smem_u32(sbuf);
    const uint32_t pb_base = smem_u32(pbuf);

    asm volatile("barrier.cluster.arrive.aligned;\n" ::: "memory");
    asm volatile("barrier.cluster.wait.aligned;\n" ::: "memory");

    int p = 0;
    float uval = (t < 256) ? g_u[urow0] : 0.f;

    for (int step = 0; step < Tz; step++) {
        const float* sbp = sbuf + (p*4 + cc)*512;
        const float* Ap2 = Atile + jq*4;
        float4 acc = make_float4(0.f, 0.f, 0.f, 0.f);
#pragma unroll 4
        for (int i = ip*64; i < ip*64 + 64; i += 4) {
            float4 s4 = *(const float4*)(sbp + i);
            float4 a;
            a = *(const float4*)(Ap2 + (i+0)*64);
            acc.x = fmaf(s4.x, a.x, acc.x); acc.y = fmaf(s4.x, a.y, acc.y);
            acc.z = fmaf(s4.x, a.z, acc.z); acc.w = fmaf(s4.x, a.w, acc.w);
            a = *(const float4*)(Ap2 + (i+1)*64);
            acc.x = fmaf(s4.y, a.x, acc.x); acc.y = fmaf(s4.y, a.y, acc.y);
            acc.z = fmaf(s4.y, a.z, acc.z); acc.w = fmaf(s4.y, a.w, acc.w);
            a = *(const float4*)(Ap2 + (i+2)*64);
            acc.x = fmaf(s4.z, a.x, acc.x); acc.y = fmaf(s4.z, a.y, acc.y);
            acc.z = fmaf(s4.z, a.z, acc.z); acc.w = fmaf(s4.z, a.w, acc.w);
            a = *(const float4*)(Ap2 + (i+3)*64);
            acc.x = fmaf(s4.w, a.x, acc.x); acc.y = fmaf(s4.w, a.y, acc.y);
            acc.z = fmaf(s4.w, a.z, acc.z); acc.w = fmaf(s4.w, a.w, acc.w);
        }
        *(float4*)&pred[t*4] = acc;
        __syncthreads();

        float y = 0.f;
        if (t < 256) {
            y = uval;
#pragma unroll
            for (int q = 0; q < 8; q++)
                y += pred[(q*64 + c2*16 + (jj >> 2))*4 + (jj & 3)];
            float s1 = y, s2 = y*y;
#pragma unroll
            for (int o = 16; o > 0; o >>= 1) {
                s1 += __shfl_xor_sync(0xffffffffu, s1, o);
                s2 += __shfl_xor_sync(0xffffffffu, s2, o);
            }
            if ((t & 31) == 0) { ws[(t>>5)*2] = s1; ws[(t>>5)*2+1] = s2; }
        }
        __syncthreads();
        if (t < 4) {
            pl[t*2+0] = ws[t*4+0] + ws[t*4+2];
            pl[t*2+1] = ws[t*4+1] + ws[t*4+3];
        }
        __syncthreads();
        if (t < 64) {
            const int r = t >> 3, k = t & 7;
            const uint32_t la = pb_base + (uint32_t)(((p*8 + rank)*8 + k) * 4);
            uint32_t ra_;
            asm volatile("mapa.shared::cluster.u32 %0, %1, %2;" : "=r"(ra_) : "r"(la), "r"(r));
            asm volatile("st.shared::cluster.f32 [%0], %1;" :: "r"(ra_), "f"(pl[k]) : "memory");
        }
        float unext = 0.f;
        if (t < 256 && step + 1 < Tz)
            unext = g_u[urow0 + (size_t)(step + 1) * ST];

        asm volatile("barrier.cluster.arrive.aligned;\n" ::: "memory");
        asm volatile("barrier.cluster.wait.aligned;\n" ::: "memory");

        if (t < 256) {
            float q1 = 0.f, q2 = 0.f;
#pragma unroll
            for (int r = 0; r < 8; r++) {
                q1 += pbuf[(p*8 + r)*8 + c2*2 + 0];
                q2 += pbuf[(p*8 + r)*8 + c2*2 + 1];
            }
            const float mean = q1 * (1.f / ST);
            const float var  = q2 * (1.f / ST) - mean * mean;
            const float rstd = rsqrtf(var + EPSC);
            const float sval = (y - mean) * rstd * gj + bj;
            __nv_bfloat16 hh = __float2bfloat16(sval);
            g_sh[urow0 + (size_t)step * ST] = hh;
            g_sl[urow0 + (size_t)step * ST] =
                __float2bfloat16(sval - __bfloat162float(hh));
            const uint32_t la = sb_base + (uint32_t)(((((p^1)*4 + c2)*512) + jg0 + jj) * 4);
#pragma unroll
            for (int r = 0; r < 8; r++) {
                uint32_t ra_;
                asm volatile("mapa.shared::cluster.u32 %0, %1, %2;" : "=r"(ra_) : "r"(la), "r"(r));
                asm volatile("st.shared::cluster.f32 [%0], %1;" :: "r"(ra_), "f"(sval) : "memory");
            }
        }
        uval = unext;

        asm volatile("barrier.cluster.arrive.aligned;\n" ::: "memory");
        asm volatile("barrier.cluster.wait.aligned;\n" ::: "memory");
        p ^= 1;
    }
}

// ---------------- launch ------------------------------------------------------
extern "C" void kernel_launch(void* const* d_in, const int* in_sizes, int n_in,
                              void* d_out, int out_size) {
    const float* x      = (const float*)d_in[0];
    const float* W_in   = (const float*)d_in[1];
    const float* b_in   = (const float*)d_in[2];
    const float* conv_w = (const float*)d_in[3];
    const float* conv_b = (const float*)d_in[4];
    const float* bng    = (const float*)d_in[5];
    const float* bnb    = (const float*)d_in[6];
    const float* lng    = (const float*)d_in[7];
    const float* lnb    = (const float*)d_in[8];
    const float* A      = (const float*)d_in[9];
    const float* Bm     = (const float*)d_in[10];
    const float* C      = (const float*)d_in[11];
    float* out = (float*)d_out;

    void *p_xh, *p_xl, *p_vh, *p_vl, *p_vch, *p_vcl, *p_u, *p_sh, *p_sl;
    void *p_wth, *p_wtl, *p_wkh, *p_wkl, *p_bmh, *p_bml, *p_cth, *p_ctl, *p_ub;
    cudaGetSymbolAddress(&p_xh,  g_xh);  cudaGetSymbolAddress(&p_xl,  g_xl);
    cudaGetSymbolAddress(&p_vh,  g_vh);  cudaGetSymbolAddress(&p_vl,  g_vl);
    cudaGetSymbolAddress(&p_vch, g_vch); cudaGetSymbolAddress(&p_vcl, g_vcl);
    cudaGetSymbolAddress(&p_u,   g_u);
    cudaGetSymbolAddress(&p_sh,  g_sh);  cudaGetSymbolAddress(&p_sl,  g_sl);
    cudaGetSymbolAddress(&p_wth, g_wth); cudaGetSymbolAddress(&p_wtl, g_wtl);
    cudaGetSymbolAddress(&p_wkh, g_wkh); cudaGetSymbolAddress(&p_wkl, g_wkl);
    cudaGetSymbolAddress(&p_bmh, g_bmh); cudaGetSymbolAddress(&p_bml, g_bml);
    cudaGetSymbolAddress(&p_cth, g_cth); cudaGetSymbolAddress(&p_ctl, g_ctl);
    cudaGetSymbolAddress(&p_ub,  g_ubias);

    cudaFuncSetAttribute(k_tgemm, cudaFuncAttributeMaxDynamicSharedMemorySize, SMB_TOTAL);
    cudaFuncSetAttribute(k_recur, cudaFuncAttributeMaxDynamicSharedMemorySize,
                         RC_SMEM_FLOATS * 4);

    // 1) weights + x split
    k_prep<<<1536, 512>>>(W_in, conv_w, C);
    k_split<<<(M_ROWS*IND)/1024, 256>>>(x);
    // 2) v = silu(x @ W_in^T + b_in) -> split
    k_tgemm<<<dim3(4, 1024), 256, SMB_TOTAL>>>(
        (const __nv_bfloat16*)p_xh, (const __nv_bfloat16*)p_xl,
        (const __nv_bfloat16*)p_wth, (const __nv_bfloat16*)p_wtl,
        b_in, nullptr, (__nv_bfloat16*)p_vh, (__nv_bfloat16*)p_vl, IND, ST, 1, 0);
    // 3) vc = conv1d(v) + conv_b -> split
    k_tgemm<<<dim3(4, 1024), 256, SMB_TOTAL>>>(
        (const __nv_bfloat16*)p_vh, (const __nv_bfloat16*)p_vl,
        (const __nv_bfloat16*)p_wkh, (const __nv_bfloat16*)p_wkl,
        conv_b, nullptr, (__nv_bfloat16*)p_vch, (__nv_bfloat16*)p_vcl, 3*ST, ST, 0, 1);
    // 4) BN stats
    k_stats<<<512, 512>>>();
    // 5) fold BN into Bm
    k_finalize<<<1, 512>>>(Bm, bng, bnb);
    // 6) u = vc_norm @ Bm + ubias -> fp32
    k_tgemm<<<dim3(4, 1024), 256, SMB_TOTAL>>>(
        (const __nv_bfloat16*)p_vch, (const __nv_bfloat16*)p_vcl,
        (const __nv_bfloat16*)p_bmh, (const __nv_bfloat16*)p_bml,
        (const float*)p_ub, (float*)p_u, nullptr, nullptr, ST, ST, 0, 0);
    // 7) sequential recurrence
    k_recur<<<dim3(8, 16), 512, RC_SMEM_FLOATS * 4>>>(A, lng, lnb);
    // 8) y = S @ C
    k_tgemm<<<dim3(2, 1024), 256, SMB_TOTAL>>>(
        (const __nv_bfloat16*)p_sh, (const __nv_bfloat16*)p_sl,
        (const __nv_bfloat16*)p_cth, (const __nv_bfloat16*)p_ctl,
        nullptr, out, nullptr, nullptr, ST, OD, 0, 0);
}

// round 7
// speedup vs baseline: 2.1477x; 1.0011x over previous
#include <cuda_runtime.h>
#include <cuda_bf16.h>
#include <math.h>
#include <cstdint>

#define Bz   64
#define Tz   2048
#define IND  256
#define ST   512
#define OD   256
#define M_ROWS (Bz*Tz)   // 131072
#define EPSC 1e-5f

// ---------------- scratch (static device memory) -----------------------------
__device__ __nv_bfloat16 g_xh[(size_t)M_ROWS*IND], g_xl[(size_t)M_ROWS*IND];
__device__ __nv_bfloat16 g_vh[(size_t)M_ROWS*ST],  g_vl[(size_t)M_ROWS*ST];
__device__ __nv_bfloat16 g_vch[(size_t)M_ROWS*ST], g_vcl[(size_t)M_ROWS*ST];
__device__ float         g_u [(size_t)M_ROWS*ST];
__device__ __nv_bfloat16 g_sh[(size_t)M_ROWS*ST],  g_sl[(size_t)M_ROWS*ST];
__device__ __nv_bfloat16 g_wth[ST*IND], g_wtl[ST*IND];     // W_in  Bt[n][k]
__device__ __nv_bfloat16 g_wkh[ST*3*ST], g_wkl[ST*3*ST];   // conv  Bt[n][tap*512+i]
__device__ __nv_bfloat16 g_bmh[ST*ST], g_bml[ST*ST];       // BN-folded Bm, Bt[j][i]
__device__ __nv_bfloat16 g_cth[OD*ST], g_ctl[OD*ST];       // C     Bt[n][k]
__device__ float g_ubias[ST];
__device__ float g_sum[ST];
__device__ float g_sumsq[ST];

__device__ __forceinline__ uint32_t smem_u32(const void* p) {
    return (uint32_t)__cvta_generic_to_shared(p);
}
__device__ __forceinline__ void split2(float x, __nv_bfloat16& h, __nv_bfloat16& l) {
    h = __float2bfloat16(x);
    l = __float2bfloat16(x - __bfloat162float(h));
}

// ---------------- prep: split/transpose all weights ---------------------------
__global__ void k_prep(const float* __restrict__ W_in, const float* __restrict__ conv_w,
                       const float* __restrict__ C) {
    int idx = blockIdx.x * blockDim.x + threadIdx.x;
    if (idx < ST*IND) {                 // W_in[n][k] -> Bt[n][k]
        split2(W_in[idx], g_wth[idx], g_wtl[idx]);
    }
    if (idx < ST*3*ST) {                // conv: Bt[n][tap*512+i] = conv_w[n][i][tap]
        int n = idx / (3*ST);
        int rem = idx % (3*ST);
        int tap = rem / ST, i = rem % ST;
        split2(conv_w[((size_t)n*ST + i)*3 + tap], g_wkh[idx], g_wkl[idx]);
    }
    if (idx < OD*ST) {                  // C[k][n] -> Ct[n][k]
        int n = idx / ST, k = idx % ST;
        split2(C[(size_t)k*OD + n], g_cth[idx], g_ctl[idx]);
    }
    if (idx < ST) { g_sum[idx] = 0.f; g_sumsq[idx] = 0.f; }
}

// split x -> bf16 hi/lo
__global__ __launch_bounds__(256)
void k_split(const float* __restrict__ x) {
    const size_t i = ((size_t)blockIdx.x * 256 + threadIdx.x) * 4;
    float4 v = *(const float4*)(x + i);
    __nv_bfloat162 h0 = __floats2bfloat162_rn(v.x, v.y);
    __nv_bfloat162 h1 = __floats2bfloat162_rn(v.z, v.w);
    __nv_bfloat162 l0 = __floats2bfloat162_rn(v.x - __bfloat162float(h0.x),
                                              v.y - __bfloat162float(h0.y));
    __nv_bfloat162 l1 = __floats2bfloat162_rn(v.z - __bfloat162float(h1.x),
                                              v.w - __bfloat162float(h1.y));
    uint2 hh; hh.x = *(uint32_t*)&h0; hh.y = *(uint32_t*)&h1;
    uint2 ll; ll.x = *(uint32_t*)&l0; ll.y = *(uint32_t*)&l1;
    *(uint2*)(g_xh + i) = hh;
    *(uint2*)(g_xl + i) = ll;
}

// ---------------- mma.sync helpers --------------------------------------------
__device__ __forceinline__ void mma16816(float* c, const uint32_t* a, const uint32_t* b) {
    asm volatile(
        "mma.sync.aligned.m16n8k16.row.col.f32.bf16.bf16.f32 "
        "{%0,%1,%2,%3}, {%4,%5,%6,%7}, {%8,%9}, {%0,%1,%2,%3};"
        : "+f"(c[0]), "+f"(c[1]), "+f"(c[2]), "+f"(c[3])
        : "r"(a[0]), "r"(a[1]), "r"(a[2]), "r"(a[3]), "r"(b[0]), "r"(b[1]));
}
__device__ __forceinline__ void ldsm4(uint32_t* r, uint32_t addr) {
    asm volatile("ldmatrix.sync.aligned.m8n8.x4.shared.b16 {%0,%1,%2,%3}, [%4];"
                 : "=r"(r[0]), "=r"(r[1]), "=r"(r[2]), "=r"(r[3]) : "r"(addr));
}
__device__ __forceinline__ void ldsm2(uint32_t* r, uint32_t addr) {
    asm volatile("ldmatrix.sync.aligned.m8n8.x2.shared.b16 {%0,%1}, [%2];"
                 : "=r"(r[0]), "=r"(r[1]) : "r"(addr));
}
__device__ __forceinline__ void cpa16(uint32_t dst, const void* src, bool pred) {
    int sz = pred ? 16 : 0;
    asm volatile("cp.async.cg.shared.global [%0], [%1], 16, %2;"
                 :: "r"(dst), "l"(src), "r"(sz) : "memory");
}
#define CPA_COMMIT() asm volatile("cp.async.commit_group;" ::: "memory")

// ---------------- split-bf16 warp-MMA GEMM -------------------------------------
// 128x128 CTA tile, K-chunks of 64, cp.async double-buffered smem,
// register-fragment double-buffered k-steps; B given as Bt[n][k].
#define SRS 72
#define TILE_HALFS (128*SRS)             // 9216 halfs = 18432 B
#define CHUNK_HALFS (4*TILE_HALFS)       // Ah, Al, Bh, Bl
#define SMB_TOTAL (2*CHUNK_HALFS*2)      // double-buffered = 147456 B

__global__ __launch_bounds__(256, 1)
void k_tgemm(const __nv_bfloat16* __restrict__ Ah, const __nv_bfloat16* __restrict__ Al,
             const __nv_bfloat16* __restrict__ Bh, const __nv_bfloat16* __restrict__ Bl,
             const float* __restrict__ bias, float* __restrict__ outf,
             __nv_bfloat16* __restrict__ outh, __nv_bfloat16* __restrict__ outl,
             int Kd, int N, int act, int convmode) {
    extern __shared__ __nv_bfloat16 smem[];
    const int t = threadIdx.x;
    const int w = t >> 5, lane = t & 31;
    const int wm = w >> 2, wn = w & 3;
    const int m0 = blockIdx.y * 128, n0 = blockIdx.x * 128;

    float acc[4][4][4];
#pragma unroll
    for (int i = 0; i < 4; i++)
#pragma unroll
        for (int j = 0; j < 4; j++)
#pragma unroll
            for (int q = 0; q < 4; q++) acc[i][j][q] = 0.f;

    const uint32_t smb = smem_u32(smem);
    const uint32_t aBase = smb +
        (uint32_t)(((wm*64 + (lane & 15)) * SRS + (lane >> 4) * 8) * 2);
    const uint32_t alOff = TILE_HALFS * 2;
    const uint32_t bBase = smb + 2*TILE_HALFS*2 +
        (uint32_t)(((wn*32 + (lane & 7)) * SRS + ((lane >> 3) & 1) * 8) * 2);
    const uint32_t blOff = TILE_HALFS * 2;

    const int sr = t >> 3, sj = t & 7;
    const int nch = Kd >> 6;

    auto stage = [&](int c, int buf) {
        const int k0 = c << 6;
        __nv_bfloat16* base = smem + buf * CHUNK_HALFS;
        __nv_bfloat16* sAh = base;
        __nv_bfloat16* sAl = base + TILE_HALFS;
        __nv_bfloat16* sBh = base + 2*TILE_HALFS;
        __nv_bfloat16* sBl = base + 3*TILE_HALFS;
        const int tap = convmode ? (k0 >> 9) : 0;
        const int kl0 = convmode ? (k0 & 511) : k0;
#pragma unroll
        for (int it = 0; it < 4; it++) {
            const int r = sr + it * 32;
            const uint32_t so = (uint32_t)((r * SRS + sj * 8) * 2);
            {
                const size_t goff = (size_t)(n0 + r) * Kd + k0 + sj * 8;
                cpa16(smem_u32(sBh) + so, Bh + goff, true);
                cpa16(smem_u32(sBl) + so, Bl + goff, true);
            }
            {
                const int rg = m0 + r;
                bool pred = true;
                size_t goff;
                if (convmode) {
                    const int tl = (rg & (Tz - 1)) + tap - 1;
                    pred = (tl >= 0) && (tl < Tz);
                    const int rs = pred ? (rg + tap - 1) : rg;
                    goff = (size_t)rs * ST + kl0 + sj * 8;
                } else {
                    goff = (size_t)rg * Kd + k0 + sj * 8;
                }
                cpa16(smem_u32(sAh) + so, Ah + goff, pred);
                cpa16(smem_u32(sAl) + so, Al + goff, pred);
            }
        }
    };

    // register fragments: double-buffered across k-steps
    uint32_t fah[2][4][4], fal[2][4][4], fbh[2][4][2], fbl[2][4][2];

    auto ldfrag = [&](int slot, uint32_t koff) {
#pragma unroll
        for (int mi = 0; mi < 4; mi++)
            ldsm4(fah[slot][mi], aBase + (uint32_t)(mi * 16 * SRS * 2) + koff);
#pragma unroll
        for (int mi = 0; mi < 4; mi++)
            ldsm4(fal[slot][mi], aBase + alOff + (uint32_t)(mi * 16 * SRS * 2) + koff);
#pragma unroll
        for (int ni = 0; ni < 4; ni++) {
            ldsm2(fbh[slot][ni], bBase + (uint32_t)(ni * 8 * SRS * 2) + koff);
            ldsm2(fbl[slot][ni], bBase + blOff + (uint32_t)(ni * 8 * SRS * 2) + koff);
        }
    };

    stage(0, 0);
    CPA_COMMIT();

    for (int c = 0; c < nch; c++) {
        const bool more = (c + 1) < nch;
        if (more) { stage(c + 1, (c + 1) & 1); CPA_COMMIT(); }
        if (more) asm volatile("cp.async.wait_group 1;" ::: "memory");
        else      asm volatile("cp.async.wait_group 0;" ::: "memory");
        __syncthreads();

        const uint32_t boff = (uint32_t)((c & 1) * CHUNK_HALFS * 2);
        ldfrag(0, boff);
#pragma unroll
        for (int ks = 0; ks < 4; ks++) {
            const int cur = ks & 1;
            if (ks < 3) ldfrag(cur ^ 1, boff + (uint32_t)((ks + 1) * 32));
            // term hh
#pragma unroll
            for (int mi = 0; mi < 4; mi++)
#pragma unroll
                for (int ni = 0; ni < 4; ni++)
                    mma16816(acc[mi][ni], fah[cur][mi], fbh[cur][ni]);
            // term hl
#pragma unroll
            for (int mi = 0; mi < 4; mi++)
#pragma unroll
                for (int ni = 0; ni < 4; ni++)
                    mma16816(acc[mi][ni], fah[cur][mi], fbl[cur][ni]);
            // term lh
#pragma unroll
            for (int mi = 0; mi < 4; mi++)
#pragma unroll
                for (int ni = 0; ni < 4; ni++)
                    mma16816(acc[mi][ni], fal[cur][mi], fbh[cur][ni]);
        }
        __syncthreads();
    }

    // ---- epilogue -------------------------------------------------------------
    const int g = lane >> 2, tg = lane & 3;
#pragma unroll
    for (int mi = 0; mi < 4; mi++) {
#pragma unroll
        for (int ni = 0; ni < 4; ni++) {
            const int col = n0 + wn*32 + ni*8 + tg*2;
            const float b0 = bias ? bias[col]     : 0.f;
            const float b1 = bias ? bias[col + 1] : 0.f;
#pragma unroll
            for (int half = 0; half < 2; half++) {
                const int row = m0 + wm*64 + mi*16 + g + half*8;
                float v0 = acc[mi][ni][half*2+0] + b0;
                float v1 = acc[mi][ni][half*2+1] + b1;
                if (act == 1) {
                    v0 = v0 / (1.f + expf(-v0));
                    v1 = v1 / (1.f + expf(-v1));
                }
                if (outf) {
                    float2 f2; f2.x = v0; f2.y = v1;
                    *(float2*)(outf + (size_t)row * N + col) = f2;
                }
                if (outh) {
                    __nv_bfloat162 h2 = __floats2bfloat162_rn(v0, v1);
                    __nv_bfloat162 l2 = __floats2bfloat162_rn(
                        v0 - __bfloat162float(h2.x), v1 - __bfloat162float(h2.y));
                    *(__nv_bfloat162*)(outh + (size_t)row * N + col) = h2;
                    *(__nv_bfloat162*)(outl + (size_t)row * N + col) = l2;
                }
            }
        }
    }
}

// ---------------- BN stats (from split vc) ------------------------------------
__global__ __launch_bounds__(512)
void k_stats() {
    const int n = threadIdx.x;
    const int rpc = M_ROWS / 512;
    const int r0 = blockIdx.x * rpc;
    float s1 = 0.f, s2 = 0.f;
    for (int r = 0; r < rpc; r++) {
        const size_t o = (size_t)(r0 + r) * ST + n;
        float v = __bfloat162float(g_vch[o]) + __bfloat162float(g_vcl[o]);
        s1 += v; s2 += v * v;
    }
    atomicAdd(&g_sum[n], s1);
    atomicAdd(&g_sumsq[n], s2);
}

// fold BN into Bm
__global__ __launch_bounds__(512)
void k_finalize(const float* __restrict__ Bm, const float* __restrict__ bng,
                const float* __restrict__ bnb) {
    __shared__ float sc[ST], sh[ST];
    const int j = threadIdx.x;
    float mu  = g_sum[j]   * (1.f / M_ROWS);
    float var = g_sumsq[j] * (1.f / M_ROWS) - mu * mu;
    float inv = rsqrtf(var + EPSC);
    float s   = bng[j] * inv;
    sc[j] = s;
    sh[j] = bnb[j] - mu * s;
    __syncthreads();
    float ub = 0.f;
    for (int i = 0; i < ST; i++) {
        float bmv = Bm[(size_t)i * ST + j];
        split2(sc[i] * bmv, g_bmh[(size_t)j * ST + i], g_bml[(size_t)j * ST + i]);
        ub += sh[i] * bmv;
    }
    g_ubias[j] = ub;
}

// ---------------- cluster recurrence (split-bf16 state out) -------------------
#define RC_SMEM_FLOATS 39064
__global__ __launch_bounds__(512, 1) __cluster_dims__(8, 1, 1)
void k_recur(const float* __restrict__ A, const float* __restrict__ lng,
             const float* __restrict__ lnb) {
    extern __shared__ float sm[];
    float* Atile = sm;            // [512][64]
    float* sbuf  = sm + 32768;    // [2][4][512]
    float* pbuf  = sm + 36864;    // [2][8][8]
    float* pred  = sm + 36992;    // [512][4]
    float* ws    = sm + 39040;    // [16]
    float* pl    = sm + 39056;    // [8]

    const int t    = threadIdx.x;
    const int rank = blockIdx.x;
    const int grp  = blockIdx.y;
    const int jg0  = rank * 64;

    for (int idx = t; idx < 512 * 16; idx += 512) {
        int i  = idx >> 4;
        int jv = (idx & 15) << 2;
        *(float4*)&Atile[i*64 + jv] = *(const float4*)(A + (size_t)i*ST + jg0 + jv);
    }
    for (int idx = t; idx < 4*512; idx += 512) sbuf[idx] = 0.f;

    const int ip = t >> 6;
    const int cc = (t >> 4) & 3;
    const int jq = t & 15;
    const int c2 = t >> 6;
    const int jj = t & 63;

    float gj = 0.f, bj = 0.f;
    size_t urow0 = 0;
    if (t < 256) {
        gj = lng[jg0 + jj];
        bj = lnb[jg0 + jj];
        const int chain = grp * 4 + c2;
        urow0 = (size_t)chain * Tz * ST + jg0 + jj;
    }

    const uint32_t sb_base = smem_u32(sbuf);
    const uint32_t pb_base = smem_u32(pbuf);

    asm volatile("barrier.cluster.arrive.aligned;\n" ::: "memory");
    asm volatile("barrier.cluster.wait.aligned;\n" ::: "memory");

    int p = 0;
    float uval = (t < 256) ? g_u[urow0] : 0.f;

    for (int step = 0; step < Tz; step++) {
        const float* sbp = sbuf + (p*4 + cc)*512;
        const float* Ap2 = Atile + jq*4;
        float4 acc = make_float4(0.f, 0.f, 0.f, 0.f);
#pragma unroll 4
        for (int i = ip*64; i < ip*64 + 64; i += 4) {
            float4 s4 = *(const float4*)(sbp + i);
            float4 a;
            a = *(const float4*)(Ap2 + (i+0)*64);
            acc.x = fmaf(s4.x, a.x, acc.x); acc.y = fmaf(s4.x, a.y, acc.y);
            acc.z = fmaf(s4.x, a.z, acc.z); acc.w = fmaf(s4.x, a.w, acc.w);
            a = *(const float4*)(Ap2 + (i+1)*64);
            acc.x = fmaf(s4.y, a.x, acc.x); acc.y = fmaf(s4.y, a.y, acc.y);
            acc.z = fmaf(s4.y, a.z, acc.z); acc.w = fmaf(s4.y, a.w, acc.w);
            a = *(const float4*)(Ap2 + (i+2)*64);
            acc.x = fmaf(s4.z, a.x, acc.x); acc.y = fmaf(s4.z, a.y, acc.y);
            acc.z = fmaf(s4.z, a.z, acc.z); acc.w = fmaf(s4.z, a.w, acc.w);
            a = *(const float4*)(Ap2 + (i+3)*64);
            acc.x = fmaf(s4.w, a.x, acc.x); acc.y = fmaf(s4.w, a.y, acc.y);
            acc.z = fmaf(s4.w, a.z, acc.z); acc.w = fmaf(s4.w, a.w, acc.w);
        }
        *(float4*)&pred[t*4] = acc;
        __syncthreads();

        float y = 0.f;
        if (t < 256) {
            y = uval;
#pragma unroll
            for (int q = 0; q < 8; q++)
                y += pred[(q*64 + c2*16 + (jj >> 2))*4 + (jj & 3)];
            float s1 = y, s2 = y*y;
#pragma unroll
            for (int o = 16; o > 0; o >>= 1) {
                s1 += __shfl_xor_sync(0xffffffffu, s1, o);
                s2 += __shfl_xor_sync(0xffffffffu, s2, o);
            }
            if ((t & 31) == 0) { ws[(t>>5)*2] = s1; ws[(t>>5)*2+1] = s2; }
        }
        __syncthreads();
        if (t < 4) {
            pl[t*2+0] = ws[t*4+0] + ws[t*4+2];
            pl[t*2+1] = ws[t*4+1] + ws[t*4+3];
        }
        __syncthreads();
        if (t < 64) {
            const int r = t >> 3, k = t & 7;
            const uint32_t la = pb_base + (uint32_t)(((p*8 + rank)*8 + k) * 4);
            uint32_t ra_;
            asm volatile("mapa.shared::cluster.u32 %0, %1, %2;" : "=r"(ra_) : "r"(la), "r"(r));
            asm volatile("st.shared::cluster.f32 [%0], %1;" :: "r"(ra_), "f"(pl[k]) : "memory");
        }
        float unext = 0.f;
        if (t < 256 && step + 1 < Tz)
            unext = g_u[urow0 + (size_t)(step + 1) * ST];

        asm volatile("barrier.cluster.arrive.aligned;\n" ::: "memory");
        asm volatile("barrier.cluster.wait.aligned;\n" ::: "memory");

        if (t < 256) {
            float q1 = 0.f, q2 = 0.f;
#pragma unroll
            for (int r = 0; r < 8; r++) {
                q1 += pbuf[(p*8 + r)*8 + c2*2 + 0];
                q2 += pbuf[(p*8 + r)*8 + c2*2 + 1];
            }
            const float mean = q1 * (1.f / ST);
            const float var  = q2 * (1.f / ST) - mean * mean;
            const float rstd = rsqrtf(var + EPSC);
            const float sval = (y - mean) * rstd * gj + bj;
            __nv_bfloat16 hh = __float2bfloat16(sval);
            g_sh[urow0 + (size_t)step * ST] = hh;
            g_sl[urow0 + (size_t)step * ST] =
                __float2bfloat16(sval - __bfloat162float(hh));
            const uint32_t la = sb_base + (uint32_t)(((((p^1)*4 + c2)*512) + jg0 + jj) * 4);
#pragma unroll
            for (int r = 0; r < 8; r++) {
                uint32_t ra_;
                asm volatile("mapa.shared::cluster.u32 %0, %1, %2;" : "=r"(ra_) : "r"(la), "r"(r));
                asm volatile("st.shared::cluster.f32 [%0], %1;" :: "r"(ra_), "f"(sval) : "memory");
            }
        }
        uval = unext;

        asm volatile("barrier.cluster.arrive.aligned;\n" ::: "memory");
        asm volatile("barrier.cluster.wait.aligned;\n" ::: "memory");
        p ^= 1;
    }
}

// ---------------- launch ------------------------------------------------------
extern "C" void kernel_launch(void* const* d_in, const int* in_sizes, int n_in,
                              void* d_out, int out_size) {
    const float* x      = (const float*)d_in[0];
    const float* W_in   = (const float*)d_in[1];
    const float* b_in   = (const float*)d_in[2];
    const float* conv_w = (const float*)d_in[3];
    const float* conv_b = (const float*)d_in[4];
    const float* bng    = (const float*)d_in[5];
    const float* bnb    = (const float*)d_in[6];
    const float* lng    = (const float*)d_in[7];
    const float* lnb    = (const float*)d_in[8];
    const float* A      = (const float*)d_in[9];
    const float* Bm     = (const float*)d_in[10];
    const float* C      = (const float*)d_in[11];
    float* out = (float*)d_out;

    void *p_xh, *p_xl, *p_vh, *p_vl, *p_vch, *p_vcl, *p_u, *p_sh, *p_sl;
    void *p_wth, *p_wtl, *p_wkh, *p_wkl, *p_bmh, *p_bml, *p_cth, *p_ctl, *p_ub;
    cudaGetSymbolAddress(&p_xh,  g_xh);  cudaGetSymbolAddress(&p_xl,  g_xl);
    cudaGetSymbolAddress(&p_vh,  g_vh);  cudaGetSymbolAddress(&p_vl,  g_vl);
    cudaGetSymbolAddress(&p_vch, g_vch); cudaGetSymbolAddress(&p_vcl, g_vcl);
    cudaGetSymbolAddress(&p_u,   g_u);
    cudaGetSymbolAddress(&p_sh,  g_sh);  cudaGetSymbolAddress(&p_sl,  g_sl);
    cudaGetSymbolAddress(&p_wth, g_wth); cudaGetSymbolAddress(&p_wtl, g_wtl);
    cudaGetSymbolAddress(&p_wkh, g_wkh); cudaGetSymbolAddress(&p_wkl, g_wkl);
    cudaGetSymbolAddress(&p_bmh, g_bmh); cudaGetSymbolAddress(&p_bml, g_bml);
    cudaGetSymbolAddress(&p_cth, g_cth); cudaGetSymbolAddress(&p_ctl, g_ctl);
    cudaGetSymbolAddress(&p_ub,  g_ubias);

    cudaFuncSetAttribute(k_tgemm, cudaFuncAttributeMaxDynamicSharedMemorySize, SMB_TOTAL);
    cudaFuncSetAttribute(k_recur, cudaFuncAttributeMaxDynamicSharedMemorySize,
                         RC_SMEM_FLOATS * 4);

    // 1) weights + x split
    k_prep<<<1536, 512>>>(W_in, conv_w, C);
    k_split<<<(M_ROWS*IND)/1024, 256>>>(x);
    // 2) v = silu(x @ W_in^T + b_in) -> split
    k_tgemm<<<dim3(4, 1024), 256, SMB_TOTAL>>>(
        (const __nv_bfloat16*)p_xh, (const __nv_bfloat16*)p_xl,
        (const __nv_bfloat16*)p_wth, (const __nv_bfloat16*)p_wtl,
        b_in, nullptr, (__nv_bfloat16*)p_vh, (__nv_bfloat16*)p_vl, IND, ST, 1, 0);
    // 3) vc = conv1d(v) + conv_b -> split
    k_tgemm<<<dim3(4, 1024), 256, SMB_TOTAL>>>(
        (const __nv_bfloat16*)p_vh, (const __nv_bfloat16*)p_vl,
        (const __nv_bfloat16*)p_wkh, (const __nv_bfloat16*)p_wkl,
        conv_b, nullptr, (__nv_bfloat16*)p_vch, (__nv_bfloat16*)p_vcl, 3*ST, ST, 0, 1);
    // 4) BN stats
    k_stats<<<512, 512>>>();
    // 5) fold BN into Bm
    k_finalize<<<1, 512>>>(Bm, bng, bnb);
    // 6) u = vc_norm @ Bm + ubias -> fp32
    k_tgemm<<<dim3(4, 1024), 256, SMB_TOTAL>>>(
        (const __nv_bfloat16*)p_vch, (const __nv_bfloat16*)p_vcl,
        (const __nv_bfloat16*)p_bmh, (const __nv_bfloat16*)p_bml,
        (const float*)p_ub, (float*)p_u, nullptr, nullptr, ST, ST, 0, 0);
    // 7) sequential recurrence
    k_recur<<<dim3(8, 16), 512, RC_SMEM_FLOATS * 4>>>(A, lng, lnb);
    // 8) y = S @ C
    k_tgemm<<<dim3(2, 1024), 256, SMB_TOTAL>>>(
        (const __nv_bfloat16*)p_sh, (const __nv_bfloat16*)p_sl,
        (const __nv_bfloat16*)p_cth, (const __nv_bfloat16*)p_ctl,
        nullptr, out, nullptr, nullptr, ST, OD, 0, 0);
}

// round 8
// speedup vs baseline: 2.2601x; 1.0523x over previous
#include <cuda_runtime.h>
#include <cuda_fp16.h>
#include <math.h>
#include <cstdint>

#define Bz   64
#define Tz   2048
#define IND  256
#define ST   512
#define OD   256
#define M_ROWS (Bz*Tz)   // 131072
#define EPSC 1e-5f

// ---------------- scratch (static device memory) -----------------------------
__device__ __half g_xh[(size_t)M_ROWS*IND], g_xl[(size_t)M_ROWS*IND];
__device__ __half g_vh[(size_t)M_ROWS*ST],  g_vl[(size_t)M_ROWS*ST];
__device__ __half g_vch[(size_t)M_ROWS*ST], g_vcl[(size_t)M_ROWS*ST];
__device__ float  g_u [(size_t)M_ROWS*ST];
__device__ __half g_sh[(size_t)M_ROWS*ST],  g_sl[(size_t)M_ROWS*ST];
__device__ __half g_wt[ST*IND];      // W_in  Bt[n][k] (single fp16)
__device__ __half g_wk[ST*3*ST];     // conv  Bt[n][tap*512+i]
__device__ __half g_bm[ST*ST];       // BN-folded Bm, Bt[j][i]
__device__ __half g_ct[OD*ST];       // C     Bt[n][k]
__device__ float g_ubias[ST];
__device__ float g_sum[ST];
__device__ float g_sumsq[ST];

__device__ __forceinline__ uint32_t smem_u32(const void* p) {
    return (uint32_t)__cvta_generic_to_shared(p);
}

// ---------------- prep: weights -> fp16, x handled by k_split -----------------
__global__ void k_prep(const float* __restrict__ W_in, const float* __restrict__ conv_w,
                       const float* __restrict__ C) {
    int idx = blockIdx.x * blockDim.x + threadIdx.x;
    if (idx < ST*IND) {                 // W_in[n][k] -> Bt[n][k]
        g_wt[idx] = __float2half_rn(W_in[idx]);
    }
    if (idx < ST*3*ST) {                // conv: Bt[n][tap*512+i] = conv_w[n][i][tap]
        int n = idx / (3*ST);
        int rem = idx % (3*ST);
        int tap = rem / ST, i = rem % ST;
        g_wk[idx] = __float2half_rn(conv_w[((size_t)n*ST + i)*3 + tap]);
    }
    if (idx < OD*ST) {                  // C[k][n] -> Ct[n][k]
        int n = idx / ST, k = idx % ST;
        g_ct[idx] = __float2half_rn(C[(size_t)k*OD + n]);
    }
    if (idx < ST) { g_sum[idx] = 0.f; g_sumsq[idx] = 0.f; }
}

// split x -> fp16 hi/lo
__global__ __launch_bounds__(256)
void k_split(const float* __restrict__ x) {
    const size_t i = ((size_t)blockIdx.x * 256 + threadIdx.x) * 4;
    float4 v = *(const float4*)(x + i);
    __half2 h0 = __floats2half2_rn(v.x, v.y);
    __half2 h1 = __floats2half2_rn(v.z, v.w);
    __half2 l0 = __floats2half2_rn(v.x - __low2float(h0), v.y - __high2float(h0));
    __half2 l1 = __floats2half2_rn(v.z - __low2float(h1), v.w - __high2float(h1));
    uint2 hh; hh.x = *(uint32_t*)&h0; hh.y = *(uint32_t*)&h1;
    uint2 ll; ll.x = *(uint32_t*)&l0; ll.y = *(uint32_t*)&l1;
    *(uint2*)(g_xh + i) = hh;
    *(uint2*)(g_xl + i) = ll;
}

// ---------------- mma.sync helpers --------------------------------------------
__device__ __forceinline__ void mma16816(float* c, const uint32_t* a, const uint32_t* b) {
    asm volatile(
        "mma.sync.aligned.m16n8k16.row.col.f32.f16.f16.f32 "
        "{%0,%1,%2,%3}, {%4,%5,%6,%7}, {%8,%9}, {%0,%1,%2,%3};"
        : "+f"(c[0]), "+f"(c[1]), "+f"(c[2]), "+f"(c[3])
        : "r"(a[0]), "r"(a[1]), "r"(a[2]), "r"(a[3]), "r"(b[0]), "r"(b[1]));
}
__device__ __forceinline__ void ldsm4(uint32_t* r, uint32_t addr) {
    asm volatile("ldmatrix.sync.aligned.m8n8.x4.shared.b16 {%0,%1,%2,%3}, [%4];"
                 : "=r"(r[0]), "=r"(r[1]), "=r"(r[2]), "=r"(r[3]) : "r"(addr));
}
__device__ __forceinline__ void ldsm2(uint32_t* r, uint32_t addr) {
    asm volatile("ldmatrix.sync.aligned.m8n8.x2.shared.b16 {%0,%1}, [%2];"
                 : "=r"(r[0]), "=r"(r[1]) : "r"(addr));
}
__device__ __forceinline__ void cpa16(uint32_t dst, const void* src, bool pred) {
    int sz = pred ? 16 : 0;
    asm volatile("cp.async.cg.shared.global [%0], [%1], 16, %2;"
                 :: "r"(dst), "l"(src), "r"(sz) : "memory");
}
#define CPA_COMMIT() asm volatile("cp.async.commit_group;" ::: "memory")

// ---------------- asymmetric fp16 warp-MMA GEMM --------------------------------
// out = act( A@B + bias ); A = Ah + Al (2-digit fp16), B single fp16.
// 128x128 CTA tile, K-chunks of 64, 2-stage cp.async; B given as Bt[n][k].
#define SRS 72
#define TILE_HALFS (128*SRS)             // 9216 halfs = 18432 B
#define CHUNK_HALFS (3*TILE_HALFS)       // Ah, Al, B
#define SMB_TOTAL (2*CHUNK_HALFS*2)      // 110592 B

__global__ __launch_bounds__(256, 1)
void k_tgemm(const __half* __restrict__ Ah, const __half* __restrict__ Al,
             const __half* __restrict__ Bp,
             const float* __restrict__ bias, float* __restrict__ outf,
             __half* __restrict__ outh, __half* __restrict__ outl,
             int Kd, int N, int act, int convmode) {
    extern __shared__ __half smem[];
    const int t = threadIdx.x;
    const int w = t >> 5, lane = t & 31;
    const int wm = w >> 2, wn = w & 3;
    const int m0 = blockIdx.y * 128, n0 = blockIdx.x * 128;

    float acc[4][4][4];
#pragma unroll
    for (int i = 0; i < 4; i++)
#pragma unroll
        for (int j = 0; j < 4; j++)
#pragma unroll
            for (int q = 0; q < 4; q++) acc[i][j][q] = 0.f;

    const uint32_t smb = smem_u32(smem);
    const uint32_t aBase = smb +
        (uint32_t)(((wm*64 + (lane & 15)) * SRS + (lane >> 4) * 8) * 2);
    const uint32_t alOff = TILE_HALFS * 2;
    const uint32_t bBase = smb + 2*TILE_HALFS*2 +
        (uint32_t)(((wn*32 + (lane & 7)) * SRS + ((lane >> 3) & 1) * 8) * 2);

    const int sr = t >> 3, sj = t & 7;
    const int nch = Kd >> 6;

    auto stage = [&](int c, int buf) {
        const int k0 = c << 6;
        __half* base = smem + buf * CHUNK_HALFS;
        __half* sAh = base;
        __half* sAl = base + TILE_HALFS;
        __half* sB  = base + 2*TILE_HALFS;
        const int tap = convmode ? (k0 >> 9) : 0;
        const int kl0 = convmode ? (k0 & 511) : k0;
#pragma unroll
        for (int it = 0; it < 4; it++) {
            const int r = sr + it * 32;
            const uint32_t so = (uint32_t)((r * SRS + sj * 8) * 2);
            {
                const size_t goff = (size_t)(n0 + r) * Kd + k0 + sj * 8;
                cpa16(smem_u32(sB) + so, Bp + goff, true);
            }
            {
                const int rg = m0 + r;
                bool pred = true;
                size_t goff;
                if (convmode) {
                    const int tl = (rg & (Tz - 1)) + tap - 1;
                    pred = (tl >= 0) && (tl < Tz);
                    const int rs = pred ? (rg + tap - 1) : rg;
                    goff = (size_t)rs * ST + kl0 + sj * 8;
                } else {
                    goff = (size_t)rg * Kd + k0 + sj * 8;
                }
                cpa16(smem_u32(sAh) + so, Ah + goff, pred);
                cpa16(smem_u32(sAl) + so, Al + goff, pred);
            }
        }
    };

    // register fragments, double-buffered across k-steps
    uint32_t fah[2][4][4], fal[2][4][4], fb[2][4][2];

    auto ldfrag = [&](int slot, uint32_t koff) {
#pragma unroll
        for (int mi = 0; mi < 4; mi++)
            ldsm4(fah[slot][mi], aBase + (uint32_t)(mi * 16 * SRS * 2) + koff);
#pragma unroll
        for (int mi = 0; mi < 4; mi++)
            ldsm4(fal[slot][mi], aBase + alOff + (uint32_t)(mi * 16 * SRS * 2) + koff);
#pragma unroll
        for (int ni = 0; ni < 4; ni++)
            ldsm2(fb[slot][ni], bBase + (uint32_t)(ni * 8 * SRS * 2) + koff);
    };

    stage(0, 0);
    CPA_COMMIT();

    for (int c = 0; c < nch; c++) {
        const bool more = (c + 1) < nch;
        if (more) { stage(c + 1, (c + 1) & 1); CPA_COMMIT(); }
        if (more) asm volatile("cp.async.wait_group 1;" ::: "memory");
        else      asm volatile("cp.async.wait_group 0;" ::: "memory");
        __syncthreads();

        const uint32_t boff = (uint32_t)((c & 1) * CHUNK_HALFS * 2);
        ldfrag(0, boff);
#pragma unroll
        for (int ks = 0; ks < 4; ks++) {
            const int cur = ks & 1;
            if (ks < 3) ldfrag(cur ^ 1, boff + (uint32_t)((ks + 1) * 32));
            // term Ah*B
#pragma unroll
            for (int mi = 0; mi < 4; mi++)
#pragma unroll
                for (int ni = 0; ni < 4; ni++)
                    mma16816(acc[mi][ni], fah[cur][mi], fb[cur][ni]);
            // term Al*B
#pragma unroll
            for (int mi = 0; mi < 4; mi++)
#pragma unroll
                for (int ni = 0; ni < 4; ni++)
                    mma16816(acc[mi][ni], fal[cur][mi], fb[cur][ni]);
        }
        __syncthreads();
    }

    // ---- epilogue -------------------------------------------------------------
    const int g = lane >> 2, tg = lane & 3;
#pragma unroll
    for (int mi = 0; mi < 4; mi++) {
#pragma unroll
        for (int ni = 0; ni < 4; ni++) {
            const int col = n0 + wn*32 + ni*8 + tg*2;
            const float b0 = bias ? bias[col]     : 0.f;
            const float b1 = bias ? bias[col + 1] : 0.f;
#pragma unroll
            for (int half = 0; half < 2; half++) {
                const int row = m0 + wm*64 + mi*16 + g + half*8;
                float v0 = acc[mi][ni][half*2+0] + b0;
                float v1 = acc[mi][ni][half*2+1] + b1;
                if (act == 1) {
                    v0 = v0 / (1.f + expf(-v0));
                    v1 = v1 / (1.f + expf(-v1));
                }
                if (outf) {
                    float2 f2; f2.x = v0; f2.y = v1;
                    *(float2*)(outf + (size_t)row * N + col) = f2;
                }
                if (outh) {
                    __half2 h2 = __floats2half2_rn(v0, v1);
                    __half2 l2 = __floats2half2_rn(v0 - __low2float(h2),
                                                   v1 - __high2float(h2));
                    *(__half2*)(outh + (size_t)row * N + col) = h2;
                    *(__half2*)(outl + (size_t)row * N + col) = l2;
                }
            }
        }
    }
}

// ---------------- BN stats (from split vc) ------------------------------------
__global__ __launch_bounds__(512)
void k_stats() {
    const int n = threadIdx.x;
    const int rpc = M_ROWS / 512;
    const int r0 = blockIdx.x * rpc;
    float s1 = 0.f, s2 = 0.f;
    for (int r = 0; r < rpc; r++) {
        const size_t o = (size_t)(r0 + r) * ST + n;
        float v = __half2float(g_vch[o]) + __half2float(g_vcl[o]);
        s1 += v; s2 += v * v;
    }
    atomicAdd(&g_sum[n], s1);
    atomicAdd(&g_sumsq[n], s2);
}

// fold BN into Bm (single fp16 weights, fp32 bias)
__global__ __launch_bounds__(512)
void k_finalize(const float* __restrict__ Bm, const float* __restrict__ bng,
                const float* __restrict__ bnb) {
    __shared__ float sc[ST], sh[ST];
    const int j = threadIdx.x;
    float mu  = g_sum[j]   * (1.f / M_ROWS);
    float var = g_sumsq[j] * (1.f / M_ROWS) - mu * mu;
    float inv = rsqrtf(var + EPSC);
    float s   = bng[j] * inv;
    sc[j] = s;
    sh[j] = bnb[j] - mu * s;
    __syncthreads();
    float ub = 0.f;
    for (int i = 0; i < ST; i++) {
        float bmv = Bm[(size_t)i * ST + j];
        g_bm[(size_t)j * ST + i] = __float2half_rn(sc[i] * bmv);
        ub += sh[i] * bmv;
    }
    g_ubias[j] = ub;
}

// ---------------- cluster recurrence (fp16 split state out) -------------------
#define RC_SMEM_FLOATS 39064
__global__ __launch_bounds__(512, 1) __cluster_dims__(8, 1, 1)
void k_recur(const float* __restrict__ A, const float* __restrict__ lng,
             const float* __restrict__ lnb) {
    extern __shared__ float sm[];
    float* Atile = sm;            // [512][64]
    float* sbuf  = sm + 32768;    // [2][4][512]
    float* pbuf  = sm + 36864;    // [2][8][8]
    float* pred  = sm + 36992;    // [512][4]
    float* ws    = sm + 39040;    // [16]
    float* pl    = sm + 39056;    // [8]

    const int t    = threadIdx.x;
    const int rank = blockIdx.x;
    const int grp  = blockIdx.y;
    const int jg0  = rank * 64;

    for (int idx = t; idx < 512 * 16; idx += 512) {
        int i  = idx >> 4;
        int jv = (idx & 15) << 2;
        *(float4*)&Atile[i*64 + jv] = *(const float4*)(A + (size_t)i*ST + jg0 + jv);
    }
    for (int idx = t; idx < 4*512; idx += 512) sbuf[idx] = 0.f;

    const int ip = t >> 6;
    const int cc = (t >> 4) & 3;
    const int jq = t & 15;
    const int c2 = t >> 6;
    const int jj = t & 63;

    float gj = 0.f, bj = 0.f;
    size_t urow0 = 0;
    if (t < 256) {
        gj = lng[jg0 + jj];
        bj = lnb[jg0 + jj];
        const int chain = grp * 4 + c2;
        urow0 = (size_t)chain * Tz * ST + jg0 + jj;
    }

    const uint32_t sb_base = smem_u32(sbuf);
    const uint32_t pb_base = smem_u32(pbuf);

    asm volatile("barrier.cluster.arrive.aligned;\n" ::: "memory");
    asm volatile("barrier.cluster.wait.aligned;\n" ::: "memory");

    int p = 0;
    float uval = (t < 256) ? g_u[urow0] : 0.f;

    for (int step = 0; step < Tz; step++) {
        const float* sbp = sbuf + (p*4 + cc)*512;
        const float* Ap2 = Atile + jq*4;
        float4 acc = make_float4(0.f, 0.f, 0.f, 0.f);
#pragma unroll 4
        for (int i = ip*64; i < ip*64 + 64; i += 4) {
            float4 s4 = *(const float4*)(sbp + i);
            float4 a;
            a = *(const float4*)(Ap2 + (i+0)*64);
            acc.x = fmaf(s4.x, a.x, acc.x); acc.y = fmaf(s4.x, a.y, acc.y);
            acc.z = fmaf(s4.x, a.z, acc.z); acc.w = fmaf(s4.x, a.w, acc.w);
            a = *(const float4*)(Ap2 + (i+1)*64);
            acc.x = fmaf(s4.y, a.x, acc.x); acc.y = fmaf(s4.y, a.y, acc.y);
            acc.z = fmaf(s4.y, a.z, acc.z); acc.w = fmaf(s4.y, a.w, acc.w);
            a = *(const float4*)(Ap2 + (i+2)*64);
            acc.x = fmaf(s4.z, a.x, acc.x); acc.y = fmaf(s4.z, a.y, acc.y);
            acc.z = fmaf(s4.z, a.z, acc.z); acc.w = fmaf(s4.z, a.w, acc.w);
            a = *(const float4*)(Ap2 + (i+3)*64);
            acc.x = fmaf(s4.w, a.x, acc.x); acc.y = fmaf(s4.w, a.y, acc.y);
            acc.z = fmaf(s4.w, a.z, acc.z); acc.w = fmaf(s4.w, a.w, acc.w);
        }
        *(float4*)&pred[t*4] = acc;
        __syncthreads();

        float y = 0.f;
        if (t < 256) {
            y = uval;
#pragma unroll
            for (int q = 0; q < 8; q++)
                y += pred[(q*64 + c2*16 + (jj >> 2))*4 + (jj & 3)];
            float s1 = y, s2 = y*y;
#pragma unroll
            for (int o = 16; o > 0; o >>= 1) {
                s1 += __shfl_xor_sync(0xffffffffu, s1, o);
                s2 += __shfl_xor_sync(0xffffffffu, s2, o);
            }
            if ((t & 31) == 0) { ws[(t>>5)*2] = s1; ws[(t>>5)*2+1] = s2; }
        }
        __syncthreads();
        if (t < 4) {
            pl[t*2+0] = ws[t*4+0] + ws[t*4+2];
            pl[t*2+1] = ws[t*4+1] + ws[t*4+3];
        }
        __syncthreads();
        if (t < 64) {
            const int r = t >> 3, k = t & 7;
            const uint32_t la = pb_base + (uint32_t)(((p*8 + rank)*8 + k) * 4);
            uint32_t ra_;
            asm volatile("mapa.shared::cluster.u32 %0, %1, %2;" : "=r"(ra_) : "r"(la), "r"(r));
            asm volatile("st.shared::cluster.f32 [%0], %1;" :: "r"(ra_), "f"(pl[k]) : "memory");
        }
        float unext = 0.f;
        if (t < 256 && step + 1 < Tz)
            unext = g_u[urow0 + (size_t)(step + 1) * ST];

        asm volatile("barrier.cluster.arrive.aligned;\n" ::: "memory");
        asm volatile("barrier.cluster.wait.aligned;\n" ::: "memory");

        if (t < 256) {
            float q1 = 0.f, q2 = 0.f;
#pragma unroll
            for (int r = 0; r < 8; r++) {
                q1 += pbuf[(p*8 + r)*8 + c2*2 + 0];
                q2 += pbuf[(p*8 + r)*8 + c2*2 + 1];
            }
            const float mean = q1 * (1.f / ST);
            const float var  = q2 * (1.f / ST) - mean * mean;
            const float rstd = rsqrtf(var + EPSC);
            const float sval = (y - mean) * rstd * gj + bj;
            __half hh = __float2half_rn(sval);
            g_sh[urow0 + (size_t)step * ST] = hh;
            g_sl[urow0 + (size_t)step * ST] =
                __float2half_rn(sval - __half2float(hh));
            const uint32_t la = sb_base + (uint32_t)(((((p^1)*4 + c2)*512) + jg0 + jj) * 4);
#pragma unroll
            for (int r = 0; r < 8; r++) {
                uint32_t ra_;
                asm volatile("mapa.shared::cluster.u32 %0, %1, %2;" : "=r"(ra_) : "r"(la), "r"(r));
                asm volatile("st.shared::cluster.f32 [%0], %1;" :: "r"(ra_), "f"(sval) : "memory");
            }
        }
        uval = unext;

        asm volatile("barrier.cluster.arrive.aligned;\n" ::: "memory");
        asm volatile("barrier.cluster.wait.aligned;\n" ::: "memory");
        p ^= 1;
    }
}

// ---------------- launch ------------------------------------------------------
extern "C" void kernel_launch(void* const* d_in, const int* in_sizes, int n_in,
                              void* d_out, int out_size) {
    const float* x      = (const float*)d_in[0];
    const float* W_in   = (const float*)d_in[1];
    const float* b_in   = (const float*)d_in[2];
    const float* conv_w = (const float*)d_in[3];
    const float* conv_b = (const float*)d_in[4];
    const float* bng    = (const float*)d_in[5];
    const float* bnb    = (const float*)d_in[6];
    const float* lng    = (const float*)d_in[7];
    const float* lnb    = (const float*)d_in[8];
    const float* A      = (const float*)d_in[9];
    const float* Bm     = (const float*)d_in[10];
    const float* C      = (const float*)d_in[11];
    float* out = (float*)d_out;

    void *p_xh, *p_xl, *p_vh, *p_vl, *p_vch, *p_vcl, *p_u, *p_sh, *p_sl;
    void *p_wt, *p_wk, *p_bm, *p_ct, *p_ub;
    cudaGetSymbolAddress(&p_xh,  g_xh);  cudaGetSymbolAddress(&p_xl,  g_xl);
    cudaGetSymbolAddress(&p_vh,  g_vh);  cudaGetSymbolAddress(&p_vl,  g_vl);
    cudaGetSymbolAddress(&p_vch, g_vch); cudaGetSymbolAddress(&p_vcl, g_vcl);
    cudaGetSymbolAddress(&p_u,   g_u);
    cudaGetSymbolAddress(&p_sh,  g_sh);  cudaGetSymbolAddress(&p_sl,  g_sl);
    cudaGetSymbolAddress(&p_wt,  g_wt);  cudaGetSymbolAddress(&p_wk,  g_wk);
    cudaGetSymbolAddress(&p_bm,  g_bm);  cudaGetSymbolAddress(&p_ct,  g_ct);
    cudaGetSymbolAddress(&p_ub,  g_ubias);

    cudaFuncSetAttribute(k_tgemm, cudaFuncAttributeMaxDynamicSharedMemorySize, SMB_TOTAL);
    cudaFuncSetAttribute(k_recur, cudaFuncAttributeMaxDynamicSharedMemorySize,
                         RC_SMEM_FLOATS * 4);

    // 1) weights + x split
    k_prep<<<1536, 512>>>(W_in, conv_w, C);
    k_split<<<(M_ROWS*IND)/1024, 256>>>(x);
    // 2) v = silu(x @ W_in^T + b_in) -> split fp16
    k_tgemm<<<dim3(4, 1024), 256, SMB_TOTAL>>>(
        (const __half*)p_xh, (const __half*)p_xl, (const __half*)p_wt,
        b_in, nullptr, (__half*)p_vh, (__half*)p_vl, IND, ST, 1, 0);
    // 3) vc = conv1d(v) + conv_b -> split fp16
    k_tgemm<<<dim3(4, 1024), 256, SMB_TOTAL>>>(
        (const __half*)p_vh, (const __half*)p_vl, (const __half*)p_wk,
        conv_b, nullptr, (__half*)p_vch, (__half*)p_vcl, 3*ST, ST, 0, 1);
    // 4) BN stats
    k_stats<<<512, 512>>>();
    // 5) fold BN into Bm
    k_finalize<<<1, 512>>>(Bm, bng, bnb);
    // 6) u = vc @ Bm2 + ubias -> fp32
    k_tgemm<<<dim3(4, 1024), 256, SMB_TOTAL>>>(
        (const __half*)p_vch, (const __half*)p_vcl, (const __half*)p_bm,
        (const float*)p_ub, (float*)p_u, nullptr, nullptr, ST, ST, 0, 0);
    // 7) sequential recurrence -> split fp16 states
    k_recur<<<dim3(8, 16), 512, RC_SMEM_FLOATS * 4>>>(A, lng, lnb);
    // 8) y = S @ C
    k_tgemm<<<dim3(2, 1024), 256, SMB_TOTAL>>>(
        (const __half*)p_sh, (const __half*)p_sl, (const __half*)p_ct,
        nullptr, out, nullptr, nullptr, ST, OD, 0, 0);
}

// round 9
// speedup vs baseline: 2.3079x; 1.0211x over previous
#include <cuda_runtime.h>
#include <cuda_fp16.h>
#include <math.h>
#include <cstdint>

#define Bz   64
#define Tz   2048
#define IND  256
#define ST   512
#define OD   256
#define M_ROWS (Bz*Tz)   // 131072
#define EPSC 1e-5f

// ---------------- scratch (static device memory) -----------------------------
__device__ __half g_xh[(size_t)M_ROWS*IND], g_xl[(size_t)M_ROWS*IND];
__device__ __half g_vh[(size_t)M_ROWS*ST],  g_vl[(size_t)M_ROWS*ST];
__device__ __half g_vch[(size_t)M_ROWS*ST], g_vcl[(size_t)M_ROWS*ST];
__device__ float  g_u [(size_t)M_ROWS*ST];
__device__ __half g_sh[(size_t)M_ROWS*ST],  g_sl[(size_t)M_ROWS*ST];
__device__ __half g_wt[ST*IND];      // W_in  Bt[n][k] (single fp16)
__device__ __half g_wk[ST*3*ST];     // conv  Bt[n][tap*512+i]
__device__ __half g_bm[ST*ST];       // BN-folded Bm, Bt[j][i]
__device__ __half g_ct[OD*ST];       // C     Bt[n][k]
__device__ float g_ubias[ST];
__device__ float g_sum[ST];
__device__ float g_sumsq[ST];

__device__ __forceinline__ uint32_t smem_u32(const void* p) {
    return (uint32_t)__cvta_generic_to_shared(p);
}

// ---------------- prep: weights -> fp16 ---------------------------------------
__global__ void k_prep(const float* __restrict__ W_in, const float* __restrict__ conv_w,
                       const float* __restrict__ C) {
    int idx = blockIdx.x * blockDim.x + threadIdx.x;
    if (idx < ST*IND) {                 // W_in[n][k] -> Bt[n][k]
        g_wt[idx] = __float2half_rn(W_in[idx]);
    }
    if (idx < ST*3*ST) {                // conv: Bt[n][tap*512+i] = conv_w[n][i][tap]
        int n = idx / (3*ST);
        int rem = idx % (3*ST);
        int tap = rem / ST, i = rem % ST;
        g_wk[idx] = __float2half_rn(conv_w[((size_t)n*ST + i)*3 + tap]);
    }
    if (idx < OD*ST) {                  // C[k][n] -> Ct[n][k]
        int n = idx / ST, k = idx % ST;
        g_ct[idx] = __float2half_rn(C[(size_t)k*OD + n]);
    }
    if (idx < ST) { g_sum[idx] = 0.f; g_sumsq[idx] = 0.f; }
}

// split x -> fp16 hi/lo
__global__ __launch_bounds__(256)
void k_split(const float* __restrict__ x) {
    const size_t i = ((size_t)blockIdx.x * 256 + threadIdx.x) * 4;
    float4 v = *(const float4*)(x + i);
    __half2 h0 = __floats2half2_rn(v.x, v.y);
    __half2 h1 = __floats2half2_rn(v.z, v.w);
    __half2 l0 = __floats2half2_rn(v.x - __low2float(h0), v.y - __high2float(h0));
    __half2 l1 = __floats2half2_rn(v.z - __low2float(h1), v.w - __high2float(h1));
    uint2 hh; hh.x = *(uint32_t*)&h0; hh.y = *(uint32_t*)&h1;
    uint2 ll; ll.x = *(uint32_t*)&l0; ll.y = *(uint32_t*)&l1;
    *(uint2*)(g_xh + i) = hh;
    *(uint2*)(g_xl + i) = ll;
}

// ---------------- mma.sync helpers --------------------------------------------
__device__ __forceinline__ void mma16816(float* c, const uint32_t* a, const uint32_t* b) {
    asm volatile(
        "mma.sync.aligned.m16n8k16.row.col.f32.f16.f16.f32 "
        "{%0,%1,%2,%3}, {%4,%5,%6,%7}, {%8,%9}, {%0,%1,%2,%3};"
        : "+f"(c[0]), "+f"(c[1]), "+f"(c[2]), "+f"(c[3])
        : "r"(a[0]), "r"(a[1]), "r"(a[2]), "r"(a[3]), "r"(b[0]), "r"(b[1]));
}
__device__ __forceinline__ void ldsm4(uint32_t* r, uint32_t addr) {
    asm volatile("ldmatrix.sync.aligned.m8n8.x4.shared.b16 {%0,%1,%2,%3}, [%4];"
                 : "=r"(r[0]), "=r"(r[1]), "=r"(r[2]), "=r"(r[3]) : "r"(addr));
}
__device__ __forceinline__ void ldsm2(uint32_t* r, uint32_t addr) {
    asm volatile("ldmatrix.sync.aligned.m8n8.x2.shared.b16 {%0,%1}, [%2];"
                 : "=r"(r[0]), "=r"(r[1]) : "r"(addr));
}
__device__ __forceinline__ void cpa16(uint32_t dst, const void* src, bool pred) {
    int sz = pred ? 16 : 0;
    asm volatile("cp.async.cg.shared.global [%0], [%1], 16, %2;"
                 :: "r"(dst), "l"(src), "r"(sz) : "memory");
}
#define CPA_COMMIT() asm volatile("cp.async.commit_group;" ::: "memory")

// ---------------- asymmetric fp16 warp-MMA GEMM --------------------------------
// out = act( A@B + bias ); A = Ah + Al (2-digit fp16), B single fp16.
// 128x128 CTA tile, K-chunks of 64, 2-stage cp.async; 2 CTAs/SM.
#define SRS 72
#define TILE_HALFS (128*SRS)             // 9216 halfs = 18432 B
#define CHUNK_HALFS (3*TILE_HALFS)       // Ah, Al, B
#define SMB_TOTAL (2*CHUNK_HALFS*2)      // 110592 B

__global__ __launch_bounds__(256, 2)
void k_tgemm(const __half* __restrict__ Ah, const __half* __restrict__ Al,
             const __half* __restrict__ Bp,
             const float* __restrict__ bias, float* __restrict__ outf,
             __half* __restrict__ outh, __half* __restrict__ outl,
             int Kd, int N, int act, int convmode) {
    extern __shared__ __half smem[];
    const int t = threadIdx.x;
    const int w = t >> 5, lane = t & 31;
    const int wm = w >> 2, wn = w & 3;
    const int m0 = blockIdx.y * 128, n0 = blockIdx.x * 128;

    float acc[4][4][4];
#pragma unroll
    for (int i = 0; i < 4; i++)
#pragma unroll
        for (int j = 0; j < 4; j++)
#pragma unroll
            for (int q = 0; q < 4; q++) acc[i][j][q] = 0.f;

    const uint32_t smb = smem_u32(smem);
    const uint32_t aBase = smb +
        (uint32_t)(((wm*64 + (lane & 15)) * SRS + (lane >> 4) * 8) * 2);
    const uint32_t alOff = TILE_HALFS * 2;
    const uint32_t bBase = smb + 2*TILE_HALFS*2 +
        (uint32_t)(((wn*32 + (lane & 7)) * SRS + ((lane >> 3) & 1) * 8) * 2);

    const int sr = t >> 3, sj = t & 7;
    const int nch = Kd >> 6;

    auto stage = [&](int c, int buf) {
        const int k0 = c << 6;
        __half* base = smem + buf * CHUNK_HALFS;
        __half* sAh = base;
        __half* sAl = base + TILE_HALFS;
        __half* sB  = base + 2*TILE_HALFS;
        const int tap = convmode ? (k0 >> 9) : 0;
        const int kl0 = convmode ? (k0 & 511) : k0;
#pragma unroll
        for (int it = 0; it < 4; it++) {
            const int r = sr + it * 32;
            const uint32_t so = (uint32_t)((r * SRS + sj * 8) * 2);
            {
                const size_t goff = (size_t)(n0 + r) * Kd + k0 + sj * 8;
                cpa16(smem_u32(sB) + so, Bp + goff, true);
            }
            {
                const int rg = m0 + r;
                bool pred = true;
                size_t goff;
                if (convmode) {
                    const int tl = (rg & (Tz - 1)) + tap - 1;
                    pred = (tl >= 0) && (tl < Tz);
                    const int rs = pred ? (rg + tap - 1) : rg;
                    goff = (size_t)rs * ST + kl0 + sj * 8;
                } else {
                    goff = (size_t)rg * Kd + k0 + sj * 8;
                }
                cpa16(smem_u32(sAh) + so, Ah + goff, pred);
                cpa16(smem_u32(sAl) + so, Al + goff, pred);
            }
        }
    };

    // single-buffered register fragments (R7: double-buffer was neutral)
    uint32_t fah[4][4], fal[4][4], fb[4][2];

    stage(0, 0);
    CPA_COMMIT();

    for (int c = 0; c < nch; c++) {
        const bool more = (c + 1) < nch;
        if (more) { stage(c + 1, (c + 1) & 1); CPA_COMMIT(); }
        if (more) asm volatile("cp.async.wait_group 1;" ::: "memory");
        else      asm volatile("cp.async.wait_group 0;" ::: "memory");
        __syncthreads();

        const uint32_t boff = (uint32_t)((c & 1) * CHUNK_HALFS * 2);
#pragma unroll
        for (int ks = 0; ks < 4; ks++) {
            const uint32_t koff = boff + (uint32_t)(ks * 32);
#pragma unroll
            for (int mi = 0; mi < 4; mi++)
                ldsm4(fah[mi], aBase + (uint32_t)(mi * 16 * SRS * 2) + koff);
#pragma unroll
            for (int mi = 0; mi < 4; mi++)
                ldsm4(fal[mi], aBase + alOff + (uint32_t)(mi * 16 * SRS * 2) + koff);
#pragma unroll
            for (int ni = 0; ni < 4; ni++)
                ldsm2(fb[ni], bBase + (uint32_t)(ni * 8 * SRS * 2) + koff);
            // term Ah*B
#pragma unroll
            for (int mi = 0; mi < 4; mi++)
#pragma unroll
                for (int ni = 0; ni < 4; ni++)
                    mma16816(acc[mi][ni], fah[mi], fb[ni]);
            // term Al*B
#pragma unroll
            for (int mi = 0; mi < 4; mi++)
#pragma unroll
                for (int ni = 0; ni < 4; ni++)
                    mma16816(acc[mi][ni], fal[mi], fb[ni]);
        }
        __syncthreads();
    }

    // ---- epilogue -------------------------------------------------------------
    const int g = lane >> 2, tg = lane & 3;
#pragma unroll
    for (int mi = 0; mi < 4; mi++) {
#pragma unroll
        for (int ni = 0; ni < 4; ni++) {
            const int col = n0 + wn*32 + ni*8 + tg*2;
            const float b0 = bias ? bias[col]     : 0.f;
            const float b1 = bias ? bias[col + 1] : 0.f;
#pragma unroll
            for (int half = 0; half < 2; half++) {
                const int row = m0 + wm*64 + mi*16 + g + half*8;
                float v0 = acc[mi][ni][half*2+0] + b0;
                float v1 = acc[mi][ni][half*2+1] + b1;
                if (act == 1) {
                    v0 = v0 / (1.f + expf(-v0));
                    v1 = v1 / (1.f + expf(-v1));
                }
                if (outf) {
                    float2 f2; f2.x = v0; f2.y = v1;
                    *(float2*)(outf + (size_t)row * N + col) = f2;
                }
                if (outh) {
                    __half2 h2 = __floats2half2_rn(v0, v1);
                    __half2 l2 = __floats2half2_rn(v0 - __low2float(h2),
                                                   v1 - __high2float(h2));
                    *(__half2*)(outh + (size_t)row * N + col) = h2;
                    *(__half2*)(outl + (size_t)row * N + col) = l2;
                }
            }
        }
    }
}

// ---------------- BN stats (from split vc) ------------------------------------
__global__ __launch_bounds__(512)
void k_stats() {
    const int n = threadIdx.x;
    const int rpc = M_ROWS / 512;
    const int r0 = blockIdx.x * rpc;
    float s1 = 0.f, s2 = 0.f;
    for (int r = 0; r < rpc; r++) {
        const size_t o = (size_t)(r0 + r) * ST + n;
        float v = __half2float(g_vch[o]) + __half2float(g_vcl[o]);
        s1 += v; s2 += v * v;
    }
    atomicAdd(&g_sum[n], s1);
    atomicAdd(&g_sumsq[n], s2);
}

// fold BN into Bm (single fp16 weights, fp32 bias)
__global__ __launch_bounds__(512)
void k_finalize(const float* __restrict__ Bm, const float* __restrict__ bng,
                const float* __restrict__ bnb) {
    __shared__ float sc[ST], sh[ST];
    const int j = threadIdx.x;
    float mu  = g_sum[j]   * (1.f / M_ROWS);
    float var = g_sumsq[j] * (1.f / M_ROWS) - mu * mu;
    float inv = rsqrtf(var + EPSC);
    float s   = bng[j] * inv;
    sc[j] = s;
    sh[j] = bnb[j] - mu * s;
    __syncthreads();
    float ub = 0.f;
    for (int i = 0; i < ST; i++) {
        float bmv = Bm[(size_t)i * ST + j];
        g_bm[(size_t)j * ST + i] = __float2half_rn(sc[i] * bmv);
        ub += sh[i] * bmv;
    }
    g_ubias[j] = ub;
}

// ---------------- cluster recurrence (fp16 split state out) -------------------
#define RC_SMEM_FLOATS 39064
__global__ __launch_bounds__(512, 1) __cluster_dims__(8, 1, 1)
void k_recur(const float* __restrict__ A, const float* __restrict__ lng,
             const float* __restrict__ lnb) {
    extern __shared__ float sm[];
    float* Atile = sm;            // [512][64]
    float* sbuf  = sm + 32768;    // [2][4][512]
    float* pbuf  = sm + 36864;    // [2][8][8]
    float* pred  = sm + 36992;    // [512][4]
    float* ws    = sm + 39040;    // [16]
    float* pl    = sm + 39056;    // [8]

    const int t    = threadIdx.x;
    const int rank = blockIdx.x;
    const int grp  = blockIdx.y;
    const int jg0  = rank * 64;

    for (int idx = t; idx < 512 * 16; idx += 512) {
        int i  = idx >> 4;
        int jv = (idx & 15) << 2;
        *(float4*)&Atile[i*64 + jv] = *(const float4*)(A + (size_t)i*ST + jg0 + jv);
    }
    for (int idx = t; idx < 4*512; idx += 512) sbuf[idx] = 0.f;

    const int ip = t >> 6;
    const int cc = (t >> 4) & 3;
    const int jq = t & 15;
    const int c2 = t >> 6;
    const int jj = t & 63;

    float gj = 0.f, bj = 0.f;
    size_t urow0 = 0;
    if (t < 256) {
        gj = lng[jg0 + jj];
        bj = lnb[jg0 + jj];
        const int chain = grp * 4 + c2;
        urow0 = (size_t)chain * Tz * ST + jg0 + jj;
    }

    const uint32_t sb_base = smem_u32(sbuf);
    const uint32_t pb_base = smem_u32(pbuf);

    asm volatile("barrier.cluster.arrive.aligned;\n" ::: "memory");
    asm volatile("barrier.cluster.wait.aligned;\n" ::: "memory");

    int p = 0;
    float uval = (t < 256) ? g_u[urow0] : 0.f;

    for (int step = 0; step < Tz; step++) {
        const float* sbp = sbuf + (p*4 + cc)*512;
        const float* Ap2 = Atile + jq*4;
        float4 acc = make_float4(0.f, 0.f, 0.f, 0.f);
#pragma unroll 4
        for (int i = ip*64; i < ip*64 + 64; i += 4) {
            float4 s4 = *(const float4*)(sbp + i);
            float4 a;
            a = *(const float4*)(Ap2 + (i+0)*64);
            acc.x = fmaf(s4.x, a.x, acc.x); acc.y = fmaf(s4.x, a.y, acc.y);
            acc.z = fmaf(s4.x, a.z, acc.z); acc.w = fmaf(s4.x, a.w, acc.w);
            a = *(const float4*)(Ap2 + (i+1)*64);
            acc.x = fmaf(s4.y, a.x, acc.x); acc.y = fmaf(s4.y, a.y, acc.y);
            acc.z = fmaf(s4.y, a.z, acc.z); acc.w = fmaf(s4.y, a.w, acc.w);
            a = *(const float4*)(Ap2 + (i+2)*64);
            acc.x = fmaf(s4.z, a.x, acc.x); acc.y = fmaf(s4.z, a.y, acc.y);
            acc.z = fmaf(s4.z, a.z, acc.z); acc.w = fmaf(s4.z, a.w, acc.w);
            a = *(const float4*)(Ap2 + (i+3)*64);
            acc.x = fmaf(s4.w, a.x, acc.x); acc.y = fmaf(s4.w, a.y, acc.y);
            acc.z = fmaf(s4.w, a.z, acc.z); acc.w = fmaf(s4.w, a.w, acc.w);
        }
        *(float4*)&pred[t*4] = acc;
        __syncthreads();

        float y = 0.f;
        if (t < 256) {
            y = uval;
#pragma unroll
            for (int q = 0; q < 8; q++)
                y += pred[(q*64 + c2*16 + (jj >> 2))*4 + (jj & 3)];
            float s1 = y, s2 = y*y;
#pragma unroll
            for (int o = 16; o > 0; o >>= 1) {
                s1 += __shfl_xor_sync(0xffffffffu, s1, o);
                s2 += __shfl_xor_sync(0xffffffffu, s2, o);
            }
            if ((t & 31) == 0) { ws[(t>>5)*2] = s1; ws[(t>>5)*2+1] = s2; }
        }
        __syncthreads();
        if (t < 4) {
            pl[t*2+0] = ws[t*4+0] + ws[t*4+2];
            pl[t*2+1] = ws[t*4+1] + ws[t*4+3];
        }
        __syncthreads();
        if (t < 64) {
            const int r = t >> 3, k = t & 7;
            const uint32_t la = pb_base + (uint32_t)(((p*8 + rank)*8 + k) * 4);
            uint32_t ra_;
            asm volatile("mapa.shared::cluster.u32 %0, %1, %2;" : "=r"(ra_) : "r"(la), "r"(r));
            asm volatile("st.shared::cluster.f32 [%0], %1;" :: "r"(ra_), "f"(pl[k]) : "memory");
        }
        float unext = 0.f;
        if (t < 256 && step + 1 < Tz)
            unext = g_u[urow0 + (size_t)(step + 1) * ST];

        asm volatile("barrier.cluster.arrive.aligned;\n" ::: "memory");
        asm volatile("barrier.cluster.wait.aligned;\n" ::: "memory");

        if (t < 256) {
            float q1 = 0.f, q2 = 0.f;
#pragma unroll
            for (int r = 0; r < 8; r++) {
                q1 += pbuf[(p*8 + r)*8 + c2*2 + 0];
                q2 += pbuf[(p*8 + r)*8 + c2*2 + 1];
            }
            const float mean = q1 * (1.f / ST);
            const float var  = q2 * (1.f / ST) - mean * mean;
            const float rstd = rsqrtf(var + EPSC);
            const float sval = (y - mean) * rstd * gj + bj;
            __half hh = __float2half_rn(sval);
            g_sh[urow0 + (size_t)step * ST] = hh;
            g_sl[urow0 + (size_t)step * ST] =
                __float2half_rn(sval - __half2float(hh));
            const uint32_t la = sb_base + (uint32_t)(((((p^1)*4 + c2)*512) + jg0 + jj) * 4);
#pragma unroll
            for (int r = 0; r < 8; r++) {
                uint32_t ra_;
                asm volatile("mapa.shared::cluster.u32 %0, %1, %2;" : "=r"(ra_) : "r"(la), "r"(r));
                asm volatile("st.shared::cluster.f32 [%0], %1;" :: "r"(ra_), "f"(sval) : "memory");
            }
        }
        uval = unext;

        asm volatile("barrier.cluster.arrive.aligned;\n" ::: "memory");
        asm volatile("barrier.cluster.wait.aligned;\n" ::: "memory");
        p ^= 1;
    }
}

// ---------------- launch ------------------------------------------------------
extern "C" void kernel_launch(void* const* d_in, const int* in_sizes, int n_in,
                              void* d_out, int out_size) {
    const float* x      = (const float*)d_in[0];
    const float* W_in   = (const float*)d_in[1];
    const float* b_in   = (const float*)d_in[2];
    const float* conv_w = (const float*)d_in[3];
    const float* conv_b = (const float*)d_in[4];
    const float* bng    = (const float*)d_in[5];
    const float* bnb    = (const float*)d_in[6];
    const float* lng    = (const float*)d_in[7];
    const float* lnb    = (const float*)d_in[8];
    const float* A      = (const float*)d_in[9];
    const float* Bm     = (const float*)d_in[10];
    const float* C      = (const float*)d_in[11];
    float* out = (float*)d_out;

    void *p_xh, *p_xl, *p_vh, *p_vl, *p_vch, *p_vcl, *p_u, *p_sh, *p_sl;
    void *p_wt, *p_wk, *p_bm, *p_ct, *p_ub;
    cudaGetSymbolAddress(&p_xh,  g_xh);  cudaGetSymbolAddress(&p_xl,  g_xl);
    cudaGetSymbolAddress(&p_vh,  g_vh);  cudaGetSymbolAddress(&p_vl,  g_vl);
    cudaGetSymbolAddress(&p_vch, g_vch); cudaGetSymbolAddress(&p_vcl, g_vcl);
    cudaGetSymbolAddress(&p_u,   g_u);
    cudaGetSymbolAddress(&p_sh,  g_sh);  cudaGetSymbolAddress(&p_sl,  g_sl);
    cudaGetSymbolAddress(&p_wt,  g_wt);  cudaGetSymbolAddress(&p_wk,  g_wk);
    cudaGetSymbolAddress(&p_bm,  g_bm);  cudaGetSymbolAddress(&p_ct,  g_ct);
    cudaGetSymbolAddress(&p_ub,  g_ubias);

    cudaFuncSetAttribute(k_tgemm, cudaFuncAttributeMaxDynamicSharedMemorySize, SMB_TOTAL);
    cudaFuncSetAttribute(k_recur, cudaFuncAttributeMaxDynamicSharedMemorySize,
                         RC_SMEM_FLOATS * 4);

    // 1) weights + x split
    k_prep<<<1536, 512>>>(W_in, conv_w, C);
    k_split<<<(M_ROWS*IND)/1024, 256>>>(x);
    // 2) v = silu(x @ W_in^T + b_in) -> split fp16
    k_tgemm<<<dim3(4, 1024), 256, SMB_TOTAL>>>(
        (const __half*)p_xh, (const __half*)p_xl, (const __half*)p_wt,
        b_in, nullptr, (__half*)p_vh, (__half*)p_vl, IND, ST, 1, 0);
    // 3) vc = conv1d(v) + conv_b -> split fp16
    k_tgemm<<<dim3(4, 1024), 256, SMB_TOTAL>>>(
        (const __half*)p_vh, (const __half*)p_vl, (const __half*)p_wk,
        conv_b, nullptr, (__half*)p_vch, (__half*)p_vcl, 3*ST, ST, 0, 1);
    // 4) BN stats
    k_stats<<<512, 512>>>();
    // 5) fold BN into Bm
    k_finalize<<<1, 512>>>(Bm, bng, bnb);
    // 6) u = vc @ Bm2 + ubias -> fp32
    k_tgemm<<<dim3(4, 1024), 256, SMB_TOTAL>>>(
        (const __half*)p_vch, (const __half*)p_vcl, (const __half*)p_bm,
        (const float*)p_ub, (float*)p_u, nullptr, nullptr, ST, ST, 0, 0);
    // 7) sequential recurrence -> split fp16 states
    k_recur<<<dim3(8, 16), 512, RC_SMEM_FLOATS * 4>>>(A, lng, lnb);
    // 8) y = S @ C
    k_tgemm<<<dim3(2, 1024), 256, SMB_TOTAL>>>(
        (const __half*)p_sh, (const __half*)p_sl, (const __half*)p_ct,
        nullptr, out, nullptr, nullptr, ST, OD, 0, 0);
}

// round 11
// speedup vs baseline: 3.1359x; 1.3588x over previous
#include <cuda_runtime.h>
#include <cuda_fp16.h>
#include <math.h>
#include <cstdint>

#define Bz   64
#define Tz   2048
#define IND  256
#define ST   512
#define OD   256
#define M_ROWS (Bz*Tz)   // 131072
#define EPSC 1e-5f

// ---------------- scratch (static device memory) -----------------------------
__device__ __half g_xh[(size_t)M_ROWS*IND], g_xl[(size_t)M_ROWS*IND];
__device__ __half g_vh[(size_t)M_ROWS*ST],  g_vl[(size_t)M_ROWS*ST];
__device__ __half g_vch[(size_t)M_ROWS*ST], g_vcl[(size_t)M_ROWS*ST];
__device__ float  g_u [(size_t)M_ROWS*ST];
__device__ __half g_sh[(size_t)M_ROWS*ST],  g_sl[(size_t)M_ROWS*ST];
__device__ __half g_wt[ST*IND];      // W_in  Bt[n][k] (single fp16)
__device__ __half g_wk[ST*3*ST];     // conv  Bt[n][tap*512+i]
__device__ __half g_bm[ST*ST];       // BN-folded Bm, Bt[j][i]
__device__ __half g_ct[OD*ST];       // C     Bt[n][k]
__device__ float g_ubias[ST];
__device__ float g_sum[ST];
__device__ float g_sumsq[ST];

__device__ __forceinline__ uint32_t smem_u32(const void* p) {
    return (uint32_t)__cvta_generic_to_shared(p);
}

// ---------------- prep: weights -> fp16 ---------------------------------------
__global__ void k_prep(const float* __restrict__ W_in, const float* __restrict__ conv_w,
                       const float* __restrict__ C) {
    int idx = blockIdx.x * blockDim.x + threadIdx.x;
    if (idx < ST*IND) {                 // W_in[n][k] -> Bt[n][k]
        g_wt[idx] = __float2half_rn(W_in[idx]);
    }
    if (idx < ST*3*ST) {                // conv: Bt[n][tap*512+i] = conv_w[n][i][tap]
        int n = idx / (3*ST);
        int rem = idx % (3*ST);
        int tap = rem / ST, i = rem % ST;
        g_wk[idx] = __float2half_rn(conv_w[((size_t)n*ST + i)*3 + tap]);
    }
    if (idx < OD*ST) {                  // C[k][n] -> Ct[n][k]
        int n = idx / ST, k = idx % ST;
        g_ct[idx] = __float2half_rn(C[(size_t)k*OD + n]);
    }
    if (idx < ST) { g_sum[idx] = 0.f; g_sumsq[idx] = 0.f; }
}

// split x -> fp16 hi/lo
__global__ __launch_bounds__(256)
void k_split(const float* __restrict__ x) {
    const size_t i = ((size_t)blockIdx.x * 256 + threadIdx.x) * 4;
    float4 v = *(const float4*)(x + i);
    __half2 h0 = __floats2half2_rn(v.x, v.y);
    __half2 h1 = __floats2half2_rn(v.z, v.w);
    __half2 l0 = __floats2half2_rn(v.x - __low2float(h0), v.y - __high2float(h0));
    __half2 l1 = __floats2half2_rn(v.z - __low2float(h1), v.w - __high2float(h1));
    uint2 hh; hh.x = *(uint32_t*)&h0; hh.y = *(uint32_t*)&h1;
    uint2 ll; ll.x = *(uint32_t*)&l0; ll.y = *(uint32_t*)&l1;
    *(uint2*)(g_xh + i) = hh;
    *(uint2*)(g_xl + i) = ll;
}

// ---------------- mma.sync helpers --------------------------------------------
__device__ __forceinline__ void mma16816(float* c, const uint32_t* a, const uint32_t* b) {
    asm volatile(
        "mma.sync.aligned.m16n8k16.row.col.f32.f16.f16.f32 "
        "{%0,%1,%2,%3}, {%4,%5,%6,%7}, {%8,%9}, {%0,%1,%2,%3};"
        : "+f"(c[0]), "+f"(c[1]), "+f"(c[2]), "+f"(c[3])
        : "r"(a[0]), "r"(a[1]), "r"(a[2]), "r"(a[3]), "r"(b[0]), "r"(b[1]));
}
__device__ __forceinline__ void ldsm4(uint32_t* r, uint32_t addr) {
    asm volatile("ldmatrix.sync.aligned.m8n8.x4.shared.b16 {%0,%1,%2,%3}, [%4];"
                 : "=r"(r[0]), "=r"(r[1]), "=r"(r[2]), "=r"(r[3]) : "r"(addr));
}
__device__ __forceinline__ void cpa16(uint32_t dst, const void* src, bool pred) {
    int sz = pred ? 16 : 0;
    asm volatile("cp.async.cg.shared.global [%0], [%1], 16, %2;"
                 :: "r"(dst), "l"(src), "r"(sz) : "memory");
}
#define CPA_COMMIT() asm volatile("cp.async.commit_group;" ::: "memory")

// ---------------- asymmetric fp16 warp-MMA GEMM --------------------------------
// out = act( A@B + bias ); A = Ah + Al (2-digit fp16), B single fp16.
// 128x128 CTA tile, K-chunks of 64, 2-stage cp.async; 2 CTAs/SM.
// Warp grid 4x2 (32-row x 64-col warp tiles) -> A ldmatrix redundancy 2.
#define SRS 72
#define TILE_HALFS (128*SRS)             // 9216 halfs = 18432 B
#define CHUNK_HALFS (3*TILE_HALFS)       // Ah, Al, B
#define SMB_TOTAL (2*CHUNK_HALFS*2)      // 110592 B

__global__ __launch_bounds__(256, 2)
void k_tgemm(const __half* __restrict__ Ah, const __half* __restrict__ Al,
             const __half* __restrict__ Bp,
             const float* __restrict__ bias, float* __restrict__ outf,
             __half* __restrict__ outh, __half* __restrict__ outl,
             int Kd, int N, int act, int convmode) {
    extern __shared__ __half smem[];
    const int t = threadIdx.x;
    const int w = t >> 5, lane = t & 31;
    const int wm = w >> 1, wn = w & 1;       // 4x2 warp grid
    const int m0 = blockIdx.y * 128, n0 = blockIdx.x * 128;

    float acc[2][8][4];
#pragma unroll
    for (int i = 0; i < 2; i++)
#pragma unroll
        for (int j = 0; j < 8; j++)
#pragma unroll
            for (int q = 0; q < 4; q++) acc[i][j][q] = 0.f;

    const uint32_t smb = smem_u32(smem);
    const uint32_t aBase = smb +
        (uint32_t)(((wm*32 + (lane & 15)) * SRS + (lane >> 4) * 8) * 2);
    const uint32_t alOff = TILE_HALFS * 2;
    // B ldsm4: lanes 0-7: n+0..7@k0 ; 8-15: n+0..7@k8 ; 16-23: n+8..15@k0 ; 24-31: n+8..15@k8
    const uint32_t bBase = smb + 2*TILE_HALFS*2 +
        (uint32_t)(((wn*64 + (lane & 7) + ((lane >> 4) & 1) * 8) * SRS
                    + ((lane >> 3) & 1) * 8) * 2);

    const int sr = t >> 3, sj = t & 7;
    const int nch = Kd >> 6;

    auto stage = [&](int c, int buf) {
        const int k0 = c << 6;
        __half* base = smem + buf * CHUNK_HALFS;
        __half* sAh = base;
        __half* sAl = base + TILE_HALFS;
        __half* sB  = base + 2*TILE_HALFS;
        const int tap = convmode ? (k0 >> 9) : 0;
        const int kl0 = convmode ? (k0 & 511) : k0;
#pragma unroll
        for (int it = 0; it < 4; it++) {
            const int r = sr + it * 32;
            const uint32_t so = (uint32_t)((r * SRS + sj * 8) * 2);
            {
                const size_t goff = (size_t)(n0 + r) * Kd + k0 + sj * 8;
                cpa16(smem_u32(sB) + so, Bp + goff, true);
            }
            {
                const int rg = m0 + r;
                bool pred = true;
                size_t goff;
                if (convmode) {
                    const int tl = (rg & (Tz - 1)) + tap - 1;
                    pred = (tl >= 0) && (tl < Tz);
                    const int rs = pred ? (rg + tap - 1) : rg;
                    goff = (size_t)rs * ST + kl0 + sj * 8;
                } else {
                    goff = (size_t)rg * Kd + k0 + sj * 8;
                }
                cpa16(smem_u32(sAh) + so, Ah + goff, pred);
                cpa16(smem_u32(sAl) + so, Al + goff, pred);
            }
        }
    };

    uint32_t fah[2][4], fal[2][4], fb[4][4];

    stage(0, 0);
    CPA_COMMIT();

    for (int c = 0; c < nch; c++) {
        const bool more = (c + 1) < nch;
        if (more) { stage(c + 1, (c + 1) & 1); CPA_COMMIT(); }
        if (more) asm volatile("cp.async.wait_group 1;" ::: "memory");
        else      asm volatile("cp.async.wait_group 0;" ::: "memory");
        __syncthreads();

        const uint32_t boff = (uint32_t)((c & 1) * CHUNK_HALFS * 2);
#pragma unroll
        for (int ks = 0; ks < 4; ks++) {
            const uint32_t koff = boff + (uint32_t)(ks * 32);
#pragma unroll
            for (int mi = 0; mi < 2; mi++) {
                ldsm4(fah[mi], aBase + (uint32_t)(mi * 16 * SRS * 2) + koff);
                ldsm4(fal[mi], aBase + alOff + (uint32_t)(mi * 16 * SRS * 2) + koff);
            }
#pragma unroll
            for (int nb = 0; nb < 4; nb++)
                ldsm4(fb[nb], bBase + (uint32_t)(nb * 16 * SRS * 2) + koff);
            // term Ah*B
#pragma unroll
            for (int mi = 0; mi < 2; mi++)
#pragma unroll
                for (int ni = 0; ni < 8; ni++)
                    mma16816(acc[mi][ni], fah[mi], &fb[ni >> 1][(ni & 1) * 2]);
            // term Al*B
#pragma unroll
            for (int mi = 0; mi < 2; mi++)
#pragma unroll
                for (int ni = 0; ni < 8; ni++)
                    mma16816(acc[mi][ni], fal[mi], &fb[ni >> 1][(ni & 1) * 2]);
        }
        __syncthreads();
    }

    // ---- epilogue -------------------------------------------------------------
    const int g = lane >> 2, tg = lane & 3;
#pragma unroll
    for (int mi = 0; mi < 2; mi++) {
#pragma unroll
        for (int ni = 0; ni < 8; ni++) {
            const int col = n0 + wn*64 + ni*8 + tg*2;
            const float b0 = bias ? bias[col]     : 0.f;
            const float b1 = bias ? bias[col + 1] : 0.f;
#pragma unroll
            for (int half = 0; half < 2; half++) {
                const int row = m0 + wm*32 + mi*16 + g + half*8;
                float v0 = acc[mi][ni][half*2+0] + b0;
                float v1 = acc[mi][ni][half*2+1] + b1;
                if (act == 1) {
                    v0 = v0 / (1.f + expf(-v0));
                    v1 = v1 / (1.f + expf(-v1));
                }
                if (outf) {
                    float2 f2; f2.x = v0; f2.y = v1;
                    *(float2*)(outf + (size_t)row * N + col) = f2;
                }
                if (outh) {
                    __half2 h2 = __floats2half2_rn(v0, v1);
                    __half2 l2 = __floats2half2_rn(v0 - __low2float(h2),
                                                   v1 - __high2float(h2));
                    *(__half2*)(outh + (size_t)row * N + col) = h2;
                    *(__half2*)(outl + (size_t)row * N + col) = l2;
                }
            }
        }
    }
}

// ---------------- BN stats (from split vc) ------------------------------------
__global__ __launch_bounds__(512)
void k_stats() {
    const int n = threadIdx.x;
    const int rpc = M_ROWS / 512;
    const int r0 = blockIdx.x * rpc;
    float s1 = 0.f, s2 = 0.f;
    for (int r = 0; r < rpc; r++) {
        const size_t o = (size_t)(r0 + r) * ST + n;
        float v = __half2float(g_vch[o]) + __half2float(g_vcl[o]);
        s1 += v; s2 += v * v;
    }
    atomicAdd(&g_sum[n], s1);
    atomicAdd(&g_sumsq[n], s2);
}

// fold BN into Bm (single fp16 weights, fp32 bias)
__global__ __launch_bounds__(512)
void k_finalize(const float* __restrict__ Bm, const float* __restrict__ bng,
                const float* __restrict__ bnb) {
    __shared__ float sc[ST], sh[ST];
    const int j = threadIdx.x;
    float mu  = g_sum[j]   * (1.f / M_ROWS);
    float var = g_sumsq[j] * (1.f / M_ROWS) - mu * mu;
    float inv = rsqrtf(var + EPSC);
    float s   = bng[j] * inv;
    sc[j] = s;
    sh[j] = bnb[j] - mu * s;
    __syncthreads();
    float ub = 0.f;
    for (int i = 0; i < ST; i++) {
        float bmv = Bm[(size_t)i * ST + j];
        g_bm[(size_t)j * ST + i] = __float2half_rn(sc[i] * bmv);
        ub += sh[i] * bmv;
    }
    g_ubias[j] = ub;
}

// ---------------- cluster recurrence: 4-chain A reuse --------------------------
// Thread (ip = t>>4, jq = t&15) computes, for ALL 4 chains, the partial matvec
// over i in [ip*16, ip*16+16) and j = jq*4..+3. One A load serves 4 chains.
// PRED_STRIDE must be a multiple of 4 (float4 writes at ip*PRED_STRIDE).
#define PRED_STRIDE 260
#define RC_OFF_SBUF 32768              // [2][4][512]
#define RC_OFF_PBUF 36864              // [2][8][8]
#define RC_OFF_PRED 36992              // [32][260]
#define RC_OFF_WS   (RC_OFF_PRED + 32*PRED_STRIDE)  // [16]
#define RC_OFF_PL   (RC_OFF_WS + 16)                // [8]
#define RC_SMEM_FLOATS (RC_OFF_PL + 8 + 8)
__global__ __launch_bounds__(512, 1) __cluster_dims__(8, 1, 1)
void k_recur(const float* __restrict__ A, const float* __restrict__ lng,
             const float* __restrict__ lnb) {
    extern __shared__ float sm[];
    float* Atile = sm;                   // [512][64]
    float* sbuf  = sm + RC_OFF_SBUF;
    float* pbuf  = sm + RC_OFF_PBUF;
    float* pred  = sm + RC_OFF_PRED;
    float* ws    = sm + RC_OFF_WS;
    float* pl    = sm + RC_OFF_PL;

    const int t    = threadIdx.x;
    const int rank = blockIdx.x;
    const int grp  = blockIdx.y;
    const int jg0  = rank * 64;

    for (int idx = t; idx < 512 * 16; idx += 512) {
        int i  = idx >> 4;
        int jv = (idx & 15) << 2;
        *(float4*)&Atile[i*64 + jv] = *(const float4*)(A + (size_t)i*ST + jg0 + jv);
    }
    for (int idx = t; idx < 4*512; idx += 512) sbuf[idx] = 0.f;

    const int ip = t >> 4;         // 0..31, i-slice of 16
    const int jq = t & 15;         // 0..15, j quad
    const int c2 = t >> 6;         // finalize: chain (t<256)
    const int jj = t & 63;

    float gj = 0.f, bj = 0.f;
    size_t urow0 = 0;
    if (t < 256) {
        gj = lng[jg0 + jj];
        bj = lnb[jg0 + jj];
        const int chain = grp * 4 + c2;
        urow0 = (size_t)chain * Tz * ST + jg0 + jj;
    }

    const uint32_t sb_base = smem_u32(sbuf);
    const uint32_t pb_base = smem_u32(pbuf);

    asm volatile("barrier.cluster.arrive.aligned;\n" ::: "memory");
    asm volatile("barrier.cluster.wait.aligned;\n" ::: "memory");

    int p = 0;
    float uval = (t < 256) ? g_u[urow0] : 0.f;

    for (int step = 0; step < Tz; step++) {
        // ---- compute: 4-chain partial matvec ------------------------------
        const float* Arow = Atile + (ip*16)*64 + jq*4;
        const float* s0p = sbuf + (p*4 + 0)*512 + ip*16;
        const float* s1p = s0p + 512;
        const float* s2p = s1p + 512;
        const float* s3p = s2p + 512;
        float4 a0 = make_float4(0,0,0,0), a1 = a0, a2 = a0, a3 = a0;
#pragma unroll
        for (int ii = 0; ii < 16; ii += 4) {
            float4 sA = *(const float4*)(s0p + ii);
            float4 sB_ = *(const float4*)(s1p + ii);
            float4 sC = *(const float4*)(s2p + ii);
            float4 sD = *(const float4*)(s3p + ii);
#pragma unroll
            for (int q2 = 0; q2 < 4; q2++) {
                float4 av = *(const float4*)(Arow + (ii + q2) * 64);
                const float w0 = (&sA.x)[q2], w1 = (&sB_.x)[q2];
                const float w2 = (&sC.x)[q2], w3 = (&sD.x)[q2];
                a0.x = fmaf(w0, av.x, a0.x); a0.y = fmaf(w0, av.y, a0.y);
                a0.z = fmaf(w0, av.z, a0.z); a0.w = fmaf(w0, av.w, a0.w);
                a1.x = fmaf(w1, av.x, a1.x); a1.y = fmaf(w1, av.y, a1.y);
                a1.z = fmaf(w1, av.z, a1.z); a1.w = fmaf(w1, av.w, a1.w);
                a2.x = fmaf(w2, av.x, a2.x); a2.y = fmaf(w2, av.y, a2.y);
                a2.z = fmaf(w2, av.z, a2.z); a2.w = fmaf(w2, av.w, a2.w);
                a3.x = fmaf(w3, av.x, a3.x); a3.y = fmaf(w3, av.y, a3.y);
                a3.z = fmaf(w3, av.z, a3.z); a3.w = fmaf(w3, av.w, a3.w);
            }
        }
        {
            float* pr = pred + ip * PRED_STRIDE + jq * 4;
            *(float4*)(pr + 0*64) = a0;
            *(float4*)(pr + 1*64) = a1;
            *(float4*)(pr + 2*64) = a2;
            *(float4*)(pr + 3*64) = a3;
        }
        __syncthreads();

        // ---- finalize y + local LN partials -------------------------------
        float y = 0.f;
        if (t < 256) {
            y = uval;
            const float* pr = pred + c2 * 64 + jj;
#pragma unroll 8
            for (int q = 0; q < 32; q++)
                y += pr[q * PRED_STRIDE];
            float s1 = y, s2 = y*y;
#pragma unroll
            for (int o = 16; o > 0; o >>= 1) {
                s1 += __shfl_xor_sync(0xffffffffu, s1, o);
                s2 += __shfl_xor_sync(0xffffffffu, s2, o);
            }
            if ((t & 31) == 0) { ws[(t>>5)*2] = s1; ws[(t>>5)*2+1] = s2; }
        }
        __syncthreads();
        if (t < 4) {
            pl[t*2+0] = ws[t*4+0] + ws[t*4+2];
            pl[t*2+1] = ws[t*4+1] + ws[t*4+3];
        }
        __syncthreads();
        if (t < 64) {
            const int r = t >> 3, k = t & 7;
            const uint32_t la = pb_base + (uint32_t)(((p*8 + rank)*8 + k) * 4);
            uint32_t ra_;
            asm volatile("mapa.shared::cluster.u32 %0, %1, %2;" : "=r"(ra_) : "r"(la), "r"(r));
            asm volatile("st.shared::cluster.f32 [%0], %1;" :: "r"(ra_), "f"(pl[k]) : "memory");
        }
        float unext = 0.f;
        if (t < 256 && step + 1 < Tz)
            unext = g_u[urow0 + (size_t)(step + 1) * ST];

        asm volatile("barrier.cluster.arrive.aligned;\n" ::: "memory");
        asm volatile("barrier.cluster.wait.aligned;\n" ::: "memory");

        if (t < 256) {
            float q1 = 0.f, q2 = 0.f;
#pragma unroll
            for (int r = 0; r < 8; r++) {
                q1 += pbuf[(p*8 + r)*8 + c2*2 + 0];
                q2 += pbuf[(p*8 + r)*8 + c2*2 + 1];
            }
            const float mean = q1 * (1.f / ST);
            const float var  = q2 * (1.f / ST) - mean * mean;
            const float rstd = rsqrtf(var + EPSC);
            const float sval = (y - mean) * rstd * gj + bj;
            __half hh = __float2half_rn(sval);
            g_sh[urow0 + (size_t)step * ST] = hh;
            g_sl[urow0 + (size_t)step * ST] =
                __float2half_rn(sval - __half2float(hh));
            const uint32_t la = sb_base + (uint32_t)(((((p^1)*4 + c2)*512) + jg0 + jj) * 4);
#pragma unroll
            for (int r = 0; r < 8; r++) {
                uint32_t ra_;
                asm volatile("mapa.shared::cluster.u32 %0, %1, %2;" : "=r"(ra_) : "r"(la), "r"(r));
                asm volatile("st.shared::cluster.f32 [%0], %1;" :: "r"(ra_), "f"(sval) : "memory");
            }
        }
        uval = unext;

        asm volatile("barrier.cluster.arrive.aligned;\n" ::: "memory");
        asm volatile("barrier.cluster.wait.aligned;\n" ::: "memory");
        p ^= 1;
    }
}

// ---------------- launch ------------------------------------------------------
extern "C" void kernel_launch(void* const* d_in, const int* in_sizes, int n_in,
                              void* d_out, int out_size) {
    const float* x      = (const float*)d_in[0];
    const float* W_in   = (const float*)d_in[1];
    const float* b_in   = (const float*)d_in[2];
    const float* conv_w = (const float*)d_in[3];
    const float* conv_b = (const float*)d_in[4];
    const float* bng    = (const float*)d_in[5];
    const float* bnb    = (const float*)d_in[6];
    const float* lng    = (const float*)d_in[7];
    const float* lnb    = (const float*)d_in[8];
    const float* A      = (const float*)d_in[9];
    const float* Bm     = (const float*)d_in[10];
    const float* C      = (const float*)d_in[11];
    float* out = (float*)d_out;

    void *p_xh, *p_xl, *p_vh, *p_vl, *p_vch, *p_vcl, *p_u, *p_sh, *p_sl;
    void *p_wt, *p_wk, *p_bm, *p_ct, *p_ub;
    cudaGetSymbolAddress(&p_xh,  g_xh);  cudaGetSymbolAddress(&p_xl,  g_xl);
    cudaGetSymbolAddress(&p_vh,  g_vh);  cudaGetSymbolAddress(&p_vl,  g_vl);
    cudaGetSymbolAddress(&p_vch, g_vch); cudaGetSymbolAddress(&p_vcl, g_vcl);
    cudaGetSymbolAddress(&p_u,   g_u);
    cudaGetSymbolAddress(&p_sh,  g_sh);  cudaGetSymbolAddress(&p_sl,  g_sl);
    cudaGetSymbolAddress(&p_wt,  g_wt);  cudaGetSymbolAddress(&p_wk,  g_wk);
    cudaGetSymbolAddress(&p_bm,  g_bm);  cudaGetSymbolAddress(&p_ct,  g_ct);
    cudaGetSymbolAddress(&p_ub,  g_ubias);

    cudaFuncSetAttribute(k_tgemm, cudaFuncAttributeMaxDynamicSharedMemorySize, SMB_TOTAL);
    cudaFuncSetAttribute(k_recur, cudaFuncAttributeMaxDynamicSharedMemorySize,
                         RC_SMEM_FLOATS * 4);

    // 1) weights + x split
    k_prep<<<1536, 512>>>(W_in, conv_w, C);
    k_split<<<(M_ROWS*IND)/1024, 256>>>(x);
    // 2) v = silu(x @ W_in^T + b_in) -> split fp16
    k_tgemm<<<dim3(4, 1024), 256, SMB_TOTAL>>>(
        (const __half*)p_xh, (const __half*)p_xl, (const __half*)p_wt,
        b_in, nullptr, (__half*)p_vh, (__half*)p_vl, IND, ST, 1, 0);
    // 3) vc = conv1d(v) + conv_b -> split fp16
    k_tgemm<<<dim3(4, 1024), 256, SMB_TOTAL>>>(
        (const __half*)p_vh, (const __half*)p_vl, (const __half*)p_wk,
        conv_b, nullptr, (__half*)p_vch, (__half*)p_vcl, 3*ST, ST, 0, 1);
    // 4) BN stats
    k_stats<<<512, 512>>>();
    // 5) fold BN into Bm
    k_finalize<<<1, 512>>>(Bm, bng, bnb);
    // 6) u = vc @ Bm2 + ubias -> fp32
    k_tgemm<<<dim3(4, 1024), 256, SMB_TOTAL>>>(
        (const __half*)p_vch, (const __half*)p_vcl, (const __half*)p_bm,
        (const float*)p_ub, (float*)p_u, nullptr, nullptr, ST, ST, 0, 0);
    // 7) sequential recurrence -> split fp16 states
    k_recur<<<dim3(8, 16), 512, RC_SMEM_FLOATS * 4>>>(A, lng, lnb);
    // 8) y = S @ C
    k_tgemm<<<dim3(2, 1024), 256, SMB_TOTAL>>>(
        (const __half*)p_sh, (const __half*)p_sl, (const __half*)p_ct,
        nullptr, out, nullptr, nullptr, ST, OD, 0, 0);
}

// round 12
// speedup vs baseline: 3.3045x; 1.0538x over previous
#include <cuda_runtime.h>
#include <cuda_fp16.h>
#include <math.h>
#include <cstdint>

#define Bz   64
#define Tz   2048
#define IND  256
#define ST   512
#define OD   256
#define M_ROWS (Bz*Tz)   // 131072
#define EPSC 1e-5f

// ---------------- scratch (static device memory) -----------------------------
__device__ __half g_xh[(size_t)M_ROWS*IND];
__device__ __half g_vh[(size_t)M_ROWS*ST];
__device__ __half g_vch[(size_t)M_ROWS*ST];
__device__ float  g_u [(size_t)M_ROWS*ST];
__device__ __half g_sh[(size_t)M_ROWS*ST],  g_sl[(size_t)M_ROWS*ST];
__device__ __half g_wt[ST*IND];      // W_in  Bt[n][k] (single fp16)
__device__ __half g_wk[ST*3*ST];     // conv  Bt[n][tap*512+i]
__device__ __half g_bm[ST*ST];       // BN-folded Bm, Bt[j][i]
__device__ __half g_ct[OD*ST];       // C     Bt[n][k]
__device__ float g_ubias[ST];
__device__ float g_sum[ST];
__device__ float g_sumsq[ST];

__device__ __forceinline__ uint32_t smem_u32(const void* p) {
    return (uint32_t)__cvta_generic_to_shared(p);
}

// ---------------- prep: weights -> fp16 ---------------------------------------
__global__ void k_prep(const float* __restrict__ W_in, const float* __restrict__ conv_w,
                       const float* __restrict__ C) {
    int idx = blockIdx.x * blockDim.x + threadIdx.x;
    if (idx < ST*IND) {                 // W_in[n][k] -> Bt[n][k]
        g_wt[idx] = __float2half_rn(W_in[idx]);
    }
    if (idx < ST*3*ST) {                // conv: Bt[n][tap*512+i] = conv_w[n][i][tap]
        int n = idx / (3*ST);
        int rem = idx % (3*ST);
        int tap = rem / ST, i = rem % ST;
        g_wk[idx] = __float2half_rn(conv_w[((size_t)n*ST + i)*3 + tap]);
    }
    if (idx < OD*ST) {                  // C[k][n] -> Ct[n][k]
        int n = idx / ST, k = idx % ST;
        g_ct[idx] = __float2half_rn(C[(size_t)k*OD + n]);
    }
    if (idx < ST) { g_sum[idx] = 0.f; g_sumsq[idx] = 0.f; }
}

// x -> fp16 (single digit; proj output is BN/LN-renormalized downstream)
__global__ __launch_bounds__(256)
void k_split(const float* __restrict__ x) {
    const size_t i = ((size_t)blockIdx.x * 256 + threadIdx.x) * 4;
    float4 v = *(const float4*)(x + i);
    __half2 h0 = __floats2half2_rn(v.x, v.y);
    __half2 h1 = __floats2half2_rn(v.z, v.w);
    uint2 hh; hh.x = *(uint32_t*)&h0; hh.y = *(uint32_t*)&h1;
    *(uint2*)(g_xh + i) = hh;
}

// ---------------- mma.sync helpers --------------------------------------------
__device__ __forceinline__ void mma16816(float* c, const uint32_t* a, const uint32_t* b) {
    asm volatile(
        "mma.sync.aligned.m16n8k16.row.col.f32.f16.f16.f32 "
        "{%0,%1,%2,%3}, {%4,%5,%6,%7}, {%8,%9}, {%0,%1,%2,%3};"
        : "+f"(c[0]), "+f"(c[1]), "+f"(c[2]), "+f"(c[3])
        : "r"(a[0]), "r"(a[1]), "r"(a[2]), "r"(a[3]), "r"(b[0]), "r"(b[1]));
}
__device__ __forceinline__ void ldsm4(uint32_t* r, uint32_t addr) {
    asm volatile("ldmatrix.sync.aligned.m8n8.x4.shared.b16 {%0,%1,%2,%3}, [%4];"
                 : "=r"(r[0]), "=r"(r[1]), "=r"(r[2]), "=r"(r[3]) : "r"(addr));
}
__device__ __forceinline__ void cpa16(uint32_t dst, const void* src, bool pred) {
    int sz = pred ? 16 : 0;
    asm volatile("cp.async.cg.shared.global [%0], [%1], 16, %2;"
                 :: "r"(dst), "l"(src), "r"(sz) : "memory");
}
#define CPA_COMMIT() asm volatile("cp.async.commit_group;" ::: "memory")

// ---------------- fp16 warp-MMA GEMM -------------------------------------------
// out = act( A@B + bias ); A = Ah (+ Al if non-null), B single fp16.
// 128x128 CTA tile, K-chunks of 64, 2-stage cp.async; 2 CTAs/SM.
// Warp grid 4x2 (32-row x 64-col warp tiles).
#define SRS 72
#define TILE_HALFS (128*SRS)             // 9216 halfs = 18432 B
#define CHUNK_HALFS (3*TILE_HALFS)       // Ah, Al, B slots
#define SMB_TOTAL (2*CHUNK_HALFS*2)      // 110592 B

__global__ __launch_bounds__(256, 2)
void k_tgemm(const __half* __restrict__ Ah, const __half* __restrict__ Al,
             const __half* __restrict__ Bp,
             const float* __restrict__ bias, float* __restrict__ outf,
             __half* __restrict__ outh, __half* __restrict__ outl,
             int Kd, int N, int act, int convmode) {
    extern __shared__ __half smem[];
    const int t = threadIdx.x;
    const int w = t >> 5, lane = t & 31;
    const int wm = w >> 1, wn = w & 1;       // 4x2 warp grid
    const int m0 = blockIdx.y * 128, n0 = blockIdx.x * 128;
    const bool twoTerm = (Al != nullptr);

    float acc[2][8][4];
#pragma unroll
    for (int i = 0; i < 2; i++)
#pragma unroll
        for (int j = 0; j < 8; j++)
#pragma unroll
            for (int q = 0; q < 4; q++) acc[i][j][q] = 0.f;

    const uint32_t smb = smem_u32(smem);
    const uint32_t aBase = smb +
        (uint32_t)(((wm*32 + (lane & 15)) * SRS + (lane >> 4) * 8) * 2);
    const uint32_t alOff = TILE_HALFS * 2;
    // B ldsm4: lanes 0-7: n+0..7@k0 ; 8-15: n+0..7@k8 ; 16-23: n+8..15@k0 ; 24-31: n+8..15@k8
    const uint32_t bBase = smb + 2*TILE_HALFS*2 +
        (uint32_t)(((wn*64 + (lane & 7) + ((lane >> 4) & 1) * 8) * SRS
                    + ((lane >> 3) & 1) * 8) * 2);

    const int sr = t >> 3, sj = t & 7;
    const int nch = Kd >> 6;

    auto stage = [&](int c, int buf) {
        const int k0 = c << 6;
        __half* base = smem + buf * CHUNK_HALFS;
        __half* sAh = base;
        __half* sAl = base + TILE_HALFS;
        __half* sB  = base + 2*TILE_HALFS;
        const int tap = convmode ? (k0 >> 9) : 0;
        const int kl0 = convmode ? (k0 & 511) : k0;
#pragma unroll
        for (int it = 0; it < 4; it++) {
            const int r = sr + it * 32;
            const uint32_t so = (uint32_t)((r * SRS + sj * 8) * 2);
            {
                const size_t goff = (size_t)(n0 + r) * Kd + k0 + sj * 8;
                cpa16(smem_u32(sB) + so, Bp + goff, true);
            }
            {
                const int rg = m0 + r;
                bool pred = true;
                size_t goff;
                if (convmode) {
                    const int tl = (rg & (Tz - 1)) + tap - 1;
                    pred = (tl >= 0) && (tl < Tz);
                    const int rs = pred ? (rg + tap - 1) : rg;
                    goff = (size_t)rs * ST + kl0 + sj * 8;
                } else {
                    goff = (size_t)rg * Kd + k0 + sj * 8;
                }
                cpa16(smem_u32(sAh) + so, Ah + goff, pred);
                if (twoTerm) cpa16(smem_u32(sAl) + so, Al + goff, pred);
            }
        }
    };

    uint32_t fah[2][4], fal[2][4], fb[4][4];

    stage(0, 0);
    CPA_COMMIT();

    for (int c = 0; c < nch; c++) {
        const bool more = (c + 1) < nch;
        if (more) { stage(c + 1, (c + 1) & 1); CPA_COMMIT(); }
        if (more) asm volatile("cp.async.wait_group 1;" ::: "memory");
        else      asm volatile("cp.async.wait_group 0;" ::: "memory");
        __syncthreads();

        const uint32_t boff = (uint32_t)((c & 1) * CHUNK_HALFS * 2);
#pragma unroll
        for (int ks = 0; ks < 4; ks++) {
            const uint32_t koff = boff + (uint32_t)(ks * 32);
#pragma unroll
            for (int mi = 0; mi < 2; mi++) {
                ldsm4(fah[mi], aBase + (uint32_t)(mi * 16 * SRS * 2) + koff);
                if (twoTerm)
                    ldsm4(fal[mi], aBase + alOff + (uint32_t)(mi * 16 * SRS * 2) + koff);
            }
#pragma unroll
            for (int nb = 0; nb < 4; nb++)
                ldsm4(fb[nb], bBase + (uint32_t)(nb * 16 * SRS * 2) + koff);
            // term Ah*B
#pragma unroll
            for (int mi = 0; mi < 2; mi++)
#pragma unroll
                for (int ni = 0; ni < 8; ni++)
                    mma16816(acc[mi][ni], fah[mi], &fb[ni >> 1][(ni & 1) * 2]);
            // term Al*B
            if (twoTerm) {
#pragma unroll
                for (int mi = 0; mi < 2; mi++)
#pragma unroll
                    for (int ni = 0; ni < 8; ni++)
                        mma16816(acc[mi][ni], fal[mi], &fb[ni >> 1][(ni & 1) * 2]);
            }
        }
        __syncthreads();
    }

    // ---- epilogue -------------------------------------------------------------
    const int g = lane >> 2, tg = lane & 3;
#pragma unroll
    for (int mi = 0; mi < 2; mi++) {
#pragma unroll
        for (int ni = 0; ni < 8; ni++) {
            const int col = n0 + wn*64 + ni*8 + tg*2;
            const float b0 = bias ? bias[col]     : 0.f;
            const float b1 = bias ? bias[col + 1] : 0.f;
#pragma unroll
            for (int half = 0; half < 2; half++) {
                const int row = m0 + wm*32 + mi*16 + g + half*8;
                float v0 = acc[mi][ni][half*2+0] + b0;
                float v1 = acc[mi][ni][half*2+1] + b1;
                if (act == 1) {
                    v0 = v0 / (1.f + expf(-v0));
                    v1 = v1 / (1.f + expf(-v1));
                }
                if (outf) {
                    float2 f2; f2.x = v0; f2.y = v1;
                    *(float2*)(outf + (size_t)row * N + col) = f2;
                }
                if (outh) {
                    __half2 h2 = __floats2half2_rn(v0, v1);
                    *(__half2*)(outh + (size_t)row * N + col) = h2;
                    if (outl) {
                        __half2 l2 = __floats2half2_rn(v0 - __low2float(h2),
                                                       v1 - __high2float(h2));
                        *(__half2*)(outl + (size_t)row * N + col) = l2;
                    }
                }
            }
        }
    }
}

// ---------------- BN stats (from fp16 vc) --------------------------------------
__global__ __launch_bounds__(512)
void k_stats() {
    const int n = threadIdx.x;
    const int rpc = M_ROWS / 512;
    const int r0 = blockIdx.x * rpc;
    float s1 = 0.f, s2 = 0.f;
    for (int r = 0; r < rpc; r++) {
        const size_t o = (size_t)(r0 + r) * ST + n;
        float v = __half2float(g_vch[o]);
        s1 += v; s2 += v * v;
    }
    atomicAdd(&g_sum[n], s1);
    atomicAdd(&g_sumsq[n], s2);
}

// fold BN into Bm (single fp16 weights, fp32 bias)
__global__ __launch_bounds__(512)
void k_finalize(const float* __restrict__ Bm, const float* __restrict__ bng,
                const float* __restrict__ bnb) {
    __shared__ float sc[ST], sh[ST];
    const int j = threadIdx.x;
    float mu  = g_sum[j]   * (1.f / M_ROWS);
    float var = g_sumsq[j] * (1.f / M_ROWS) - mu * mu;
    float inv = rsqrtf(var + EPSC);
    float s   = bng[j] * inv;
    sc[j] = s;
    sh[j] = bnb[j] - mu * s;
    __syncthreads();
    float ub = 0.f;
    for (int i = 0; i < ST; i++) {
        float bmv = Bm[(size_t)i * ST + j];
        g_bm[(size_t)j * ST + i] = __float2half_rn(sc[i] * bmv);
        ub += sh[i] * bmv;
    }
    g_ubias[j] = ub;
}

// ---------------- cluster recurrence: 4-chain A reuse --------------------------
#define PRED_STRIDE 260
#define RC_OFF_SBUF 32768              // [2][4][512]
#define RC_OFF_PBUF 36864              // [2][8][8]
#define RC_OFF_PRED 36992              // [32][260]
#define RC_OFF_WS   (RC_OFF_PRED + 32*PRED_STRIDE)  // [16]
#define RC_OFF_PL   (RC_OFF_WS + 16)                // [8]
#define RC_SMEM_FLOATS (RC_OFF_PL + 8 + 8)
__global__ __launch_bounds__(512, 1) __cluster_dims__(8, 1, 1)
void k_recur(const float* __restrict__ A, const float* __restrict__ lng,
             const float* __restrict__ lnb) {
    extern __shared__ float sm[];
    float* Atile = sm;                   // [512][64]
    float* sbuf  = sm + RC_OFF_SBUF;
    float* pbuf  = sm + RC_OFF_PBUF;
    float* pred  = sm + RC_OFF_PRED;
    float* ws    = sm + RC_OFF_WS;
    float* pl    = sm + RC_OFF_PL;

    const int t    = threadIdx.x;
    const int rank = blockIdx.x;
    const int grp  = blockIdx.y;
    const int jg0  = rank * 64;

    for (int idx = t; idx < 512 * 16; idx += 512) {
        int i  = idx >> 4;
        int jv = (idx & 15) << 2;
        *(float4*)&Atile[i*64 + jv] = *(const float4*)(A + (size_t)i*ST + jg0 + jv);
    }
    for (int idx = t; idx < 4*512; idx += 512) sbuf[idx] = 0.f;

    const int ip = t >> 4;         // 0..31, i-slice of 16
    const int jq = t & 15;         // 0..15, j quad
    const int c2 = t >> 6;         // finalize: chain (t<256)
    const int jj = t & 63;

    float gj = 0.f, bj = 0.f;
    size_t urow0 = 0;
    if (t < 256) {
        gj = lng[jg0 + jj];
        bj = lnb[jg0 + jj];
        const int chain = grp * 4 + c2;
        urow0 = (size_t)chain * Tz * ST + jg0 + jj;
    }

    const uint32_t sb_base = smem_u32(sbuf);
    const uint32_t pb_base = smem_u32(pbuf);

    asm volatile("barrier.cluster.arrive.aligned;\n" ::: "memory");
    asm volatile("barrier.cluster.wait.aligned;\n" ::: "memory");

    int p = 0;
    float uval = (t < 256) ? g_u[urow0] : 0.f;

    for (int step = 0; step < Tz; step++) {
        // ---- compute: 4-chain partial matvec ------------------------------
        const float* Arow = Atile + (ip*16)*64 + jq*4;
        const float* s0p = sbuf + (p*4 + 0)*512 + ip*16;
        const float* s1p = s0p + 512;
        const float* s2p = s1p + 512;
        const float* s3p = s2p + 512;
        float4 a0 = make_float4(0,0,0,0), a1 = a0, a2 = a0, a3 = a0;
#pragma unroll
        for (int ii = 0; ii < 16; ii += 4) {
            float4 sA = *(const float4*)(s0p + ii);
            float4 sB_ = *(const float4*)(s1p + ii);
            float4 sC = *(const float4*)(s2p + ii);
            float4 sD = *(const float4*)(s3p + ii);
#pragma unroll
            for (int q2 = 0; q2 < 4; q2++) {
                float4 av = *(const float4*)(Arow + (ii + q2) * 64);
                const float w0 = (&sA.x)[q2], w1 = (&sB_.x)[q2];
                const float w2 = (&sC.x)[q2], w3 = (&sD.x)[q2];
                a0.x = fmaf(w0, av.x, a0.x); a0.y = fmaf(w0, av.y, a0.y);
                a0.z = fmaf(w0, av.z, a0.z); a0.w = fmaf(w0, av.w, a0.w);
                a1.x = fmaf(w1, av.x, a1.x); a1.y = fmaf(w1, av.y, a1.y);
                a1.z = fmaf(w1, av.z, a1.z); a1.w = fmaf(w1, av.w, a1.w);
                a2.x = fmaf(w2, av.x, a2.x); a2.y = fmaf(w2, av.y, a2.y);
                a2.z = fmaf(w2, av.z, a2.z); a2.w = fmaf(w2, av.w, a2.w);
                a3.x = fmaf(w3, av.x, a3.x); a3.y = fmaf(w3, av.y, a3.y);
                a3.z = fmaf(w3, av.z, a3.z); a3.w = fmaf(w3, av.w, a3.w);
            }
        }
        {
            float* pr = pred + ip * PRED_STRIDE + jq * 4;
            *(float4*)(pr + 0*64) = a0;
            *(float4*)(pr + 1*64) = a1;
            *(float4*)(pr + 2*64) = a2;
            *(float4*)(pr + 3*64) = a3;
        }
        __syncthreads();

        // ---- finalize y + local LN partials -------------------------------
        float y = 0.f;
        if (t < 256) {
            y = uval;
            const float* pr = pred + c2 * 64 + jj;
#pragma unroll 8
            for (int q = 0; q < 32; q++)
                y += pr[q * PRED_STRIDE];
            float s1 = y, s2 = y*y;
#pragma unroll
            for (int o = 16; o > 0; o >>= 1) {
                s1 += __shfl_xor_sync(0xffffffffu, s1, o);
                s2 += __shfl_xor_sync(0xffffffffu, s2, o);
            }
            if ((t & 31) == 0) { ws[(t>>5)*2] = s1; ws[(t>>5)*2+1] = s2; }
        }
        __syncthreads();
        if (t < 4) {
            pl[t*2+0] = ws[t*4+0] + ws[t*4+2];
            pl[t*2+1] = ws[t*4+1] + ws[t*4+3];
        }
        __syncthreads();
        if (t < 64) {
            const int r = t >> 3, k = t & 7;
            const uint32_t la = pb_base + (uint32_t)(((p*8 + rank)*8 + k) * 4);
            uint32_t ra_;
            asm volatile("mapa.shared::cluster.u32 %0, %1, %2;" : "=r"(ra_) : "r"(la), "r"(r));
            asm volatile("st.shared::cluster.f32 [%0], %1;" :: "r"(ra_), "f"(pl[k]) : "memory");
        }
        float unext = 0.f;
        if (t < 256 && step + 1 < Tz)
            unext = g_u[urow0 + (size_t)(step + 1) * ST];

        asm volatile("barrier.cluster.arrive.aligned;\n" ::: "memory");
        asm volatile("barrier.cluster.wait.aligned;\n" ::: "memory");

        if (t < 256) {
            float q1 = 0.f, q2 = 0.f;
#pragma unroll
            for (int r = 0; r < 8; r++) {
                q1 += pbuf[(p*8 + r)*8 + c2*2 + 0];
                q2 += pbuf[(p*8 + r)*8 + c2*2 + 1];
            }
            const float mean = q1 * (1.f / ST);
            const float var  = q2 * (1.f / ST) - mean * mean;
            const float rstd = rsqrtf(var + EPSC);
            const float sval = (y - mean) * rstd * gj + bj;
            __half hh = __float2half_rn(sval);
            g_sh[urow0 + (size_t)step * ST] = hh;
            g_sl[urow0 + (size_t)step * ST] =
                __float2half_rn(sval - __half2float(hh));
            const uint32_t la = sb_base + (uint32_t)(((((p^1)*4 + c2)*512) + jg0 + jj) * 4);
#pragma unroll
            for (int r = 0; r < 8; r++) {
                uint32_t ra_;
                asm volatile("mapa.shared::cluster.u32 %0, %1, %2;" : "=r"(ra_) : "r"(la), "r"(r));
                asm volatile("st.shared::cluster.f32 [%0], %1;" :: "r"(ra_), "f"(sval) : "memory");
            }
        }
        uval = unext;

        asm volatile("barrier.cluster.arrive.aligned;\n" ::: "memory");
        asm volatile("barrier.cluster.wait.aligned;\n" ::: "memory");
        p ^= 1;
    }
}

// ---------------- launch ------------------------------------------------------
extern "C" void kernel_launch(void* const* d_in, const int* in_sizes, int n_in,
                              void* d_out, int out_size) {
    const float* x      = (const float*)d_in[0];
    const float* W_in   = (const float*)d_in[1];
    const float* b_in   = (const float*)d_in[2];
    const float* conv_w = (const float*)d_in[3];
    const float* conv_b = (const float*)d_in[4];
    const float* bng    = (const float*)d_in[5];
    const float* bnb    = (const float*)d_in[6];
    const float* lng    = (const float*)d_in[7];
    const float* lnb    = (const float*)d_in[8];
    const float* A      = (const float*)d_in[9];
    const float* Bm     = (const float*)d_in[10];
    const float* C      = (const float*)d_in[11];
    float* out = (float*)d_out;

    void *p_xh, *p_vh, *p_vch, *p_u, *p_sh, *p_sl;
    void *p_wt, *p_wk, *p_bm, *p_ct, *p_ub;
    cudaGetSymbolAddress(&p_xh,  g_xh);
    cudaGetSymbolAddress(&p_vh,  g_vh);
    cudaGetSymbolAddress(&p_vch, g_vch);
    cudaGetSymbolAddress(&p_u,   g_u);
    cudaGetSymbolAddress(&p_sh,  g_sh);  cudaGetSymbolAddress(&p_sl,  g_sl);
    cudaGetSymbolAddress(&p_wt,  g_wt);  cudaGetSymbolAddress(&p_wk,  g_wk);
    cudaGetSymbolAddress(&p_bm,  g_bm);  cudaGetSymbolAddress(&p_ct,  g_ct);
    cudaGetSymbolAddress(&p_ub,  g_ubias);

    cudaFuncSetAttribute(k_tgemm, cudaFuncAttributeMaxDynamicSharedMemorySize, SMB_TOTAL);
    cudaFuncSetAttribute(k_recur, cudaFuncAttributeMaxDynamicSharedMemorySize,
                         RC_SMEM_FLOATS * 4);

    // 1) weights + x -> fp16
    k_prep<<<1536, 512>>>(W_in, conv_w, C);
    k_split<<<(M_ROWS*IND)/1024, 256>>>(x);
    // 2) v = silu(x @ W_in^T + b_in) -> fp16 (single)
    k_tgemm<<<dim3(4, 1024), 256, SMB_TOTAL>>>(
        (const __half*)p_xh, nullptr, (const __half*)p_wt,
        b_in, nullptr, (__half*)p_vh, nullptr, IND, ST, 1, 0);
    // 3) vc = conv1d(v) + conv_b -> fp16 (single)
    k_tgemm<<<dim3(4, 1024), 256, SMB_TOTAL>>>(
        (const __half*)p_vh, nullptr, (const __half*)p_wk,
        conv_b, nullptr, (__half*)p_vch, nullptr, 3*ST, ST, 0, 1);
    // 4) BN stats
    k_stats<<<512, 512>>>();
    // 5) fold BN into Bm
    k_finalize<<<1, 512>>>(Bm, bng, bnb);
    // 6) u = vc @ Bm2 + ubias -> fp32 (single-term A)
    k_tgemm<<<dim3(4, 1024), 256, SMB_TOTAL>>>(
        (const __half*)p_vch, nullptr, (const __half*)p_bm,
        (const float*)p_ub, (float*)p_u, nullptr, nullptr, ST, ST, 0, 0);
    // 7) sequential recurrence -> split fp16 states
    k_recur<<<dim3(8, 16), 512, RC_SMEM_FLOATS * 4>>>(A, lng, lnb);
    // 8) y = S @ C  (2-term: output is NOT renormalized afterwards)
    k_tgemm<<<dim3(2, 1024), 256, SMB_TOTAL>>>(
        (const __half*)p_sh, (const __half*)p_sl, (const __half*)p_ct,
        nullptr, out, nullptr, nullptr, ST, OD, 0, 0);
}

// round 13
// speedup vs baseline: 3.8908x; 1.1774x over previous
#include <cuda_runtime.h>
#include <cuda_fp16.h>
#include <math.h>
#include <cstdint>

#define Bz   64
#define Tz   2048
#define IND  256
#define ST   512
#define OD   256
#define M_ROWS (Bz*Tz)   // 131072
#define EPSC 1e-5f

// ---------------- scratch (static device memory) -----------------------------
__device__ __half g_xh[(size_t)M_ROWS*IND];
__device__ __half g_vh[(size_t)M_ROWS*ST];
__device__ __half g_vch[(size_t)M_ROWS*ST];
__device__ float  g_u [(size_t)M_ROWS*ST];
__device__ __half g_sh[(size_t)M_ROWS*ST],  g_sl[(size_t)M_ROWS*ST];
__device__ __half g_wt[ST*IND];      // W_in  Bt[n][k]
__device__ __half g_wk[ST*3*ST];     // conv  Bt[n][tap*512+i]
__device__ __half g_bm[ST*ST];       // BN-folded Bm, Bt[j][i]
__device__ __half g_ct[OD*ST];       // C     Bt[n][k]
__device__ float g_ubias[ST];
__device__ float g_sum[ST];
__device__ float g_sumsq[ST];

__device__ __forceinline__ uint32_t smem_u32(const void* p) {
    return (uint32_t)__cvta_generic_to_shared(p);
}

// ---------------- prep: weights -> fp16 ---------------------------------------
__global__ void k_prep(const float* __restrict__ W_in, const float* __restrict__ conv_w,
                       const float* __restrict__ C) {
    int idx = blockIdx.x * blockDim.x + threadIdx.x;
    if (idx < ST*IND) {
        g_wt[idx] = __float2half_rn(W_in[idx]);
    }
    if (idx < ST*3*ST) {
        int n = idx / (3*ST);
        int rem = idx % (3*ST);
        int tap = rem / ST, i = rem % ST;
        g_wk[idx] = __float2half_rn(conv_w[((size_t)n*ST + i)*3 + tap]);
    }
    if (idx < OD*ST) {
        int n = idx / ST, k = idx % ST;
        g_ct[idx] = __float2half_rn(C[(size_t)k*OD + n]);
    }
    if (idx < ST) { g_sum[idx] = 0.f; g_sumsq[idx] = 0.f; }
}

// x -> fp16 (single digit)
__global__ __launch_bounds__(256)
void k_split(const float* __restrict__ x) {
    const size_t i = ((size_t)blockIdx.x * 256 + threadIdx.x) * 4;
    float4 v = *(const float4*)(x + i);
    __half2 h0 = __floats2half2_rn(v.x, v.y);
    __half2 h1 = __floats2half2_rn(v.z, v.w);
    uint2 hh; hh.x = *(uint32_t*)&h0; hh.y = *(uint32_t*)&h1;
    *(uint2*)(g_xh + i) = hh;
}

// ---------------- mma.sync helpers --------------------------------------------
__device__ __forceinline__ void mma16816(float* c, const uint32_t* a, const uint32_t* b) {
    asm volatile(
        "mma.sync.aligned.m16n8k16.row.col.f32.f16.f16.f32 "
        "{%0,%1,%2,%3}, {%4,%5,%6,%7}, {%8,%9}, {%0,%1,%2,%3};"
        : "+f"(c[0]), "+f"(c[1]), "+f"(c[2]), "+f"(c[3])
        : "r"(a[0]), "r"(a[1]), "r"(a[2]), "r"(a[3]), "r"(b[0]), "r"(b[1]));
}
__device__ __forceinline__ void ldsm4(uint32_t* r, uint32_t addr) {
    asm volatile("ldmatrix.sync.aligned.m8n8.x4.shared.b16 {%0,%1,%2,%3}, [%4];"
                 : "=r"(r[0]), "=r"(r[1]), "=r"(r[2]), "=r"(r[3]) : "r"(addr));
}
__device__ __forceinline__ void cpa16(uint32_t dst, const void* src, bool pred) {
    int sz = pred ? 16 : 0;
    asm volatile("cp.async.cg.shared.global [%0], [%1], 16, %2;"
                 :: "r"(dst), "l"(src), "r"(sz) : "memory");
}
#define CPA_COMMIT() asm volatile("cp.async.commit_group;" ::: "memory")

// ---------------- fp16 warp-MMA GEMM (templated on term count) -----------------
// TWOT=0: A single digit, chunk = {Ah,B}, 3-stage pipeline.
// TWOT=1: A 2-digit,     chunk = {Ah,Al,B}, 2-stage pipeline.
// 128x128 CTA tile, K-chunks of 64; 2 CTAs/SM; warp grid 4x2.
#define SRS 72
#define TILE_HALFS (128*SRS)             // 18432 B
#define SMB_TOTAL (6*TILE_HALFS*2)       // 110592 B (3x2 or 2x3 tiles)

template<int TWOT>
__global__ __launch_bounds__(256, 2)
void k_tgemm(const __half* __restrict__ Ah, const __half* __restrict__ Al,
             const __half* __restrict__ Bp,
             const float* __restrict__ bias, float* __restrict__ outf,
             __half* __restrict__ outh, __half* __restrict__ outl,
             int Kd, int N, int act, int convmode) {
    constexpr int NSTAGE = TWOT ? 2 : 3;
    constexpr int CHUNKH = (2 + TWOT) * TILE_HALFS;
    extern __shared__ __half smem[];
    const int t = threadIdx.x;
    const int w = t >> 5, lane = t & 31;
    const int wm = w >> 1, wn = w & 1;
    const int m0 = blockIdx.y * 128, n0 = blockIdx.x * 128;

    float acc[2][8][4];
#pragma unroll
    for (int i = 0; i < 2; i++)
#pragma unroll
        for (int j = 0; j < 8; j++)
#pragma unroll
            for (int q = 0; q < 4; q++) acc[i][j][q] = 0.f;

    const uint32_t smb = smem_u32(smem);
    const uint32_t aBase = smb +
        (uint32_t)(((wm*32 + (lane & 15)) * SRS + (lane >> 4) * 8) * 2);
    const uint32_t alOff = TILE_HALFS * 2;
    const uint32_t bBase = smb + (1 + TWOT)*TILE_HALFS*2 +
        (uint32_t)(((wn*64 + (lane & 7) + ((lane >> 4) & 1) * 8) * SRS
                    + ((lane >> 3) & 1) * 8) * 2);

    const int sr = t >> 3, sj = t & 7;
    const int nch = Kd >> 6;

    auto stage = [&](int c, int buf) {
        const int k0 = c << 6;
        __half* base = smem + buf * CHUNKH;
        __half* sAh = base;
        __half* sAl = base + TILE_HALFS;
        __half* sB  = base + (1 + TWOT)*TILE_HALFS;
        const int tap = convmode ? (k0 >> 9) : 0;
        const int kl0 = convmode ? (k0 & 511) : k0;
#pragma unroll
        for (int it = 0; it < 4; it++) {
            const int r = sr + it * 32;
            const uint32_t so = (uint32_t)((r * SRS + sj * 8) * 2);
            {
                const size_t goff = (size_t)(n0 + r) * Kd + k0 + sj * 8;
                cpa16(smem_u32(sB) + so, Bp + goff, true);
            }
            {
                const int rg = m0 + r;
                bool pred = true;
                size_t goff;
                if (convmode) {
                    const int tl = (rg & (Tz - 1)) + tap - 1;
                    pred = (tl >= 0) && (tl < Tz);
                    const int rs = pred ? (rg + tap - 1) : rg;
                    goff = (size_t)rs * ST + kl0 + sj * 8;
                } else {
                    goff = (size_t)rg * Kd + k0 + sj * 8;
                }
                cpa16(smem_u32(sAh) + so, Ah + goff, pred);
                if (TWOT) cpa16(smem_u32(sAl) + so, Al + goff, pred);
            }
        }
    };

    uint32_t fah[2][4], fal[2][4], fb[4][4];

    stage(0, 0);
    CPA_COMMIT();
    if (NSTAGE == 3 && nch > 1) { stage(1, 1); CPA_COMMIT(); }

    for (int c = 0; c < nch; c++) {
        if (c + NSTAGE - 1 < nch) {
            stage(c + NSTAGE - 1, (c + NSTAGE - 1) % NSTAGE);
            CPA_COMMIT();
        }
        int pend = nch - 1 - c;
        if (pend > NSTAGE - 1) pend = NSTAGE - 1;
        if (pend >= 2)      asm volatile("cp.async.wait_group 2;" ::: "memory");
        else if (pend == 1) asm volatile("cp.async.wait_group 1;" ::: "memory");
        else                asm volatile("cp.async.wait_group 0;" ::: "memory");
        __syncthreads();

        const uint32_t boff = (uint32_t)((c % NSTAGE) * CHUNKH * 2);
#pragma unroll
        for (int ks = 0; ks < 4; ks++) {
            const uint32_t koff = boff + (uint32_t)(ks * 32);
#pragma unroll
            for (int mi = 0; mi < 2; mi++) {
                ldsm4(fah[mi], aBase + (uint32_t)(mi * 16 * SRS * 2) + koff);
                if (TWOT)
                    ldsm4(fal[mi], aBase + alOff + (uint32_t)(mi * 16 * SRS * 2) + koff);
            }
#pragma unroll
            for (int nb = 0; nb < 4; nb++)
                ldsm4(fb[nb], bBase + (uint32_t)(nb * 16 * SRS * 2) + koff);
#pragma unroll
            for (int mi = 0; mi < 2; mi++)
#pragma unroll
                for (int ni = 0; ni < 8; ni++)
                    mma16816(acc[mi][ni], fah[mi], &fb[ni >> 1][(ni & 1) * 2]);
            if (TWOT) {
#pragma unroll
                for (int mi = 0; mi < 2; mi++)
#pragma unroll
                    for (int ni = 0; ni < 8; ni++)
                        mma16816(acc[mi][ni], fal[mi], &fb[ni >> 1][(ni & 1) * 2]);
            }
        }
        __syncthreads();
    }

    // ---- epilogue -------------------------------------------------------------
    const int g = lane >> 2, tg = lane & 3;
#pragma unroll
    for (int mi = 0; mi < 2; mi++) {
#pragma unroll
        for (int ni = 0; ni < 8; ni++) {
            const int col = n0 + wn*64 + ni*8 + tg*2;
            const float b0 = bias ? bias[col]     : 0.f;
            const float b1 = bias ? bias[col + 1] : 0.f;
#pragma unroll
            for (int half = 0; half < 2; half++) {
                const int row = m0 + wm*32 + mi*16 + g + half*8;
                float v0 = acc[mi][ni][half*2+0] + b0;
                float v1 = acc[mi][ni][half*2+1] + b1;
                if (act == 1) {
                    v0 = v0 / (1.f + expf(-v0));
                    v1 = v1 / (1.f + expf(-v1));
                }
                if (outf) {
                    float2 f2; f2.x = v0; f2.y = v1;
                    *(float2*)(outf + (size_t)row * N + col) = f2;
                }
                if (outh) {
                    __half2 h2 = __floats2half2_rn(v0, v1);
                    *(__half2*)(outh + (size_t)row * N + col) = h2;
                    if (outl) {
                        __half2 l2 = __floats2half2_rn(v0 - __low2float(h2),
                                                       v1 - __high2float(h2));
                        *(__half2*)(outl + (size_t)row * N + col) = l2;
                    }
                }
            }
        }
    }
}

// ---------------- BN stats -----------------------------------------------------
__global__ __launch_bounds__(512)
void k_stats() {
    const int n = threadIdx.x;
    const int rpc = M_ROWS / 512;
    const int r0 = blockIdx.x * rpc;
    float s1 = 0.f, s2 = 0.f;
    for (int r = 0; r < rpc; r++) {
        const size_t o = (size_t)(r0 + r) * ST + n;
        float v = __half2float(g_vch[o]);
        s1 += v; s2 += v * v;
    }
    atomicAdd(&g_sum[n], s1);
    atomicAdd(&g_sumsq[n], s2);
}

__global__ __launch_bounds__(512)
void k_finalize(const float* __restrict__ Bm, const float* __restrict__ bng,
                const float* __restrict__ bnb) {
    __shared__ float sc[ST], sh[ST];
    const int j = threadIdx.x;
    float mu  = g_sum[j]   * (1.f / M_ROWS);
    float var = g_sumsq[j] * (1.f / M_ROWS) - mu * mu;
    float inv = rsqrtf(var + EPSC);
    float s   = bng[j] * inv;
    sc[j] = s;
    sh[j] = bnb[j] - mu * s;
    __syncthreads();
    float ub = 0.f;
    for (int i = 0; i < ST; i++) {
        float bmv = Bm[(size_t)i * ST + j];
        g_bm[(size_t)j * ST + i] = __float2half_rn(sc[i] * bmv);
        ub += sh[i] * bmv;
    }
    g_ubias[j] = ub;
}

// ---------------- cluster recurrence: folded LN, 1 cluster barrier/step --------
// sbuf holds RAW pre-LN state r; A' = gamma[i]*A[i][j] in smem.
// r_{t+1} = rstd*(r_t@A') - rstd*mean*colsum + cbias + u.
// Normalized s_t written one step later (stats arrive with next barrier).
#define PRED_STRIDE 260
#define RC_OFF_SBUF 32768              // [2][4][512]
#define RC_OFF_PBUF 36864              // [2][8][8]
#define RC_OFF_PRED 36992              // [32][260]
#define RC_OFF_WS   (RC_OFF_PRED + 32*PRED_STRIDE)
#define RC_OFF_CS   (RC_OFF_WS + 16)                // colsum [64]
#define RC_OFF_CB   (RC_OFF_CS + 64)                // cbias  [64]
#define RC_SMEM_FLOATS (RC_OFF_CB + 64 + 8)
__global__ __launch_bounds__(512, 1) __cluster_dims__(8, 1, 1)
void k_recur(const float* __restrict__ A, const float* __restrict__ lng,
             const float* __restrict__ lnb) {
    extern __shared__ float sm[];
    float* Atile  = sm;                  // [512][64] = gamma[i]*A[i][jg0+j]
    float* sbuf   = sm + RC_OFF_SBUF;
    float* pbuf   = sm + RC_OFF_PBUF;
    float* pred   = sm + RC_OFF_PRED;
    float* ws     = sm + RC_OFF_WS;
    float* colsum = sm + RC_OFF_CS;
    float* cbias  = sm + RC_OFF_CB;

    const int t    = threadIdx.x;
    const int rank = blockIdx.x;
    const int grp  = blockIdx.y;
    const int jg0  = rank * 64;

    for (int idx = t; idx < 512 * 16; idx += 512) {
        int i  = idx >> 4;
        int jv = (idx & 15) << 2;
        float gi = lng[i];
        float4 a = *(const float4*)(A + (size_t)i*ST + jg0 + jv);
        a.x *= gi; a.y *= gi; a.z *= gi; a.w *= gi;
        *(float4*)&Atile[i*64 + jv] = a;
    }
    for (int idx = t; idx < 4*512; idx += 512) sbuf[idx] = 0.f;
    __syncthreads();
    if (t < 64) {                       // colsum[j] = sum_i A'[i][j]
        float cs = 0.f;
        for (int i = 0; i < 512; i++) cs += Atile[i*64 + t];
        colsum[t] = cs;
    } else if (t < 128) {               // cbias[j] = sum_i beta[i]*A[i][j]
        const int jj2 = t - 64;
        float cb = 0.f;
        for (int i = 0; i < 512; i++)
            cb += lnb[i] * A[(size_t)i*ST + jg0 + jj2];
        cbias[jj2] = cb;
    }

    const int ip = t >> 4;         // 0..31, i-slice of 16
    const int jq = t & 15;         // 0..15, j quad
    const int c2 = t >> 6;         // finalize: chain (t<256)
    const int jj = t & 63;

    float gj = 0.f, bj = 0.f;
    size_t urow0 = 0;
    if (t < 256) {
        gj = lng[jg0 + jj];
        bj = lnb[jg0 + jj];
        const int chain = grp * 4 + c2;
        urow0 = (size_t)chain * Tz * ST + jg0 + jj;
    }

    const uint32_t sb_base = smem_u32(sbuf);
    const uint32_t pb_base = smem_u32(pbuf);

    __syncthreads();
    asm volatile("barrier.cluster.arrive.aligned;\n" ::: "memory");
    asm volatile("barrier.cluster.wait.aligned;\n" ::: "memory");

    int p = 0;
    float uval  = (t < 256) ? g_u[urow0] : 0.f;
    float yprev = 0.f;

    for (int step = 0; step < Tz; step++) {
        // ---- matvec on raw r (4-chain A-reuse) ----------------------------
        const float* Arow = Atile + (ip*16)*64 + jq*4;
        const float* s0p = sbuf + (p*4 + 0)*512 + ip*16;
        const float* s1p = s0p + 512;
        const float* s2p = s1p + 512;
        const float* s3p = s2p + 512;
        float4 a0 = make_float4(0,0,0,0), a1 = a0, a2 = a0, a3 = a0;
#pragma unroll
        for (int ii = 0; ii < 16; ii += 4) {
            float4 sA = *(const float4*)(s0p + ii);
            float4 sB_ = *(const float4*)(s1p + ii);
            float4 sC = *(const float4*)(s2p + ii);
            float4 sD = *(const float4*)(s3p + ii);
#pragma unroll
            for (int q2 = 0; q2 < 4; q2++) {
                float4 av = *(const float4*)(Arow + (ii + q2) * 64);
                const float w0 = (&sA.x)[q2], w1 = (&sB_.x)[q2];
                const float w2 = (&sC.x)[q2], w3 = (&sD.x)[q2];
                a0.x = fmaf(w0, av.x, a0.x); a0.y = fmaf(w0, av.y, a0.y);
                a0.z = fmaf(w0, av.z, a0.z); a0.w = fmaf(w0, av.w, a0.w);
                a1.x = fmaf(w1, av.x, a1.x); a1.y = fmaf(w1, av.y, a1.y);
                a1.z = fmaf(w1, av.z, a1.z); a1.w = fmaf(w1, av.w, a1.w);
                a2.x = fmaf(w2, av.x, a2.x); a2.y = fmaf(w2, av.y, a2.y);
                a2.z = fmaf(w2, av.z, a2.z); a2.w = fmaf(w2, av.w, a2.w);
                a3.x = fmaf(w3, av.x, a3.x); a3.y = fmaf(w3, av.y, a3.y);
                a3.z = fmaf(w3, av.z, a3.z); a3.w = fmaf(w3, av.w, a3.w);
            }
        }
        {
            float* pr = pred + ip * PRED_STRIDE + jq * 4;
            *(float4*)(pr + 0*64) = a0;
            *(float4*)(pr + 1*64) = a1;
            *(float4*)(pr + 2*64) = a2;
            *(float4*)(pr + 3*64) = a3;
        }
        __syncthreads();

        // ---- finalize: stats of r_{t-1}, write s_{t-1}, compute r_t --------
        float ynew = 0.f;
        if (t < 256) {
            float alpha = 0.f, beta = 0.f, cw = 0.f;
            if (step > 0) {
                float q1 = 0.f, q2s = 0.f;
#pragma unroll
                for (int r = 0; r < 8; r++) {
                    q1  += pbuf[(p*8 + r)*8 + c2*2 + 0];
                    q2s += pbuf[(p*8 + r)*8 + c2*2 + 1];
                }
                const float mean = q1 * (1.f / ST);
                const float var  = q2s * (1.f / ST) - mean * mean;
                const float rstd = rsqrtf(var + EPSC);
                alpha = rstd; beta = -rstd * mean; cw = 1.f;
                // write normalized s_{step-1}
                const float sv = (yprev - mean) * rstd * gj + bj;
                __half hh = __float2half_rn(sv);
                g_sh[urow0 + (size_t)(step-1) * ST] = hh;
                g_sl[urow0 + (size_t)(step-1) * ST] =
                    __float2half_rn(sv - __half2float(hh));
            }
            float acc = 0.f;
            const float* pr = pred + c2 * 64 + jj;
#pragma unroll 8
            for (int q = 0; q < 32; q++)
                acc += pr[q * PRED_STRIDE];
            ynew = fmaf(alpha, acc, fmaf(beta, colsum[jj], fmaf(cw, cbias[jj], uval)));
            float s1 = ynew, s2 = ynew * ynew;
#pragma unroll
            for (int o = 16; o > 0; o >>= 1) {
                s1 += __shfl_xor_sync(0xffffffffu, s1, o);
                s2 += __shfl_xor_sync(0xffffffffu, s2, o);
            }
            if ((t & 31) == 0) { ws[(t>>5)*2] = s1; ws[(t>>5)*2+1] = s2; }
        }
        __syncthreads();

        // ---- broadcast raw r_t + its partials to all 8 CTAs ----------------
        if (t < 64) {
            const int r = t >> 3, k = t & 7;
            const int cc = k >> 1, b = k & 1;
            const float val = ws[cc*4 + b] + ws[cc*4 + b + 2];
            const uint32_t la = pb_base + (uint32_t)((((p^1)*8 + rank)*8 + k) * 4);
            uint32_t ra_;
            asm volatile("mapa.shared::cluster.u32 %0, %1, %2;" : "=r"(ra_) : "r"(la), "r"(r));
            asm volatile("st.shared::cluster.f32 [%0], %1;" :: "r"(ra_), "f"(val) : "memory");
        }
        if (t < 256) {
            const uint32_t la = sb_base + (uint32_t)(((((p^1)*4 + c2)*512) + jg0 + jj) * 4);
#pragma unroll
            for (int r = 0; r < 8; r++) {
                uint32_t ra_;
                asm volatile("mapa.shared::cluster.u32 %0, %1, %2;" : "=r"(ra_) : "r"(la), "r"(r));
                asm volatile("st.shared::cluster.f32 [%0], %1;" :: "r"(ra_), "f"(ynew) : "memory");
            }
        }
        float unext = 0.f;
        if (t < 256 && step + 1 < Tz)
            unext = g_u[urow0 + (size_t)(step + 1) * ST];

        asm volatile("barrier.cluster.arrive.aligned;\n" ::: "memory");
        asm volatile("barrier.cluster.wait.aligned;\n" ::: "memory");

        yprev = ynew;
        uval  = unext;
        p ^= 1;
    }

    // ---- tail: write s_{Tz-1} using last broadcast stats -----------------------
    if (t < 256) {
        float q1 = 0.f, q2s = 0.f;
#pragma unroll
        for (int r = 0; r < 8; r++) {
            q1  += pbuf[(p*8 + r)*8 + c2*2 + 0];
            q2s += pbuf[(p*8 + r)*8 + c2*2 + 1];
        }
        const float mean = q1 * (1.f / ST);
        const float var  = q2s * (1.f / ST) - mean * mean;
        const float rstd = rsqrtf(var + EPSC);
        const float sv = (yprev - mean) * rstd * gj + bj;
        __half hh = __float2half_rn(sv);
        g_sh[urow0 + (size_t)(Tz-1) * ST] = hh;
        g_sl[urow0 + (size_t)(Tz-1) * ST] =
            __float2half_rn(sv - __half2float(hh));
    }
}

// ---------------- launch ------------------------------------------------------
extern "C" void kernel_launch(void* const* d_in, const int* in_sizes, int n_in,
                              void* d_out, int out_size) {
    const float* x      = (const float*)d_in[0];
    const float* W_in   = (const float*)d_in[1];
    const float* b_in   = (const float*)d_in[2];
    const float* conv_w = (const float*)d_in[3];
    const float* conv_b = (const float*)d_in[4];
    const float* bng    = (const float*)d_in[5];
    const float* bnb    = (const float*)d_in[6];
    const float* lng    = (const float*)d_in[7];
    const float* lnb    = (const float*)d_in[8];
    const float* A      = (const float*)d_in[9];
    const float* Bm     = (const float*)d_in[10];
    const float* C      = (const float*)d_in[11];
    float* out = (float*)d_out;

    void *p_xh, *p_vh, *p_vch, *p_u, *p_sh, *p_sl;
    void *p_wt, *p_wk, *p_bm, *p_ct, *p_ub;
    cudaGetSymbolAddress(&p_xh,  g_xh);
    cudaGetSymbolAddress(&p_vh,  g_vh);
    cudaGetSymbolAddress(&p_vch, g_vch);
    cudaGetSymbolAddress(&p_u,   g_u);
    cudaGetSymbolAddress(&p_sh,  g_sh);  cudaGetSymbolAddress(&p_sl,  g_sl);
    cudaGetSymbolAddress(&p_wt,  g_wt);  cudaGetSymbolAddress(&p_wk,  g_wk);
    cudaGetSymbolAddress(&p_bm,  g_bm);  cudaGetSymbolAddress(&p_ct,  g_ct);
    cudaGetSymbolAddress(&p_ub,  g_ubias);

    cudaFuncSetAttribute(k_tgemm<0>, cudaFuncAttributeMaxDynamicSharedMemorySize, SMB_TOTAL);
    cudaFuncSetAttribute(k_tgemm<1>, cudaFuncAttributeMaxDynamicSharedMemorySize, SMB_TOTAL);
    cudaFuncSetAttribute(k_recur, cudaFuncAttributeMaxDynamicSharedMemorySize,
                         RC_SMEM_FLOATS * 4);

    // 1) weights + x -> fp16
    k_prep<<<1536, 512>>>(W_in, conv_w, C);
    k_split<<<(M_ROWS*IND)/1024, 256>>>(x);
    // 2) v = silu(x @ W_in^T + b_in) -> fp16
    k_tgemm<0><<<dim3(4, 1024), 256, SMB_TOTAL>>>(
        (const __half*)p_xh, nullptr, (const __half*)p_wt,
        b_in, nullptr, (__half*)p_vh, nullptr, IND, ST, 1, 0);
    // 3) vc = conv1d(v) + conv_b -> fp16
    k_tgemm<0><<<dim3(4, 1024), 256, SMB_TOTAL>>>(
        (const __half*)p_vh, nullptr, (const __half*)p_wk,
        conv_b, nullptr, (__half*)p_vch, nullptr, 3*ST, ST, 0, 1);
    // 4) BN stats
    k_stats<<<512, 512>>>();
    // 5) fold BN into Bm
    k_finalize<<<1, 512>>>(Bm, bng, bnb);
    // 6) u = vc @ Bm2 + ubias -> fp32
    k_tgemm<0><<<dim3(4, 1024), 256, SMB_TOTAL>>>(
        (const __half*)p_vch, nullptr, (const __half*)p_bm,
        (const float*)p_ub, (float*)p_u, nullptr, nullptr, ST, ST, 0, 0);
    // 7) recurrence (folded LN, 1 cluster barrier/step) -> split fp16 states
    k_recur<<<dim3(8, 16), 512, RC_SMEM_FLOATS * 4>>>(A, lng, lnb);
    // 8) y = S @ C (2-term)
    k_tgemm<1><<<dim3(2, 1024), 256, SMB_TOTAL>>>(
        (const __half*)p_sh, (const __half*)p_sl, (const __half*)p_ct,
        nullptr, out, nullptr, nullptr, ST, OD, 0, 0);
}

// round 14
// speedup vs baseline: 3.9464x; 1.0143x over previous
#include <cuda_runtime.h>
#include <cuda_fp16.h>
#include <math.h>
#include <cstdint>

#define Bz   64
#define Tz   2048
#define IND  256
#define ST   512
#define OD   256
#define M_ROWS (Bz*Tz)   // 131072
#define EPSC 1e-5f

// ---------------- scratch (static device memory) -----------------------------
__device__ __half g_xh[(size_t)M_ROWS*IND];
__device__ __half g_vh[(size_t)M_ROWS*ST];
__device__ __half g_vch[(size_t)M_ROWS*ST];
__device__ float  g_u [(size_t)M_ROWS*ST];
__device__ __half g_sh[(size_t)M_ROWS*ST];
__device__ __half g_wt[ST*IND];      // W_in  Bt[n][k]
__device__ __half g_wk[ST*3*ST];     // conv  Bt[n][tap*512+i]
__device__ __half g_bm[ST*ST];       // BN-folded Bm, Bt[j][i]
__device__ __half g_ct[OD*ST];       // C     Bt[n][k]
__device__ float g_ubias[ST];
__device__ float g_sum[ST];
__device__ float g_sumsq[ST];

__device__ __forceinline__ uint32_t smem_u32(const void* p) {
    return (uint32_t)__cvta_generic_to_shared(p);
}

// ---------------- prep: weights -> fp16 ---------------------------------------
__global__ void k_prep(const float* __restrict__ W_in, const float* __restrict__ conv_w,
                       const float* __restrict__ C) {
    int idx = blockIdx.x * blockDim.x + threadIdx.x;
    if (idx < ST*IND) {
        g_wt[idx] = __float2half_rn(W_in[idx]);
    }
    if (idx < ST*3*ST) {
        int n = idx / (3*ST);
        int rem = idx % (3*ST);
        int tap = rem / ST, i = rem % ST;
        g_wk[idx] = __float2half_rn(conv_w[((size_t)n*ST + i)*3 + tap]);
    }
    if (idx < OD*ST) {
        int n = idx / ST, k = idx % ST;
        g_ct[idx] = __float2half_rn(C[(size_t)k*OD + n]);
    }
    if (idx < ST) { g_sum[idx] = 0.f; g_sumsq[idx] = 0.f; }
}

// x -> fp16
__global__ __launch_bounds__(256)
void k_split(const float* __restrict__ x) {
    const size_t i = ((size_t)blockIdx.x * 256 + threadIdx.x) * 4;
    float4 v = *(const float4*)(x + i);
    __half2 h0 = __floats2half2_rn(v.x, v.y);
    __half2 h1 = __floats2half2_rn(v.z, v.w);
    uint2 hh; hh.x = *(uint32_t*)&h0; hh.y = *(uint32_t*)&h1;
    *(uint2*)(g_xh + i) = hh;
}

// ---------------- mma.sync helpers --------------------------------------------
__device__ __forceinline__ void mma16816(float* c, const uint32_t* a, const uint32_t* b) {
    asm volatile(
        "mma.sync.aligned.m16n8k16.row.col.f32.f16.f16.f32 "
        "{%0,%1,%2,%3}, {%4,%5,%6,%7}, {%8,%9}, {%0,%1,%2,%3};"
        : "+f"(c[0]), "+f"(c[1]), "+f"(c[2]), "+f"(c[3])
        : "r"(a[0]), "r"(a[1]), "r"(a[2]), "r"(a[3]), "r"(b[0]), "r"(b[1]));
}
__device__ __forceinline__ void ldsm4(uint32_t* r, uint32_t addr) {
    asm volatile("ldmatrix.sync.aligned.m8n8.x4.shared.b16 {%0,%1,%2,%3}, [%4];"
                 : "=r"(r[0]), "=r"(r[1]), "=r"(r[2]), "=r"(r[3]) : "r"(addr));
}
__device__ __forceinline__ void cpa16(uint32_t dst, const void* src, bool pred) {
    int sz = pred ? 16 : 0;
    asm volatile("cp.async.cg.shared.global [%0], [%1], 16, %2;"
                 :: "r"(dst), "l"(src), "r"(sz) : "memory");
}
#define CPA_COMMIT() asm volatile("cp.async.commit_group;" ::: "memory")

// ---------------- fp16 warp-MMA GEMM (single-term A) ---------------------------
// 128x128 CTA tile, K-chunks of 64, 3-stage cp.async, ONE syncthreads/chunk;
// 2 CTAs/SM; warp grid 4x2 (32-row x 64-col warp tiles).
#define SRS 72
#define TILE_HALFS (128*SRS)             // 18432 B
#define CHUNKH (2*TILE_HALFS)            // A, B
#define SMB_TOTAL (3*CHUNKH*2)           // 110592 B

__global__ __launch_bounds__(256, 2)
void k_tgemm(const __half* __restrict__ Ah, const __half* __restrict__ Bp,
             const float* __restrict__ bias, float* __restrict__ outf,
             __half* __restrict__ outh,
             int Kd, int N, int act, int convmode) {
    extern __shared__ __half smem[];
    const int t = threadIdx.x;
    const int w = t >> 5, lane = t & 31;
    const int wm = w >> 1, wn = w & 1;
    const int m0 = blockIdx.y * 128, n0 = blockIdx.x * 128;

    float acc[2][8][4];
#pragma unroll
    for (int i = 0; i < 2; i++)
#pragma unroll
        for (int j = 0; j < 8; j++)
#pragma unroll
            for (int q = 0; q < 4; q++) acc[i][j][q] = 0.f;

    const uint32_t smb = smem_u32(smem);
    const uint32_t aBase = smb +
        (uint32_t)(((wm*32 + (lane & 15)) * SRS + (lane >> 4) * 8) * 2);
    const uint32_t bBase = smb + TILE_HALFS*2 +
        (uint32_t)(((wn*64 + (lane & 7) + ((lane >> 4) & 1) * 8) * SRS
                    + ((lane >> 3) & 1) * 8) * 2);

    const int sr = t >> 3, sj = t & 7;
    const int nch = Kd >> 6;

    auto stage = [&](int c, int buf) {
        const int k0 = c << 6;
        __half* base = smem + buf * CHUNKH;
        __half* sAh = base;
        __half* sB  = base + TILE_HALFS;
        const int tap = convmode ? (k0 >> 9) : 0;
        const int kl0 = convmode ? (k0 & 511) : k0;
#pragma unroll
        for (int it = 0; it < 4; it++) {
            const int r = sr + it * 32;
            const uint32_t so = (uint32_t)((r * SRS + sj * 8) * 2);
            {
                const size_t goff = (size_t)(n0 + r) * Kd + k0 + sj * 8;
                cpa16(smem_u32(sB) + so, Bp + goff, true);
            }
            {
                const int rg = m0 + r;
                bool pred = true;
                size_t goff;
                if (convmode) {
                    const int tl = (rg & (Tz - 1)) + tap - 1;
                    pred = (tl >= 0) && (tl < Tz);
                    const int rs = pred ? (rg + tap - 1) : rg;
                    goff = (size_t)rs * ST + kl0 + sj * 8;
                } else {
                    goff = (size_t)rg * Kd + k0 + sj * 8;
                }
                cpa16(smem_u32(sAh) + so, Ah + goff, pred);
            }
        }
    };

    uint32_t fah[2][4], fb[4][4];

    stage(0, 0);
    CPA_COMMIT();
    if (nch > 1) { stage(1, 1); CPA_COMMIT(); }

    for (int c = 0; c < nch; c++) {
        // wait for chunk c (allow 1 later group in flight)
        if (c < nch - 1) asm volatile("cp.async.wait_group 1;" ::: "memory");
        else             asm volatile("cp.async.wait_group 0;" ::: "memory");
        __syncthreads();
        // prefetch chunk c+2 into buf (c+2)%3 (last read by chunk c-1, done pre-sync)
        if (c + 2 < nch) { stage(c + 2, (c + 2) % 3); CPA_COMMIT(); }

        const uint32_t boff = (uint32_t)((c % 3) * CHUNKH * 2);
#pragma unroll
        for (int ks = 0; ks < 4; ks++) {
            const uint32_t koff = boff + (uint32_t)(ks * 32);
#pragma unroll
            for (int mi = 0; mi < 2; mi++)
                ldsm4(fah[mi], aBase + (uint32_t)(mi * 16 * SRS * 2) + koff);
#pragma unroll
            for (int nb = 0; nb < 4; nb++)
                ldsm4(fb[nb], bBase + (uint32_t)(nb * 16 * SRS * 2) + koff);
#pragma unroll
            for (int mi = 0; mi < 2; mi++)
#pragma unroll
                for (int ni = 0; ni < 8; ni++)
                    mma16816(acc[mi][ni], fah[mi], &fb[ni >> 1][(ni & 1) * 2]);
        }
    }

    // ---- epilogue -------------------------------------------------------------
    const int g = lane >> 2, tg = lane & 3;
#pragma unroll
    for (int mi = 0; mi < 2; mi++) {
#pragma unroll
        for (int ni = 0; ni < 8; ni++) {
            const int col = n0 + wn*64 + ni*8 + tg*2;
            const float b0 = bias ? bias[col]     : 0.f;
            const float b1 = bias ? bias[col + 1] : 0.f;
#pragma unroll
            for (int half = 0; half < 2; half++) {
                const int row = m0 + wm*32 + mi*16 + g + half*8;
                float v0 = acc[mi][ni][half*2+0] + b0;
                float v1 = acc[mi][ni][half*2+1] + b1;
                if (act == 1) {
                    v0 = v0 / (1.f + expf(-v0));
                    v1 = v1 / (1.f + expf(-v1));
                }
                if (outf) {
                    float2 f2; f2.x = v0; f2.y = v1;
                    *(float2*)(outf + (size_t)row * N + col) = f2;
                }
                if (outh) {
                    __half2 h2 = __floats2half2_rn(v0, v1);
                    *(__half2*)(outh + (size_t)row * N + col) = h2;
                }
            }
        }
    }
}

// ---------------- BN stats -----------------------------------------------------
__global__ __launch_bounds__(512)
void k_stats() {
    const int n = threadIdx.x;
    const int rpc = M_ROWS / 512;
    const int r0 = blockIdx.x * rpc;
    float s1 = 0.f, s2 = 0.f;
    for (int r = 0; r < rpc; r++) {
        const size_t o = (size_t)(r0 + r) * ST + n;
        float v = __half2float(g_vch[o]);
        s1 += v; s2 += v * v;
    }
    atomicAdd(&g_sum[n], s1);
    atomicAdd(&g_sumsq[n], s2);
}

__global__ __launch_bounds__(512)
void k_finalize(const float* __restrict__ Bm, const float* __restrict__ bng,
                const float* __restrict__ bnb) {
    __shared__ float sc[ST], sh[ST];
    const int j = threadIdx.x;
    float mu  = g_sum[j]   * (1.f / M_ROWS);
    float var = g_sumsq[j] * (1.f / M_ROWS) - mu * mu;
    float inv = rsqrtf(var + EPSC);
    float s   = bng[j] * inv;
    sc[j] = s;
    sh[j] = bnb[j] - mu * s;
    __syncthreads();
    float ub = 0.f;
    for (int i = 0; i < ST; i++) {
        float bmv = Bm[(size_t)i * ST + j];
        g_bm[(size_t)j * ST + i] = __float2half_rn(sc[i] * bmv);
        ub += sh[i] * bmv;
    }
    g_ubias[j] = ub;
}

// ---------------- cluster recurrence: folded LN, 1 cluster barrier/step --------
#define PRED_STRIDE 260
#define RC_OFF_SBUF 32768              // [2][4][512]
#define RC_OFF_PBUF 36864              // [2][8][8]
#define RC_OFF_PRED 36992              // [32][260]
#define RC_OFF_WS   (RC_OFF_PRED + 32*PRED_STRIDE)
#define RC_OFF_CS   (RC_OFF_WS + 16)                // colsum [64]
#define RC_OFF_CB   (RC_OFF_CS + 64)                // cbias  [64]
#define RC_SMEM_FLOATS (RC_OFF_CB + 64 + 8)
__global__ __launch_bounds__(512, 1) __cluster_dims__(8, 1, 1)
void k_recur(const float* __restrict__ A, const float* __restrict__ lng,
             const float* __restrict__ lnb) {
    extern __shared__ float sm[];
    float* Atile  = sm;                  // [512][64] = gamma[i]*A[i][jg0+j]
    float* sbuf   = sm + RC_OFF_SBUF;
    float* pbuf   = sm + RC_OFF_PBUF;
    float* pred   = sm + RC_OFF_PRED;
    float* ws     = sm + RC_OFF_WS;
    float* colsum = sm + RC_OFF_CS;
    float* cbias  = sm + RC_OFF_CB;

    const int t    = threadIdx.x;
    const int rank = blockIdx.x;
    const int grp  = blockIdx.y;
    const int jg0  = rank * 64;

    for (int idx = t; idx < 512 * 16; idx += 512) {
        int i  = idx >> 4;
        int jv = (idx & 15) << 2;
        float gi = lng[i];
        float4 a = *(const float4*)(A + (size_t)i*ST + jg0 + jv);
        a.x *= gi; a.y *= gi; a.z *= gi; a.w *= gi;
        *(float4*)&Atile[i*64 + jv] = a;
    }
    for (int idx = t; idx < 4*512; idx += 512) sbuf[idx] = 0.f;
    __syncthreads();
    if (t < 64) {
        float cs = 0.f;
        for (int i = 0; i < 512; i++) cs += Atile[i*64 + t];
        colsum[t] = cs;
    } else if (t < 128) {
        const int jj2 = t - 64;
        float cb = 0.f;
        for (int i = 0; i < 512; i++)
            cb += lnb[i] * A[(size_t)i*ST + jg0 + jj2];
        cbias[jj2] = cb;
    }

    const int ip = t >> 4;
    const int jq = t & 15;
    const int c2 = t >> 6;
    const int jj = t & 63;

    float gj = 0.f, bj = 0.f;
    size_t urow0 = 0;
    if (t < 256) {
        gj = lng[jg0 + jj];
        bj = lnb[jg0 + jj];
        const int chain = grp * 4 + c2;
        urow0 = (size_t)chain * Tz * ST + jg0 + jj;
    }

    const uint32_t sb_base = smem_u32(sbuf);
    const uint32_t pb_base = smem_u32(pbuf);

    __syncthreads();
    asm volatile("barrier.cluster.arrive.aligned;\n" ::: "memory");
    asm volatile("barrier.cluster.wait.aligned;\n" ::: "memory");

    int p = 0;
    float uval  = (t < 256) ? g_u[urow0] : 0.f;
    float yprev = 0.f;

    for (int step = 0; step < Tz; step++) {
        const float* Arow = Atile + (ip*16)*64 + jq*4;
        const float* s0p = sbuf + (p*4 + 0)*512 + ip*16;
        const float* s1p = s0p + 512;
        const float* s2p = s1p + 512;
        const float* s3p = s2p + 512;
        float4 a0 = make_float4(0,0,0,0), a1 = a0, a2 = a0, a3 = a0;
#pragma unroll
        for (int ii = 0; ii < 16; ii += 4) {
            float4 sA = *(const float4*)(s0p + ii);
            float4 sB_ = *(const float4*)(s1p + ii);
            float4 sC = *(const float4*)(s2p + ii);
            float4 sD = *(const float4*)(s3p + ii);
#pragma unroll
            for (int q2 = 0; q2 < 4; q2++) {
                float4 av = *(const float4*)(Arow + (ii + q2) * 64);
                const float w0 = (&sA.x)[q2], w1 = (&sB_.x)[q2];
                const float w2 = (&sC.x)[q2], w3 = (&sD.x)[q2];
                a0.x = fmaf(w0, av.x, a0.x); a0.y = fmaf(w0, av.y, a0.y);
                a0.z = fmaf(w0, av.z, a0.z); a0.w = fmaf(w0, av.w, a0.w);
                a1.x = fmaf(w1, av.x, a1.x); a1.y = fmaf(w1, av.y, a1.y);
                a1.z = fmaf(w1, av.z, a1.z); a1.w = fmaf(w1, av.w, a1.w);
                a2.x = fmaf(w2, av.x, a2.x); a2.y = fmaf(w2, av.y, a2.y);
                a2.z = fmaf(w2, av.z, a2.z); a2.w = fmaf(w2, av.w, a2.w);
                a3.x = fmaf(w3, av.x, a3.x); a3.y = fmaf(w3, av.y, a3.y);
                a3.z = fmaf(w3, av.z, a3.z); a3.w = fmaf(w3, av.w, a3.w);
            }
        }
        {
            float* pr = pred + ip * PRED_STRIDE + jq * 4;
            *(float4*)(pr + 0*64) = a0;
            *(float4*)(pr + 1*64) = a1;
            *(float4*)(pr + 2*64) = a2;
            *(float4*)(pr + 3*64) = a3;
        }
        __syncthreads();

        float ynew = 0.f;
        if (t < 256) {
            float alpha = 0.f, beta = 0.f, cw = 0.f;
            if (step > 0) {
                float q1 = 0.f, q2s = 0.f;
#pragma unroll
                for (int r = 0; r < 8; r++) {
                    q1  += pbuf[(p*8 + r)*8 + c2*2 + 0];
                    q2s += pbuf[(p*8 + r)*8 + c2*2 + 1];
                }
                const float mean = q1 * (1.f / ST);
                const float var  = q2s * (1.f / ST) - mean * mean;
                const float rstd = rsqrtf(var + EPSC);
                alpha = rstd; beta = -rstd * mean; cw = 1.f;
                const float sv = (yprev - mean) * rstd * gj + bj;
                g_sh[urow0 + (size_t)(step-1) * ST] = __float2half_rn(sv);
            }
            float acc = 0.f;
            const float* pr = pred + c2 * 64 + jj;
#pragma unroll 8
            for (int q = 0; q < 32; q++)
                acc += pr[q * PRED_STRIDE];
            ynew = fmaf(alpha, acc, fmaf(beta, colsum[jj], fmaf(cw, cbias[jj], uval)));
            float s1 = ynew, s2 = ynew * ynew;
#pragma unroll
            for (int o = 16; o > 0; o >>= 1) {
                s1 += __shfl_xor_sync(0xffffffffu, s1, o);
                s2 += __shfl_xor_sync(0xffffffffu, s2, o);
            }
            if ((t & 31) == 0) { ws[(t>>5)*2] = s1; ws[(t>>5)*2+1] = s2; }
        }
        __syncthreads();

        if (t < 64) {
            const int r = t >> 3, k = t & 7;
            const int cc = k >> 1, b = k & 1;
            const float val = ws[cc*4 + b] + ws[cc*4 + b + 2];
            const uint32_t la = pb_base + (uint32_t)((((p^1)*8 + rank)*8 + k) * 4);
            uint32_t ra_;
            asm volatile("mapa.shared::cluster.u32 %0, %1, %2;" : "=r"(ra_) : "r"(la), "r"(r));
            asm volatile("st.shared::cluster.f32 [%0], %1;" :: "r"(ra_), "f"(val) : "memory");
        }
        if (t < 256) {
            const uint32_t la = sb_base + (uint32_t)(((((p^1)*4 + c2)*512) + jg0 + jj) * 4);
#pragma unroll
            for (int r = 0; r < 8; r++) {
                uint32_t ra_;
                asm volatile("mapa.shared::cluster.u32 %0, %1, %2;" : "=r"(ra_) : "r"(la), "r"(r));
                asm volatile("st.shared::cluster.f32 [%0], %1;" :: "r"(ra_), "f"(ynew) : "memory");
            }
        }
        float unext = 0.f;
        if (t < 256 && step + 1 < Tz)
            unext = g_u[urow0 + (size_t)(step + 1) * ST];

        asm volatile("barrier.cluster.arrive.aligned;\n" ::: "memory");
        asm volatile("barrier.cluster.wait.aligned;\n" ::: "memory");

        yprev = ynew;
        uval  = unext;
        p ^= 1;
    }

    // tail: write s_{Tz-1}
    if (t < 256) {
        float q1 = 0.f, q2s = 0.f;
#pragma unroll
        for (int r = 0; r < 8; r++) {
            q1  += pbuf[(p*8 + r)*8 + c2*2 + 0];
            q2s += pbuf[(p*8 + r)*8 + c2*2 + 1];
        }
        const float mean = q1 * (1.f / ST);
        const float var  = q2s * (1.f / ST) - mean * mean;
        const float rstd = rsqrtf(var + EPSC);
        const float sv = (yprev - mean) * rstd * gj + bj;
        g_sh[urow0 + (size_t)(Tz-1) * ST] = __float2half_rn(sv);
    }
}

// ---------------- launch ------------------------------------------------------
extern "C" void kernel_launch(void* const* d_in, const int* in_sizes, int n_in,
                              void* d_out, int out_size) {
    const float* x      = (const float*)d_in[0];
    const float* W_in   = (const float*)d_in[1];
    const float* b_in   = (const float*)d_in[2];
    const float* conv_w = (const float*)d_in[3];
    const float* conv_b = (const float*)d_in[4];
    const float* bng    = (const float*)d_in[5];
    const float* bnb    = (const float*)d_in[6];
    const float* lng    = (const float*)d_in[7];
    const float* lnb    = (const float*)d_in[8];
    const float* A      = (const float*)d_in[9];
    const float* Bm     = (const float*)d_in[10];
    const float* C      = (const float*)d_in[11];
    float* out = (float*)d_out;

    void *p_xh, *p_vh, *p_vch, *p_u, *p_sh;
    void *p_wt, *p_wk, *p_bm, *p_ct, *p_ub;
    cudaGetSymbolAddress(&p_xh,  g_xh);
    cudaGetSymbolAddress(&p_vh,  g_vh);
    cudaGetSymbolAddress(&p_vch, g_vch);
    cudaGetSymbolAddress(&p_u,   g_u);
    cudaGetSymbolAddress(&p_sh,  g_sh);
    cudaGetSymbolAddress(&p_wt,  g_wt);  cudaGetSymbolAddress(&p_wk,  g_wk);
    cudaGetSymbolAddress(&p_bm,  g_bm);  cudaGetSymbolAddress(&p_ct,  g_ct);
    cudaGetSymbolAddress(&p_ub,  g_ubias);

    cudaFuncSetAttribute(k_tgemm, cudaFuncAttributeMaxDynamicSharedMemorySize, SMB_TOTAL);
    cudaFuncSetAttribute(k_recur, cudaFuncAttributeMaxDynamicSharedMemorySize,
                         RC_SMEM_FLOATS * 4);

    // 1) weights + x -> fp16
    k_prep<<<1536, 512>>>(W_in, conv_w, C);
    k_split<<<(M_ROWS*IND)/1024, 256>>>(x);
    // 2) v = silu(x @ W_in^T + b_in) -> fp16
    k_tgemm<<<dim3(4, 1024), 256, SMB_TOTAL>>>(
        (const __half*)p_xh, (const __half*)p_wt,
        b_in, nullptr, (__half*)p_vh, IND, ST, 1, 0);
    // 3) vc = conv1d(v) + conv_b -> fp16
    k_tgemm<<<dim3(4, 1024), 256, SMB_TOTAL>>>(
        (const __half*)p_vh, (const __half*)p_wk,
        conv_b, nullptr, (__half*)p_vch, 3*ST, ST, 0, 1);
    // 4) BN stats
    k_stats<<<512, 512>>>();
    // 5) fold BN into Bm
    k_finalize<<<1, 512>>>(Bm, bng, bnb);
    // 6) u = vc @ Bm2 + ubias -> fp32
    k_tgemm<<<dim3(4, 1024), 256, SMB_TOTAL>>>(
        (const __half*)p_vch, (const __half*)p_bm,
        (const float*)p_ub, (float*)p_u, nullptr, ST, ST, 0, 0);
    // 7) recurrence -> fp16 states
    k_recur<<<dim3(8, 16), 512, RC_SMEM_FLOATS * 4>>>(A, lng, lnb);
    // 8) y = S @ C (single-term)
    k_tgemm<<<dim3(2, 1024), 256, SMB_TOTAL>>>(
        (const __half*)p_sh, (const __half*)p_ct,
        nullptr, out, nullptr, ST, OD, 0, 0);
}